// round 9
// baseline (speedup 1.0000x reference)
#include <cuda_runtime.h>
#include <cuda_bf16.h>
#include <cstdint>
#include <math.h>

#define BATCH 8192
#define EDIM  256
#define HDIM  50
#define N_INNER 31
#define N_LEAF  32

// ---------------------------------------------------------------------------
// Device scratch
// ---------------------------------------------------------------------------
__device__ float g_pR[N_INNER * BATCH];
__device__ float g_yleaf[N_LEAF * BATCH];

__device__ __nv_bfloat16 g_xh[BATCH * EDIM];
__device__ __nv_bfloat16 g_xl[BATCH * EDIM];
__device__ __nv_bfloat16 g_e0h[BATCH * EDIM];
__device__ __nv_bfloat16 g_e0l[BATCH * EDIM];
__device__ __nv_bfloat16 g_e1h[BATCH * EDIM];
__device__ __nv_bfloat16 g_e1l[BATCH * EDIM];
// encoder weights transposed [4][N=256][K=256] bf16 hi/lo
__device__ __nv_bfloat16 g_wth[4 * 65536];
__device__ __nv_bfloat16 g_wtl[4 * 65536];
// inner W1 transposed [31][64][256], Ww transposed [31][256][64]
__device__ __nv_bfloat16 g_w1th[N_INNER * 64 * 256];
__device__ __nv_bfloat16 g_w1tl[N_INNER * 64 * 256];
__device__ __nv_bfloat16 g_wwth[N_INNER * 256 * 64];
__device__ __nv_bfloat16 g_wwtl[N_INNER * 256 * 64];
// int8 leaf path: E quantized (2 splits) + per-row scale
__device__ int8_t g_eq1[BATCH * EDIM];
__device__ int8_t g_eq2[BATCH * EDIM];
__device__ float  g_sr[BATCH];
// leaf W1 quantized [32][256 n][256 k] + per-(mat,n) scale
__device__ int8_t g_wq1[N_LEAF * 65536];
__device__ int8_t g_wq2[N_LEAF * 65536];
__device__ float  g_wsc[N_LEAF * 256];

// ---------------------------------------------------------------------------
// Helpers
// ---------------------------------------------------------------------------
__device__ __forceinline__ uint32_t smem_u32(const void* p) {
    uint32_t a;
    asm("{ .reg .u64 t; cvta.to.shared.u64 t, %1; cvt.u32.u64 %0, t; }" : "=r"(a) : "l"(p));
    return a;
}
#define CP_ASYNC16(dst, src) \
    asm volatile("cp.async.cg.shared.global [%0], [%1], 16;" :: "r"(dst), "l"(src) : "memory")
#define CP_COMMIT() asm volatile("cp.async.commit_group;" ::: "memory")
#define CP_WAIT2()  asm volatile("cp.async.wait_group 2;" ::: "memory")
#define CP_WAIT1()  asm volatile("cp.async.wait_group 1;" ::: "memory")
#define CP_WAIT0()  asm volatile("cp.async.wait_group 0;" ::: "memory")

#define LDSM4(r, addr) \
    asm volatile("ldmatrix.sync.aligned.m8n8.x4.shared.b16 {%0,%1,%2,%3}, [%4];" \
        : "=r"((r)[0]), "=r"((r)[1]), "=r"((r)[2]), "=r"((r)[3]) : "r"(addr))

__device__ __forceinline__ void mma_bf16(float* c, const uint32_t* a, const uint32_t* b) {
    asm volatile(
        "mma.sync.aligned.m16n8k16.row.col.f32.bf16.bf16.f32 "
        "{%0,%1,%2,%3}, {%4,%5,%6,%7}, {%8,%9}, {%0,%1,%2,%3};"
        : "+f"(c[0]), "+f"(c[1]), "+f"(c[2]), "+f"(c[3])
        : "r"(a[0]), "r"(a[1]), "r"(a[2]), "r"(a[3]), "r"(b[0]), "r"(b[1]));
}

__device__ __forceinline__ void mma_s8(int* c, const uint32_t* a, const uint32_t* b) {
    asm volatile(
        "mma.sync.aligned.m16n8k32.row.col.s32.s8.s8.s32 "
        "{%0,%1,%2,%3}, {%4,%5,%6,%7}, {%8,%9}, {%0,%1,%2,%3};"
        : "+r"(c[0]), "+r"(c[1]), "+r"(c[2]), "+r"(c[3])
        : "r"(a[0]), "r"(a[1]), "r"(a[2]), "r"(a[3]), "r"(b[0]), "r"(b[1]));
}

__device__ __forceinline__ void split2(float a, float b, uint32_t& hi, uint32_t& lo) {
    __nv_bfloat16 h0 = __float2bfloat16(a), h1 = __float2bfloat16(b);
    __nv_bfloat16 l0 = __float2bfloat16(a - __bfloat162float(h0));
    __nv_bfloat16 l1 = __float2bfloat16(b - __bfloat162float(h1));
    __nv_bfloat16 hh[2] = {h0, h1}, ll[2] = {l0, l1};
    hi = *(uint32_t*)hh;
    lo = *(uint32_t*)ll;
}

__device__ __forceinline__ int8_t q8(float v) {
    int q = __float2int_rn(v);
    q = max(-127, min(127, q));
    return (int8_t)q;
}

// ---------------------------------------------------------------------------
// Mega-prep. Regions by blockIdx.x:
// x split | W1 t+split | Ww t+split | zero yl | 4x enc-W transpose | leaf-W q
// ---------------------------------------------------------------------------
#define PR_X   2048
#define PR_W1  (PR_X + 1984)
#define PR_WW  (PR_W1 + 1984)
#define PR_Z   (PR_WW + 256)
#define PR_WT  (PR_Z + 4 * 64)
#define PR_LQ  (PR_WT + N_LEAF)

__global__ __launch_bounds__(256) void prep_all_kernel(
    const float* __restrict__ x, __nv_bfloat16* __restrict__ xh,
    __nv_bfloat16* __restrict__ xl,
    const float* __restrict__ W1, __nv_bfloat16* __restrict__ w1h,
    __nv_bfloat16* __restrict__ w1l,
    const float* __restrict__ Ww, __nv_bfloat16* __restrict__ wwh,
    __nv_bfloat16* __restrict__ wwl,
    float* __restrict__ yl,
    const float* __restrict__ encW, __nv_bfloat16* __restrict__ wth,
    __nv_bfloat16* __restrict__ wtl,
    const float* __restrict__ lfW, int8_t* __restrict__ wq1,
    int8_t* __restrict__ wq2, float* __restrict__ wsc)
{
    const int bid = blockIdx.x;
    const int t = threadIdx.x;
    if (bid < PR_X) {
        int i = bid * 256 + t;
        float4 v = ((const float4*)x)[i];
        float f[4] = {v.x, v.y, v.z, v.w};
        __nv_bfloat16 h[4], l[4];
#pragma unroll
        for (int j = 0; j < 4; j++) {
            h[j] = __float2bfloat16(f[j]);
            l[j] = __float2bfloat16(f[j] - __bfloat162float(h[j]));
        }
        *(uint2*)(xh + 4 * (size_t)i) = *(uint2*)h;
        *(uint2*)(xl + 4 * (size_t)i) = *(uint2*)l;
    } else if (bid < PR_W1) {
        int idx = (bid - PR_X) * 256 + t;
        int k = idx & 255, j = (idx >> 8) & 63, n = idx >> 14;
        float v = (j < HDIM) ? W1[((size_t)n * 256 + k) * HDIM + j] : 0.f;
        __nv_bfloat16 h = __float2bfloat16(v);
        w1h[idx] = h;
        w1l[idx] = __float2bfloat16(v - __bfloat162float(h));
    } else if (bid < PR_WW) {
        int idx = (bid - PR_W1) * 256 + t;
        int j = idx & 63, d = (idx >> 6) & 255, n = idx >> 14;
        float v = (j < HDIM) ? Ww[((size_t)n * HDIM + j) * 256 + d] : 0.f;
        __nv_bfloat16 h = __float2bfloat16(v);
        wwh[idx] = h;
        wwl[idx] = __float2bfloat16(v - __bfloat162float(h));
    } else if (bid < PR_Z) {
        int i = (bid - PR_WW) * 256 + t;
        ((float4*)yl)[i] = make_float4(0.f, 0.f, 0.f, 0.f);
    } else if (bid < PR_WT) {
        __shared__ float tt[32][33];
        const int rel = bid - PR_Z;
        const int mat = rel >> 6;
        const int sub = rel & 63;
        const int nb = (sub & 7) * 32, kb = (sub >> 3) * 32;
        const int tx = t & 31, ty = t >> 5;
        const float* src = encW + (size_t)mat * 65536;
#pragma unroll
        for (int i = 0; i < 4; i++)
            tt[ty + 8 * i][tx] = src[(size_t)(kb + ty + 8 * i) * 256 + nb + tx];
        __syncthreads();
#pragma unroll
        for (int i = 0; i < 4; i++) {
            float v = tt[tx][ty + 8 * i];
            size_t idx = (size_t)mat * 65536 + (size_t)(nb + ty + 8 * i) * 256 + kb + tx;
            __nv_bfloat16 h = __float2bfloat16(v);
            wth[idx] = h;
            wtl[idx] = __float2bfloat16(v - __bfloat162float(h));
        }
    } else {
        // leaf W1 int8 quantization: per (mat, n-col) scale, 2 splits
        const int mat = bid - PR_WT;
        const int n = t;
        const float* src = lfW + (size_t)mat * 65536;  // [k][n]
        float mx = 0.f;
        for (int k = 0; k < 256; k++)
            mx = fmaxf(mx, fabsf(src[(size_t)k * 256 + n]));
        const float sc = fmaxf(mx, 1e-20f) * (1.f / 127.f);
        const float inv = 1.f / sc;
        wsc[mat * 256 + n] = sc;
        int8_t* d1 = wq1 + ((size_t)mat * 256 + n) * 256;
        int8_t* d2 = wq2 + ((size_t)mat * 256 + n) * 256;
        for (int k = 0; k < 256; k++) {
            float w = src[(size_t)k * 256 + n];
            int8_t a = q8(w * inv);
            float r = w - (float)a * sc;
            d1[k] = a;
            d2[k] = q8(r * inv * 128.f);
        }
    }
}

// ---------------------------------------------------------------------------
// Encoder GEMM L1-L3 (M=64, N=128, 3-stage, 256 thr). Proven r5/r6/r7.
// ---------------------------------------------------------------------------
#define E_AH 0
#define E_AL 5120
#define E_BH 10240
#define E_BL 20480
#define E_SZ 30720
#define ENC_SMEM (3 * E_SZ)

__global__ __launch_bounds__(256, 2) void enc_kernel(
    const __nv_bfloat16* __restrict__ Ah, const __nv_bfloat16* __restrict__ Al,
    const __nv_bfloat16* __restrict__ Bh, const __nv_bfloat16* __restrict__ Bl,
    const float* __restrict__ bias,
    __nv_bfloat16* __restrict__ oh, __nv_bfloat16* __restrict__ ol)
{
    extern __shared__ char smem[];
    const uint32_t sbase = smem_u32(smem);
    const int tid = threadIdx.x;
    const int lane = tid & 31, warp = tid >> 5;
    const int m0 = blockIdx.x * 64;
    const int n0 = blockIdx.y * 128;
    const int wm = (warp >> 2) * 32;
    const int wn = (warp & 3) * 32;

    float c[2][4][4];
#pragma unroll
    for (int mf = 0; mf < 2; mf++)
#pragma unroll
        for (int nf = 0; nf < 4; nf++)
#pragma unroll
            for (int q = 0; q < 4; q++) c[mf][nf][q] = 0.f;

    const int crow = tid >> 2;
    const int cu   = tid & 3;
    const int arow = (lane & 7) + ((lane >> 3) & 1) * 8;
    const int acol = (lane >> 4) * 8;
    const int brow = (lane & 7) + (lane >> 4) * 8;
    const int bcol = ((lane >> 3) & 1) * 8;

#define E_ISSUE(CI) do {                                                        \
    const int k0_ = (CI) * 32;                                                  \
    const uint32_t st_ = sbase + ((CI) % 3) * E_SZ;                             \
    const uint32_t da = st_ + crow * 80 + cu * 16;                              \
    const size_t ga = (size_t)(m0 + crow) * 256 + k0_ + cu * 8;                 \
    const size_t gb = (size_t)(n0 + crow) * 256 + k0_ + cu * 8;                 \
    CP_ASYNC16(da,         Ah + ga);                                            \
    CP_ASYNC16(da + E_AL,  Al + ga);                                            \
    CP_ASYNC16(st_ + E_BH + crow * 80 + cu * 16,        Bh + gb);               \
    CP_ASYNC16(st_ + E_BH + (crow + 64) * 80 + cu * 16, Bh + gb + 64 * 256);    \
    CP_ASYNC16(st_ + E_BL + crow * 80 + cu * 16,        Bl + gb);               \
    CP_ASYNC16(st_ + E_BL + (crow + 64) * 80 + cu * 16, Bl + gb + 64 * 256);    \
    CP_COMMIT();                                                                \
} while (0)

    E_ISSUE(0);
    E_ISSUE(1);

#pragma unroll 1
    for (int ci = 0; ci < 8; ci++) {
        if (ci < 7) CP_WAIT1(); else CP_WAIT0();
        __syncthreads();
        if (ci < 6) E_ISSUE(ci + 2);

        const uint32_t st = sbase + (ci % 3) * E_SZ;
#pragma unroll
        for (int kk = 0; kk < 32; kk += 16) {
            uint32_t ah[2][4], al[2][4];
#pragma unroll
            for (int mf = 0; mf < 2; mf++) {
                uint32_t addr = st + (wm + mf * 16 + arow) * 80 + (kk + acol) * 2;
                LDSM4(ah[mf], addr);
                LDSM4(al[mf], addr + E_AL);
            }
            uint32_t bhf[4][2], blf[4][2];
#pragma unroll
            for (int np = 0; np < 2; np++) {
                uint32_t addr = st + E_BH
                              + (wn + np * 16 + brow) * 80 + (kk + bcol) * 2;
                uint32_t r[4];
                LDSM4(r, addr);
                bhf[2 * np][0] = r[0]; bhf[2 * np][1] = r[1];
                bhf[2 * np + 1][0] = r[2]; bhf[2 * np + 1][1] = r[3];
                LDSM4(r, addr + (E_BL - E_BH));
                blf[2 * np][0] = r[0]; blf[2 * np][1] = r[1];
                blf[2 * np + 1][0] = r[2]; blf[2 * np + 1][1] = r[3];
            }
#pragma unroll
            for (int mf = 0; mf < 2; mf++)
#pragma unroll
                for (int nf = 0; nf < 4; nf++) {
                    mma_bf16(c[mf][nf], ah[mf], bhf[nf]);
                    mma_bf16(c[mf][nf], ah[mf], blf[nf]);
                    mma_bf16(c[mf][nf], al[mf], bhf[nf]);
                }
        }
    }
#undef E_ISSUE

    const int erow = lane >> 2;
    const int ecol = (lane & 3) * 2;
#pragma unroll
    for (int mf = 0; mf < 2; mf++) {
        const int gr0 = m0 + wm + mf * 16 + erow;
#pragma unroll
        for (int nf = 0; nf < 4; nf++) {
            const int gc = n0 + wn + nf * 8 + ecol;
            float2 bb = *(const float2*)&bias[gc];
            float v00 = fmaxf(c[mf][nf][0] + bb.x, 0.f);
            float v01 = fmaxf(c[mf][nf][1] + bb.y, 0.f);
            float v10 = fmaxf(c[mf][nf][2] + bb.x, 0.f);
            float v11 = fmaxf(c[mf][nf][3] + bb.y, 0.f);
            const size_t i0 = (size_t)gr0 * 256 + gc;
            const size_t i1 = (size_t)(gr0 + 8) * 256 + gc;
            uint32_t h0, l0, h1, l1;
            split2(v00, v01, h0, l0);
            split2(v10, v11, h1, l1);
            *(uint32_t*)(oh + i0) = h0;
            *(uint32_t*)(oh + i1) = h1;
            *(uint32_t*)(ol + i0) = l0;
            *(uint32_t*)(ol + i1) = l1;
        }
    }
}

// ---------------------------------------------------------------------------
// Encoder L4 (M=64, N=256 full rows, 512 thr, 4-stage) + int8 quantization
// of the output (row-max scaling) alongside bf16 hi/lo for the inner kernel.
// ---------------------------------------------------------------------------
#define E4_STG 51200
#define E4_MAX (4 * E4_STG)
#define E4_SMEM (E4_MAX + 256)

__global__ __launch_bounds__(512, 1) void enc4_kernel(
    const __nv_bfloat16* __restrict__ Ah, const __nv_bfloat16* __restrict__ Al,
    const __nv_bfloat16* __restrict__ Bh, const __nv_bfloat16* __restrict__ Bl,
    const float* __restrict__ bias,
    __nv_bfloat16* __restrict__ oh, __nv_bfloat16* __restrict__ ol,
    int8_t* __restrict__ eq1, int8_t* __restrict__ eq2,
    float* __restrict__ srp)
{
    extern __shared__ char smem[];
    const uint32_t sb = smem_u32(smem);
    const int tid = threadIdx.x;
    const int lane = tid & 31, w = tid >> 5;
    const int m0 = blockIdx.x * 64;
    const int wm = (w >> 3) * 32;
    const int wn = (w & 7) * 32;

    int* smax = (int*)(smem + E4_MAX);     // 64 per-row maxima (float-as-int)
    if (tid < 64) smax[tid] = 0;

    float c[2][4][4];
#pragma unroll
    for (int mf = 0; mf < 2; mf++)
#pragma unroll
        for (int nf = 0; nf < 4; nf++)
#pragma unroll
            for (int q = 0; q < 4; q++) c[mf][nf][q] = 0.f;

    const int arow = (lane & 7) + ((lane >> 3) & 1) * 8;
    const int acol = (lane >> 4) * 8;
    const int brow = (lane & 7) + (lane >> 4) * 8;
    const int bcol = ((lane >> 3) & 1) * 8;

    auto issue = [&](int CI) {
        const int k0_ = CI * 32;
        const uint32_t st_ = sb + (CI % 4) * E4_STG;
        if (tid < 256) {
            const int row = tid >> 2, u = tid & 3;
            const uint32_t d = st_ + row * 80 + u * 16;
            const size_t ga = (size_t)(m0 + row) * 256 + k0_ + u * 8;
            CP_ASYNC16(d, Ah + ga);
            CP_ASYNC16(d + 5120, Al + ga);
        } else {
            const int t2 = tid - 256, u = t2 & 3, r0_ = t2 >> 2;
#pragma unroll
            for (int rep = 0; rep < 4; rep++) {
                const int row = r0_ + rep * 64;
                const uint32_t d = st_ + 10240 + row * 80 + u * 16;
                const size_t gb = (size_t)row * 256 + k0_ + u * 8;
                CP_ASYNC16(d, Bh + gb);
                CP_ASYNC16(d + 20480, Bl + gb);
            }
        }
        CP_COMMIT();
    };

    issue(0); issue(1); issue(2);

#pragma unroll 1
    for (int ci = 0; ci < 8; ci++) {
        const int pend = (2 < 7 - ci) ? 2 : 7 - ci;
        if (pend == 2) CP_WAIT2();
        else if (pend == 1) CP_WAIT1();
        else CP_WAIT0();
        __syncthreads();
        if (ci + 3 < 8) issue(ci + 3);

        const uint32_t st = sb + (ci % 4) * E4_STG;
#pragma unroll
        for (int kk = 0; kk < 32; kk += 16) {
            uint32_t ah[2][4], al[2][4];
#pragma unroll
            for (int mf = 0; mf < 2; mf++) {
                const uint32_t addr = st + (wm + mf * 16 + arow) * 80 + (kk + acol) * 2;
                LDSM4(ah[mf], addr);
                LDSM4(al[mf], addr + 5120);
            }
#pragma unroll
            for (int np = 0; np < 2; np++) {
                const uint32_t baddr = st + 10240
                    + (wn + np * 16 + brow) * 80 + (kk + bcol) * 2;
                uint32_t rh[4], rl[4];
                LDSM4(rh, baddr);
                LDSM4(rl, baddr + 20480);
                uint32_t b0h[2] = {rh[0], rh[1]}, b1h[2] = {rh[2], rh[3]};
                uint32_t b0l[2] = {rl[0], rl[1]}, b1l[2] = {rl[2], rl[3]};
#pragma unroll
                for (int mf = 0; mf < 2; mf++) {
                    mma_bf16(c[mf][2 * np],     ah[mf], b0h);
                    mma_bf16(c[mf][2 * np],     ah[mf], b0l);
                    mma_bf16(c[mf][2 * np],     al[mf], b0h);
                    mma_bf16(c[mf][2 * np + 1], ah[mf], b1h);
                    mma_bf16(c[mf][2 * np + 1], ah[mf], b1l);
                    mma_bf16(c[mf][2 * np + 1], al[mf], b1h);
                }
            }
        }
    }

    const int erow = lane >> 2;
    const int ecol = (lane & 3) * 2;

    // pass 1: bf16 hi/lo stores + per-row max
#pragma unroll
    for (int mf = 0; mf < 2; mf++) {
        const int lr = wm + mf * 16 + erow;
        float mx0 = 0.f, mx1 = 0.f;
#pragma unroll
        for (int nf = 0; nf < 4; nf++) {
            const int gc = wn + nf * 8 + ecol;
            float2 bb = *(const float2*)&bias[gc];
            float v00 = fmaxf(c[mf][nf][0] + bb.x, 0.f);
            float v01 = fmaxf(c[mf][nf][1] + bb.y, 0.f);
            float v10 = fmaxf(c[mf][nf][2] + bb.x, 0.f);
            float v11 = fmaxf(c[mf][nf][3] + bb.y, 0.f);
            mx0 = fmaxf(mx0, fmaxf(v00, v01));
            mx1 = fmaxf(mx1, fmaxf(v10, v11));
            const size_t i0 = (size_t)(m0 + lr) * 256 + gc;
            const size_t i1 = (size_t)(m0 + lr + 8) * 256 + gc;
            uint32_t h0, l0, h1, l1;
            split2(v00, v01, h0, l0);
            split2(v10, v11, h1, l1);
            *(uint32_t*)(oh + i0) = h0;
            *(uint32_t*)(oh + i1) = h1;
            *(uint32_t*)(ol + i0) = l0;
            *(uint32_t*)(ol + i1) = l1;
        }
        mx0 = fmaxf(mx0, __shfl_xor_sync(0xffffffffu, mx0, 1));
        mx0 = fmaxf(mx0, __shfl_xor_sync(0xffffffffu, mx0, 2));
        mx1 = fmaxf(mx1, __shfl_xor_sync(0xffffffffu, mx1, 1));
        mx1 = fmaxf(mx1, __shfl_xor_sync(0xffffffffu, mx1, 2));
        if ((lane & 3) == 0) {
            atomicMax(&smax[lr],     __float_as_int(mx0));
            atomicMax(&smax[lr + 8], __float_as_int(mx1));
        }
    }
    __syncthreads();

    // pass 2: quantize to int8 hi/lo with per-row scale
#pragma unroll
    for (int mf = 0; mf < 2; mf++) {
        const int lr = wm + mf * 16 + erow;
        const float sr0 = fmaxf(__int_as_float(smax[lr]),     1e-20f) * (1.f / 127.f);
        const float sr1 = fmaxf(__int_as_float(smax[lr + 8]), 1e-20f) * (1.f / 127.f);
        const float iv0 = 1.f / sr0, iv1 = 1.f / sr1;
        if ((w & 7) == 0 && (lane & 3) == 0) {
            srp[m0 + lr] = sr0;
            srp[m0 + lr + 8] = sr1;
        }
#pragma unroll
        for (int nf = 0; nf < 4; nf++) {
            const int gc = wn + nf * 8 + ecol;
            float2 bb = *(const float2*)&bias[gc];
            float v00 = fmaxf(c[mf][nf][0] + bb.x, 0.f);
            float v01 = fmaxf(c[mf][nf][1] + bb.y, 0.f);
            float v10 = fmaxf(c[mf][nf][2] + bb.x, 0.f);
            float v11 = fmaxf(c[mf][nf][3] + bb.y, 0.f);
            int8_t a00 = q8(v00 * iv0), a01 = q8(v01 * iv0);
            int8_t a10 = q8(v10 * iv1), a11 = q8(v11 * iv1);
            int8_t b00 = q8((v00 - (float)a00 * sr0) * iv0 * 128.f);
            int8_t b01 = q8((v01 - (float)a01 * sr0) * iv0 * 128.f);
            int8_t b10 = q8((v10 - (float)a10 * sr1) * iv1 * 128.f);
            int8_t b11 = q8((v11 - (float)a11 * sr1) * iv1 * 128.f);
            const size_t i0 = (size_t)(m0 + lr) * 256 + gc;
            const size_t i1 = (size_t)(m0 + lr + 8) * 256 + gc;
            char2 p;
            p.x = a00; p.y = a01; *(char2*)(eq1 + i0) = p;
            p.x = a10; p.y = a11; *(char2*)(eq1 + i1) = p;
            p.x = b00; p.y = b01; *(char2*)(eq2 + i0) = p;
            p.x = b10; p.y = b11; *(char2*)(eq2 + i1) = p;
        }
    }
}

// ---------------------------------------------------------------------------
// Leaf GEMM via int8 IMMA (m16n8k32). M=64, N=128, K=256 in 4 chunks of 64.
// 3-stage pipeline. D ~= sr*sc*(C11 + Ccross/128). Epilogue reduces with W2.
// ---------------------------------------------------------------------------
#define LQ_A2  5120
#define LQ_B1  10240
#define LQ_B2  20480
#define LQ_STG 30720
#define LQ_SC  (3 * LQ_STG)
#define LQ_B1S (LQ_SC + 512)
#define LQ_W2S (LQ_B1S + 512)
#define LQ_SMEM (LQ_W2S + 512)

__global__ __launch_bounds__(256, 2) void leaf_i8_kernel(
    const int8_t* __restrict__ Aq1, const int8_t* __restrict__ Aq2,
    const int8_t* __restrict__ Wq1, const int8_t* __restrict__ Wq2,
    const float* __restrict__ srp, const float* __restrict__ wsc,
    const float* __restrict__ b1, const float* __restrict__ w2,
    float* __restrict__ yleaf)
{
    extern __shared__ char smem[];
    const uint32_t sb = smem_u32(smem);
    const int tid = threadIdx.x;
    const int lane = tid & 31, w = tid >> 5;
    const int m0 = blockIdx.x * 64;
    const int n0 = blockIdx.y * 128;
    const int mat = blockIdx.z;
    const int wm = (w >> 2) * 32;    // {0,32}
    const int wn = (w & 3) * 32;     // {0,32,64,96}

    const int8_t* wq1p = Wq1 + ((size_t)mat * 256 + n0) * 256;
    const int8_t* wq2p = Wq2 + ((size_t)mat * 256 + n0) * 256;

    float* s_sc = (float*)(smem + LQ_SC);
    float* s_b1 = (float*)(smem + LQ_B1S);
    float* s_w2 = (float*)(smem + LQ_W2S);
    if (tid < 128) {
        s_sc[tid] = wsc[mat * 256 + n0 + tid];
        s_b1[tid] = b1[(size_t)mat * 256 + n0 + tid];
        s_w2[tid] = w2[(size_t)mat * 256 + n0 + tid];
    }

    int c11[2][4][4], ccr[2][4][4];
#pragma unroll
    for (int mf = 0; mf < 2; mf++)
#pragma unroll
        for (int nf = 0; nf < 4; nf++)
#pragma unroll
            for (int q = 0; q < 4; q++) { c11[mf][nf][q] = 0; ccr[mf][nf][q] = 0; }

    const int arow = (lane & 7) + ((lane >> 3) & 1) * 8;
    const int acolB = (lane >> 4) * 16;          // byte offset
    const int brow = (lane & 7) + (lane >> 4) * 8;
    const int bcolB = ((lane >> 3) & 1) * 16;    // byte offset

    auto issue = [&](int CI) {
        const int k0_ = CI * 64;
        const uint32_t st_ = sb + (CI % 3) * LQ_STG;
        const int row = tid >> 2, u = tid & 3;
        {   // A: 64 rows x 64B per split
            const uint32_t d = st_ + row * 80 + u * 16;
            const size_t ga = (size_t)(m0 + row) * 256 + k0_ + u * 16;
            CP_ASYNC16(d, Aq1 + ga);
            CP_ASYNC16(d + LQ_A2, Aq2 + ga);
        }
        {   // B: 128 rows x 64B per split (2 reps)
#pragma unroll
            for (int rep = 0; rep < 2; rep++) {
                const int r = row + rep * 64;
                const uint32_t d = st_ + LQ_B1 + r * 80 + u * 16;
                const size_t gb = (size_t)r * 256 + k0_ + u * 16;
                CP_ASYNC16(d, wq1p + gb);
                CP_ASYNC16(d + (LQ_B2 - LQ_B1), wq2p + gb);
            }
        }
        CP_COMMIT();
    };

    issue(0);
    issue(1);

#pragma unroll 1
    for (int ci = 0; ci < 4; ci++) {
        if (ci < 3) CP_WAIT1(); else CP_WAIT0();
        __syncthreads();
        if (ci + 2 < 4) issue(ci + 2);

        const uint32_t st = sb + (ci % 3) * LQ_STG;
#pragma unroll
        for (int kk = 0; kk < 64; kk += 32) {
            uint32_t a1[2][4], a2[2][4];
#pragma unroll
            for (int mf = 0; mf < 2; mf++) {
                const uint32_t addr = st + (wm + mf * 16 + arow) * 80 + kk + acolB;
                LDSM4(a1[mf], addr);
                LDSM4(a2[mf], addr + LQ_A2);
            }
#pragma unroll
            for (int np = 0; np < 2; np++) {
                const uint32_t baddr = st + LQ_B1
                    + (wn + np * 16 + brow) * 80 + kk + bcolB;
                uint32_t r1[4], r2[4];
                LDSM4(r1, baddr);
                LDSM4(r2, baddr + (LQ_B2 - LQ_B1));
                uint32_t b01[2] = {r1[0], r1[1]}, b11[2] = {r1[2], r1[3]};
                uint32_t b02[2] = {r2[0], r2[1]}, b12[2] = {r2[2], r2[3]};
#pragma unroll
                for (int mf = 0; mf < 2; mf++) {
                    mma_s8(c11[mf][2 * np],     a1[mf], b01);
                    mma_s8(ccr[mf][2 * np],     a1[mf], b02);
                    mma_s8(ccr[mf][2 * np],     a2[mf], b01);
                    mma_s8(c11[mf][2 * np + 1], a1[mf], b11);
                    mma_s8(ccr[mf][2 * np + 1], a1[mf], b12);
                    mma_s8(ccr[mf][2 * np + 1], a2[mf], b11);
                }
            }
        }
    }

    // epilogue
    const int erow = lane >> 2;
    const int ecol = (lane & 3) * 2;
    float part[2][2] = {{0.f, 0.f}, {0.f, 0.f}};
#pragma unroll
    for (int mf = 0; mf < 2; mf++) {
        const int r0 = m0 + wm + mf * 16 + erow;
        const float sr0 = srp[r0], sr1 = srp[r0 + 8];
#pragma unroll
        for (int nf = 0; nf < 4; nf++) {
            const int lc = wn + nf * 8 + ecol;
            const float sc0 = s_sc[lc], sc1 = s_sc[lc + 1];
            const float bb0 = s_b1[lc], bb1 = s_b1[lc + 1];
            const float w0 = s_w2[lc], w1 = s_w2[lc + 1];
            float d00 = ((float)c11[mf][nf][0] + (float)ccr[mf][nf][0] * 0.0078125f) * sr0 * sc0;
            float d01 = ((float)c11[mf][nf][1] + (float)ccr[mf][nf][1] * 0.0078125f) * sr0 * sc1;
            float d10 = ((float)c11[mf][nf][2] + (float)ccr[mf][nf][2] * 0.0078125f) * sr1 * sc0;
            float d11 = ((float)c11[mf][nf][3] + (float)ccr[mf][nf][3] * 0.0078125f) * sr1 * sc1;
            part[mf][0] = fmaf(fmaxf(d00 + bb0, 0.f), w0, part[mf][0]);
            part[mf][0] = fmaf(fmaxf(d01 + bb1, 0.f), w1, part[mf][0]);
            part[mf][1] = fmaf(fmaxf(d10 + bb0, 0.f), w0, part[mf][1]);
            part[mf][1] = fmaf(fmaxf(d11 + bb1, 0.f), w1, part[mf][1]);
        }
    }
#pragma unroll
    for (int mf = 0; mf < 2; mf++)
#pragma unroll
        for (int h = 0; h < 2; h++) {
            part[mf][h] += __shfl_xor_sync(0xffffffffu, part[mf][h], 1);
            part[mf][h] += __shfl_xor_sync(0xffffffffu, part[mf][h], 2);
        }
    if ((lane & 3) == 0) {
#pragma unroll
        for (int mf = 0; mf < 2; mf++)
#pragma unroll
            for (int h = 0; h < 2; h++) {
                const int row = m0 + wm + mf * 16 + h * 8 + erow;
                atomicAdd(&yleaf[(size_t)mat * BATCH + row], part[mf][h]);
            }
    }
}

// ---------------------------------------------------------------------------
// Inner-node kernel (r6 proven, unchanged; bf16 3-MMA)
// ---------------------------------------------------------------------------
#define IA_SZ  20480
#define IB_SZ  24576
#define IN_HH  73728
#define IN_HL  82944
#define IN_RED 92160
#define IN_WBS 93696
#define IN_WBTS 93952
#define IN_SMEM 94208

__global__ __launch_bounds__(256, 2) void inner_mma_kernel(
    const __nv_bfloat16* __restrict__ eh, const __nv_bfloat16* __restrict__ el,
    const __nv_bfloat16* __restrict__ w1h, const __nv_bfloat16* __restrict__ w1l,
    const __nv_bfloat16* __restrict__ wwh, const __nv_bfloat16* __restrict__ wwl,
    const float* __restrict__ x, const float* __restrict__ b1,
    const float* __restrict__ bw, const float* __restrict__ Wb,
    const float* __restrict__ bb, const float* __restrict__ Wbt,
    const float* __restrict__ bbt, float* __restrict__ pR)
{
    extern __shared__ char smem[];
    const uint32_t sb = smem_u32(smem);
    const int tid = threadIdx.x, lane = tid & 31, w = tid >> 5;
    const int n = blockIdx.y, m0 = blockIdx.x * 64;

    float* sWb  = (float*)(smem + IN_WBS);
    float* sWbt = (float*)(smem + IN_WBTS);
    if (tid < HDIM)          sWb[tid] = Wb[n * HDIM + tid];
    else if (tid < 2 * HDIM) sWbt[tid - HDIM] = Wbt[n * HDIM + tid - HDIM];

    const int crow = tid >> 2, cu = tid & 3;
    const __nv_bfloat16* w1hp = w1h + (size_t)n * 64 * 256;
    const __nv_bfloat16* w1lp = w1l + (size_t)n * 64 * 256;
    const __nv_bfloat16* wwhp = wwh + (size_t)n * 256 * 64;
    const __nv_bfloat16* wwlp = wwl + (size_t)n * 256 * 64;

#define IN_ISSUE(CI) do {                                           \
    const int k0_ = (CI) * 32;                                      \
    const uint32_t st_ = sb + ((CI) % 3) * IA_SZ;                   \
    const uint32_t d = st_ + crow * 80 + cu * 16;                   \
    const size_t ga = (size_t)(m0 + crow) * 256 + k0_ + cu * 8;     \
    const size_t gw = (size_t)crow * 256 + k0_ + cu * 8;            \
    CP_ASYNC16(d,         eh + ga);                                 \
    CP_ASYNC16(d + 5120,  el + ga);                                 \
    CP_ASYNC16(d + 10240, w1hp + gw);                               \
    CP_ASYNC16(d + 15360, w1lp + gw);                               \
    CP_COMMIT();                                                    \
} while (0)

    const int arow = (lane & 7) + ((lane >> 3) & 1) * 8;
    const int acol = (lane >> 4) * 8;
    const int brow = (lane & 7) + (lane >> 4) * 8;
    const int bcol = ((lane >> 3) & 1) * 8;

    const int wmA = (w >> 1) * 16, wnA = (w & 1) * 32;
    float accA[4][4];
#pragma unroll
    for (int i = 0; i < 4; i++)
#pragma unroll
        for (int q = 0; q < 4; q++) accA[i][q] = 0.f;

    IN_ISSUE(0);
    IN_ISSUE(1);

#pragma unroll 1
    for (int ci = 0; ci < 8; ci++) {
        if (ci < 7) CP_WAIT1(); else CP_WAIT0();
        __syncthreads();
        if (ci < 6) IN_ISSUE(ci + 2);

        const uint32_t st = sb + (ci % 3) * IA_SZ;
#pragma unroll
        for (int kk = 0; kk < 32; kk += 16) {
            uint32_t ah[4], al[4];
            const uint32_t aaddr = st + (wmA + arow) * 80 + (kk + acol) * 2;
            LDSM4(ah, aaddr);
            LDSM4(al, aaddr + 5120);
            uint32_t bh[4][2], bl[4][2];
#pragma unroll
            for (int g = 0; g < 2; g++) {
                const uint32_t baddr = st + 10240
                    + (wnA + g * 16 + brow) * 80 + (kk + bcol) * 2;
                uint32_t r[4];
                LDSM4(r, baddr);
                bh[2 * g][0] = r[0]; bh[2 * g][1] = r[1];
                bh[2 * g + 1][0] = r[2]; bh[2 * g + 1][1] = r[3];
                LDSM4(r, baddr + 5120);
                bl[2 * g][0] = r[0]; bl[2 * g][1] = r[1];
                bl[2 * g + 1][0] = r[2]; bl[2 * g + 1][1] = r[3];
            }
#pragma unroll
            for (int nf = 0; nf < 4; nf++) {
                mma_bf16(accA[nf], ah, bh[nf]);
                mma_bf16(accA[nf], ah, bl[nf]);
                mma_bf16(accA[nf], al, bh[nf]);
            }
        }
    }
#undef IN_ISSUE

    {
        const int r0 = wmA + (lane >> 2);
#pragma unroll
        for (int nf = 0; nf < 4; nf++) {
            const int col = wnA + nf * 8 + (lane & 3) * 2;
            const float bb0 = (col < HDIM)     ? b1[n * HDIM + col]     : 0.f;
            const float bb1 = (col + 1 < HDIM) ? b1[n * HDIM + col + 1] : 0.f;
            float v00 = fmaxf(accA[nf][0] + bb0, 0.f);
            float v01 = fmaxf(accA[nf][1] + bb1, 0.f);
            float v10 = fmaxf(accA[nf][2] + bb0, 0.f);
            float v11 = fmaxf(accA[nf][3] + bb1, 0.f);
            uint32_t h0, l0, h1, l1;
            split2(v00, v01, h0, l0);
            split2(v10, v11, h1, l1);
            *(uint32_t*)(smem + IN_HH + r0 * 144 + col * 2) = h0;
            *(uint32_t*)(smem + IN_HL + r0 * 144 + col * 2) = l0;
            *(uint32_t*)(smem + IN_HH + (r0 + 8) * 144 + col * 2) = h1;
            *(uint32_t*)(smem + IN_HL + (r0 + 8) * 144 + col * 2) = l1;
        }
    }
    __syncthreads();

#define IN_ISSUE_B(KK) do {                                         \
    const uint32_t st_ = sb + ((KK) % 3) * IB_SZ;                   \
    const uint32_t d = st_ + tid * 48;                              \
    const size_t g = (size_t)tid * 64 + (KK) * 16;                  \
    CP_ASYNC16(d,          wwhp + g);                               \
    CP_ASYNC16(d + 16,     wwhp + g + 8);                           \
    CP_ASYNC16(d + 12288,      wwlp + g);                           \
    CP_ASYNC16(d + 12288 + 16, wwlp + g + 8);                       \
    CP_COMMIT();                                                    \
} while (0)

    const int wmB = (w >> 1) * 16, wnB = (w & 1) * 128;
    float z[16][4];
#pragma unroll
    for (int nf = 0; nf < 16; nf++)
#pragma unroll
        for (int q = 0; q < 4; q++) z[nf][q] = 0.f;

    IN_ISSUE_B(0);
    IN_ISSUE_B(1);

#pragma unroll 1
    for (int kk = 0; kk < 4; kk++) {
        if (kk < 3) CP_WAIT1(); else CP_WAIT0();
        __syncthreads();
        if (kk < 2) IN_ISSUE_B(kk + 2);

        const uint32_t st = sb + (kk % 3) * IB_SZ;
        uint32_t ah[4], al[4];
        const uint32_t aaddr = sb + IN_HH + (wmB + arow) * 144 + (kk * 16 + acol) * 2;
        LDSM4(ah, aaddr);
        LDSM4(al, aaddr + (IN_HL - IN_HH));
#pragma unroll
        for (int g = 0; g < 8; g++) {
            const uint32_t baddr = st + (wnB + g * 16 + brow) * 48 + bcol * 2;
            uint32_t rh[4], rl[4];
            LDSM4(rh, baddr);
            LDSM4(rl, baddr + 12288);
            uint32_t b0h[2] = {rh[0], rh[1]}, b1h[2] = {rh[2], rh[3]};
            uint32_t b0l[2] = {rl[0], rl[1]}, b1l[2] = {rl[2], rl[3]};
            mma_bf16(z[2 * g],     ah, b0h);
            mma_bf16(z[2 * g],     ah, b0l);
            mma_bf16(z[2 * g],     al, b0h);
            mma_bf16(z[2 * g + 1], ah, b1h);
            mma_bf16(z[2 * g + 1], ah, b1l);
            mma_bf16(z[2 * g + 1], al, b1h);
        }
    }
#undef IN_ISSUE_B

    float* redmax = (float*)(smem + IN_RED);
    float* redse  = redmax + 128;
    float* redsx  = redse + 128;

    const int r0 = wmB + (lane >> 2), r1 = r0 + 8;
    float mx0 = -1e30f, mx1 = -1e30f;
#pragma unroll
    for (int nf = 0; nf < 16; nf++) {
        const int col = wnB + nf * 8 + (lane & 3) * 2;
        float2 bwv = *(const float2*)&bw[n * 256 + col];
        z[nf][0] += bwv.x; z[nf][1] += bwv.y;
        z[nf][2] += bwv.x; z[nf][3] += bwv.y;
        mx0 = fmaxf(mx0, fmaxf(z[nf][0], z[nf][1]));
        mx1 = fmaxf(mx1, fmaxf(z[nf][2], z[nf][3]));
    }
    mx0 = fmaxf(mx0, __shfl_xor_sync(0xffffffffu, mx0, 1));
    mx0 = fmaxf(mx0, __shfl_xor_sync(0xffffffffu, mx0, 2));
    mx1 = fmaxf(mx1, __shfl_xor_sync(0xffffffffu, mx1, 1));
    mx1 = fmaxf(mx1, __shfl_xor_sync(0xffffffffu, mx1, 2));
    if ((lane & 3) == 0) {
        redmax[(w & 1) * 64 + r0] = mx0;
        redmax[(w & 1) * 64 + r1] = mx1;
    }
    __syncthreads();
    mx0 = fmaxf(redmax[r0], redmax[64 + r0]);
    mx1 = fmaxf(redmax[r1], redmax[64 + r1]);

    float se0 = 0.f, sx0 = 0.f, se1 = 0.f, sx1 = 0.f;
    const float* x0 = x + (size_t)(m0 + r0) * 256;
    const float* x1 = x + (size_t)(m0 + r1) * 256;
#pragma unroll
    for (int nf = 0; nf < 16; nf++) {
        const int col = wnB + nf * 8 + (lane & 3) * 2;
        float2 xv0 = *(const float2*)&x0[col];
        float2 xv1 = *(const float2*)&x1[col];
        float e;
        e = __expf(z[nf][0] - mx0); se0 += e; sx0 = fmaf(e, xv0.x, sx0);
        e = __expf(z[nf][1] - mx0); se0 += e; sx0 = fmaf(e, xv0.y, sx0);
        e = __expf(z[nf][2] - mx1); se1 += e; sx1 = fmaf(e, xv1.x, sx1);
        e = __expf(z[nf][3] - mx1); se1 += e; sx1 = fmaf(e, xv1.y, sx1);
    }
#pragma unroll
    for (int off = 1; off <= 2; off <<= 1) {
        se0 += __shfl_xor_sync(0xffffffffu, se0, off);
        sx0 += __shfl_xor_sync(0xffffffffu, sx0, off);
        se1 += __shfl_xor_sync(0xffffffffu, se1, off);
        sx1 += __shfl_xor_sync(0xffffffffu, sx1, off);
    }
    if ((lane & 3) == 0) {
        redse[(w & 1) * 64 + r0] = se0; redse[(w & 1) * 64 + r1] = se1;
        redsx[(w & 1) * 64 + r0] = sx0; redsx[(w & 1) * 64 + r1] = sx1;
    }
    __syncthreads();

    if ((w & 1) == 0) {
        float pb0 = 0.f, pbt0 = 0.f, pb1 = 0.f, pbt1 = 0.f;
        for (int j = (lane & 3); j < HDIM; j += 4) {
            float h0 = __bfloat162float(*(const __nv_bfloat16*)(smem + IN_HH + r0 * 144 + j * 2))
                     + __bfloat162float(*(const __nv_bfloat16*)(smem + IN_HL + r0 * 144 + j * 2));
            float h1 = __bfloat162float(*(const __nv_bfloat16*)(smem + IN_HH + r1 * 144 + j * 2))
                     + __bfloat162float(*(const __nv_bfloat16*)(smem + IN_HL + r1 * 144 + j * 2));
            pb0  = fmaf(h0, sWb[j],  pb0);
            pbt0 = fmaf(h0, sWbt[j], pbt0);
            pb1  = fmaf(h1, sWb[j],  pb1);
            pbt1 = fmaf(h1, sWbt[j], pbt1);
        }
#pragma unroll
        for (int off = 1; off <= 2; off <<= 1) {
            pb0  += __shfl_xor_sync(0xffffffffu, pb0, off);
            pbt0 += __shfl_xor_sync(0xffffffffu, pbt0, off);
            pb1  += __shfl_xor_sync(0xffffffffu, pb1, off);
            pbt1 += __shfl_xor_sync(0xffffffffu, pbt1, off);
        }
        if ((lane & 3) == 0) {
            const float bbn = bb[n], bbtn = bbt[n];
            float seA = redse[r0] + redse[64 + r0];
            float sxA = redsx[r0] + redsx[64 + r0];
            float val = (pbt0 + bbtn) * (sxA / seA + pb0 + bbn);
            pR[(size_t)n * BATCH + m0 + r0] = 1.f / (1.f + __expf(-val));
            seA = redse[r1] + redse[64 + r1];
            sxA = redsx[r1] + redsx[64 + r1];
            val = (pbt1 + bbtn) * (sxA / seA + pb1 + bbn);
            pR[(size_t)n * BATCH + m0 + r1] = 1.f / (1.f + __expf(-val));
        }
    }
}

// ---------------------------------------------------------------------------
// Combine
// ---------------------------------------------------------------------------
__global__ __launch_bounds__(256) void combine_kernel(
    const float* __restrict__ pR, const float* __restrict__ yl,
    const float* __restrict__ b2, float* __restrict__ out)
{
    const int b = blockIdx.x * 256 + threadIdx.x;
    float p[N_INNER];
#pragma unroll
    for (int i = 0; i < N_INNER; i++) p[i] = pR[(size_t)i * BATCH + b];

    float prob[N_LEAF];
    prob[0] = 1.f;
#pragma unroll
    for (int lev = 0; lev < 5; lev++) {
        const int cnt = 1 << lev;
        const int off = cnt - 1;
#pragma unroll
        for (int i = N_LEAF - 1; i >= 0; i--) {
            if (i < cnt) {
                float pr   = p[off + i];
                float base = prob[i];
                prob[2 * i]     = base * (1.f - pr);
                prob[2 * i + 1] = base * pr;
            }
        }
    }
    float acc = 0.f;
#pragma unroll
    for (int l = 0; l < N_LEAF; l++)
        acc = fmaf(prob[l], yl[(size_t)l * BATCH + b] + b2[l], acc);
    out[b] = acc;
}

// ---------------------------------------------------------------------------
extern "C" void kernel_launch(void* const* d_in, const int* in_sizes, int n_in,
                              void* d_out, int out_size)
{
    const float* x       = (const float*)d_in[0];
    const float* enc_W   = (const float*)d_in[1];
    const float* enc_b   = (const float*)d_in[2];
    const float* in_W1   = (const float*)d_in[3];
    const float* in_b1   = (const float*)d_in[4];
    const float* in_Ww   = (const float*)d_in[5];
    const float* in_bw   = (const float*)d_in[6];
    const float* in_Wb   = (const float*)d_in[7];
    const float* in_bb   = (const float*)d_in[8];
    const float* in_Wbt  = (const float*)d_in[9];
    const float* in_bbt  = (const float*)d_in[10];
    const float* lf_W1   = (const float*)d_in[11];
    const float* lf_b1   = (const float*)d_in[12];
    const float* lf_W2   = (const float*)d_in[13];
    const float* lf_b2   = (const float*)d_in[14];
    float* out = (float*)d_out;

    float *pR, *yl, *srp, *wscp;
    __nv_bfloat16 *xh, *xl, *e0h, *e0l, *e1h, *e1l, *wth, *wtl;
    __nv_bfloat16 *w1th, *w1tl, *wwth, *wwtl;
    int8_t *eq1, *eq2, *wq1, *wq2;
    cudaGetSymbolAddress((void**)&pR,  g_pR);
    cudaGetSymbolAddress((void**)&yl,  g_yleaf);
    cudaGetSymbolAddress((void**)&xh,  g_xh);
    cudaGetSymbolAddress((void**)&xl,  g_xl);
    cudaGetSymbolAddress((void**)&e0h, g_e0h);
    cudaGetSymbolAddress((void**)&e0l, g_e0l);
    cudaGetSymbolAddress((void**)&e1h, g_e1h);
    cudaGetSymbolAddress((void**)&e1l, g_e1l);
    cudaGetSymbolAddress((void**)&wth, g_wth);
    cudaGetSymbolAddress((void**)&wtl, g_wtl);
    cudaGetSymbolAddress((void**)&w1th, g_w1th);
    cudaGetSymbolAddress((void**)&w1tl, g_w1tl);
    cudaGetSymbolAddress((void**)&wwth, g_wwth);
    cudaGetSymbolAddress((void**)&wwtl, g_wwtl);
    cudaGetSymbolAddress((void**)&eq1, g_eq1);
    cudaGetSymbolAddress((void**)&eq2, g_eq2);
    cudaGetSymbolAddress((void**)&srp, g_sr);
    cudaGetSymbolAddress((void**)&wq1, g_wq1);
    cudaGetSymbolAddress((void**)&wq2, g_wq2);
    cudaGetSymbolAddress((void**)&wscp, g_wsc);

    cudaFuncSetAttribute(enc_kernel,   cudaFuncAttributeMaxDynamicSharedMemorySize, ENC_SMEM);
    cudaFuncSetAttribute(enc4_kernel,  cudaFuncAttributeMaxDynamicSharedMemorySize, E4_SMEM);
    cudaFuncSetAttribute(leaf_i8_kernel, cudaFuncAttributeMaxDynamicSharedMemorySize, LQ_SMEM);
    cudaFuncSetAttribute(inner_mma_kernel, cudaFuncAttributeMaxDynamicSharedMemorySize, IN_SMEM);

    // 1) prep (includes leaf-W int8 quantization)
    prep_all_kernel<<<PR_LQ, 256>>>(x, xh, xl, in_W1, w1th, w1tl,
                                    in_Ww, wwth, wwtl, yl,
                                    enc_W, wth, wtl,
                                    lf_W1, wq1, wq2, wscp);

    // 2-4) encoder L1-L3
    enc_kernel<<<dim3(128, 2), 256, ENC_SMEM>>>(xh, xl, wth, wtl,
        enc_b, e0h, e0l);
    enc_kernel<<<dim3(128, 2), 256, ENC_SMEM>>>(e0h, e0l, wth + 65536, wtl + 65536,
        enc_b + 256, e1h, e1l);
    enc_kernel<<<dim3(128, 2), 256, ENC_SMEM>>>(e1h, e1l, wth + 2 * 65536, wtl + 2 * 65536,
        enc_b + 512, e0h, e0l);

    // 5) encoder L4 + int8 quantization of E
    enc4_kernel<<<128, 512, E4_SMEM>>>(e0h, e0l, wth + 3 * 65536, wtl + 3 * 65536,
        enc_b + 768, e1h, e1l, eq1, eq2, srp);

    // 6) leaves via int8 IMMA (profiled launch)
    leaf_i8_kernel<<<dim3(128, 2, N_LEAF), 256, LQ_SMEM>>>(
        eq1, eq2, wq1, wq2, srp, wscp, lf_b1, lf_W2, yl);

    // 7) inner gates (bf16)
    inner_mma_kernel<<<dim3(BATCH / 64, N_INNER), 256, IN_SMEM>>>(
        e1h, e1l, w1th, w1tl, wwth, wwtl,
        x, in_b1, in_bw, in_Wb, in_bb, in_Wbt, in_bbt, pR);

    // 8) combine
    combine_kernel<<<BATCH / 256, 256>>>(pR, yl, lf_b2, out);
}

// round 10
// speedup vs baseline: 1.2388x; 1.2388x over previous
#include <cuda_runtime.h>
#include <cuda_bf16.h>
#include <cstdint>
#include <math.h>

#define BATCH 8192
#define EDIM  256
#define HDIM  50
#define N_INNER 31
#define N_LEAF  32

// ---------------------------------------------------------------------------
// Device scratch
// ---------------------------------------------------------------------------
__device__ float g_pR[N_INNER * BATCH];
__device__ float g_yleaf[N_LEAF * BATCH];

__device__ __nv_bfloat16 g_xh[BATCH * EDIM];
__device__ __nv_bfloat16 g_xl[BATCH * EDIM];
__device__ __nv_bfloat16 g_e0h[BATCH * EDIM];
__device__ __nv_bfloat16 g_e0l[BATCH * EDIM];
__device__ __nv_bfloat16 g_e1h[BATCH * EDIM];
__device__ __nv_bfloat16 g_e1l[BATCH * EDIM];
// encoder weights transposed [4][N=256][K=256] bf16 hi/lo
__device__ __nv_bfloat16 g_wth[4 * 65536];
__device__ __nv_bfloat16 g_wtl[4 * 65536];
// inner W1 transposed [31][64][256], Ww transposed [31][256][64]
__device__ __nv_bfloat16 g_w1th[N_INNER * 64 * 256];
__device__ __nv_bfloat16 g_w1tl[N_INNER * 64 * 256];
__device__ __nv_bfloat16 g_wwth[N_INNER * 256 * 64];
__device__ __nv_bfloat16 g_wwtl[N_INNER * 256 * 64];
// int8 leaf path: E quantized (2 splits) + per-row scale
__device__ int8_t g_eq1[BATCH * EDIM];
__device__ int8_t g_eq2[BATCH * EDIM];
__device__ float  g_sr[BATCH];
// leaf W1 quantized [32][256 n][256 k] + per-(mat,n) scale
__device__ int8_t g_wq1[N_LEAF * 65536];
__device__ int8_t g_wq2[N_LEAF * 65536];
__device__ float  g_wsc[N_LEAF * 256];

// ---------------------------------------------------------------------------
// Helpers
// ---------------------------------------------------------------------------
__device__ __forceinline__ uint32_t smem_u32(const void* p) {
    uint32_t a;
    asm("{ .reg .u64 t; cvta.to.shared.u64 t, %1; cvt.u32.u64 %0, t; }" : "=r"(a) : "l"(p));
    return a;
}
#define CP_ASYNC16(dst, src) \
    asm volatile("cp.async.cg.shared.global [%0], [%1], 16;" :: "r"(dst), "l"(src) : "memory")
#define CP_COMMIT() asm volatile("cp.async.commit_group;" ::: "memory")
#define CP_WAIT2()  asm volatile("cp.async.wait_group 2;" ::: "memory")
#define CP_WAIT1()  asm volatile("cp.async.wait_group 1;" ::: "memory")
#define CP_WAIT0()  asm volatile("cp.async.wait_group 0;" ::: "memory")

#define LDSM4(r, addr) \
    asm volatile("ldmatrix.sync.aligned.m8n8.x4.shared.b16 {%0,%1,%2,%3}, [%4];" \
        : "=r"((r)[0]), "=r"((r)[1]), "=r"((r)[2]), "=r"((r)[3]) : "r"(addr))

__device__ __forceinline__ void mma_bf16(float* c, const uint32_t* a, const uint32_t* b) {
    asm volatile(
        "mma.sync.aligned.m16n8k16.row.col.f32.bf16.bf16.f32 "
        "{%0,%1,%2,%3}, {%4,%5,%6,%7}, {%8,%9}, {%0,%1,%2,%3};"
        : "+f"(c[0]), "+f"(c[1]), "+f"(c[2]), "+f"(c[3])
        : "r"(a[0]), "r"(a[1]), "r"(a[2]), "r"(a[3]), "r"(b[0]), "r"(b[1]));
}

__device__ __forceinline__ void mma_s8(int* c, const uint32_t* a, const uint32_t* b) {
    asm volatile(
        "mma.sync.aligned.m16n8k32.row.col.s32.s8.s8.s32 "
        "{%0,%1,%2,%3}, {%4,%5,%6,%7}, {%8,%9}, {%0,%1,%2,%3};"
        : "+r"(c[0]), "+r"(c[1]), "+r"(c[2]), "+r"(c[3])
        : "r"(a[0]), "r"(a[1]), "r"(a[2]), "r"(a[3]), "r"(b[0]), "r"(b[1]));
}

__device__ __forceinline__ void split2(float a, float b, uint32_t& hi, uint32_t& lo) {
    __nv_bfloat16 h0 = __float2bfloat16(a), h1 = __float2bfloat16(b);
    __nv_bfloat16 l0 = __float2bfloat16(a - __bfloat162float(h0));
    __nv_bfloat16 l1 = __float2bfloat16(b - __bfloat162float(h1));
    __nv_bfloat16 hh[2] = {h0, h1}, ll[2] = {l0, l1};
    hi = *(uint32_t*)hh;
    lo = *(uint32_t*)ll;
}

__device__ __forceinline__ int8_t q8(float v) {
    int q = __float2int_rn(v);
    q = max(-127, min(127, q));
    return (int8_t)q;
}

// ---------------------------------------------------------------------------
// Mega-prep. Regions by blockIdx.x:
// x split | W1 t+split | Ww t+split | zero yl | 4x enc-W transpose |
// leaf-W quant (128 blocks: mat x k-quarter, wide coalesced stores)
// ---------------------------------------------------------------------------
#define PR_X   2048
#define PR_W1  (PR_X + 1984)
#define PR_WW  (PR_W1 + 1984)
#define PR_Z   (PR_WW + 256)
#define PR_WT  (PR_Z + 4 * 64)
#define PR_LQ  (PR_WT + N_LEAF * 4)

__global__ __launch_bounds__(256) void prep_all_kernel(
    const float* __restrict__ x, __nv_bfloat16* __restrict__ xh,
    __nv_bfloat16* __restrict__ xl,
    const float* __restrict__ W1, __nv_bfloat16* __restrict__ w1h,
    __nv_bfloat16* __restrict__ w1l,
    const float* __restrict__ Ww, __nv_bfloat16* __restrict__ wwh,
    __nv_bfloat16* __restrict__ wwl,
    float* __restrict__ yl,
    const float* __restrict__ encW, __nv_bfloat16* __restrict__ wth,
    __nv_bfloat16* __restrict__ wtl,
    const float* __restrict__ lfW, int8_t* __restrict__ wq1,
    int8_t* __restrict__ wq2, float* __restrict__ wsc)
{
    const int bid = blockIdx.x;
    const int t = threadIdx.x;
    if (bid < PR_X) {
        int i = bid * 256 + t;
        float4 v = ((const float4*)x)[i];
        float f[4] = {v.x, v.y, v.z, v.w};
        __nv_bfloat16 h[4], l[4];
#pragma unroll
        for (int j = 0; j < 4; j++) {
            h[j] = __float2bfloat16(f[j]);
            l[j] = __float2bfloat16(f[j] - __bfloat162float(h[j]));
        }
        *(uint2*)(xh + 4 * (size_t)i) = *(uint2*)h;
        *(uint2*)(xl + 4 * (size_t)i) = *(uint2*)l;
    } else if (bid < PR_W1) {
        int idx = (bid - PR_X) * 256 + t;
        int k = idx & 255, j = (idx >> 8) & 63, n = idx >> 14;
        float v = (j < HDIM) ? W1[((size_t)n * 256 + k) * HDIM + j] : 0.f;
        __nv_bfloat16 h = __float2bfloat16(v);
        w1h[idx] = h;
        w1l[idx] = __float2bfloat16(v - __bfloat162float(h));
    } else if (bid < PR_WW) {
        int idx = (bid - PR_W1) * 256 + t;
        int j = idx & 63, d = (idx >> 6) & 255, n = idx >> 14;
        float v = (j < HDIM) ? Ww[((size_t)n * HDIM + j) * 256 + d] : 0.f;
        __nv_bfloat16 h = __float2bfloat16(v);
        wwh[idx] = h;
        wwl[idx] = __float2bfloat16(v - __bfloat162float(h));
    } else if (bid < PR_Z) {
        int i = (bid - PR_WW) * 256 + t;
        ((float4*)yl)[i] = make_float4(0.f, 0.f, 0.f, 0.f);
    } else if (bid < PR_WT) {
        __shared__ float tt[32][33];
        const int rel = bid - PR_Z;
        const int mat = rel >> 6;
        const int sub = rel & 63;
        const int nb = (sub & 7) * 32, kb = (sub >> 3) * 32;
        const int tx = t & 31, ty = t >> 5;
        const float* src = encW + (size_t)mat * 65536;
#pragma unroll
        for (int i = 0; i < 4; i++)
            tt[ty + 8 * i][tx] = src[(size_t)(kb + ty + 8 * i) * 256 + nb + tx];
        __syncthreads();
#pragma unroll
        for (int i = 0; i < 4; i++) {
            float v = tt[tx][ty + 8 * i];
            size_t idx = (size_t)mat * 65536 + (size_t)(nb + ty + 8 * i) * 256 + kb + tx;
            __nv_bfloat16 h = __float2bfloat16(v);
            wth[idx] = h;
            wtl[idx] = __float2bfloat16(v - __bfloat162float(h));
        }
    } else {
        // leaf W1 int8 quantization (coalesced loads, register packing,
        // uint4 stores). Block = (mat, k-quarter); thread = n column.
        const int rel = bid - PR_WT;
        const int mat = rel >> 2;
        const int kq  = (rel & 3) * 64;
        const int n = t;
        const float* src = lfW + (size_t)mat * 65536;  // [k][n]
        float mx = 0.f;
#pragma unroll 4
        for (int k = 0; k < 256; k++)
            mx = fmaxf(mx, fabsf(src[(size_t)k * 256 + n]));
        const float sc = fmaxf(mx, 1e-20f) * (1.f / 127.f);
        const float inv = 1.f / sc;
        if (kq == 0) wsc[mat * 256 + n] = sc;
        int8_t* d1 = wq1 + ((size_t)mat * 256 + n) * 256 + kq;
        int8_t* d2 = wq2 + ((size_t)mat * 256 + n) * 256 + kq;
        uint32_t p1[16], p2[16];
#pragma unroll
        for (int kk = 0; kk < 64; kk += 4) {
            uint32_t v1 = 0, v2 = 0;
#pragma unroll
            for (int j = 0; j < 4; j++) {
                float wv = src[(size_t)(kq + kk + j) * 256 + n];
                int a = __float2int_rn(wv * inv);
                a = max(-127, min(127, a));
                float r = wv - (float)a * sc;
                int b = __float2int_rn(r * inv * 128.f);
                b = max(-127, min(127, b));
                v1 |= (uint32_t)((uint8_t)(int8_t)a) << (8 * j);
                v2 |= (uint32_t)((uint8_t)(int8_t)b) << (8 * j);
            }
            p1[kk >> 2] = v1;
            p2[kk >> 2] = v2;
        }
#pragma unroll
        for (int v = 0; v < 4; v++) {
            *(uint4*)(d1 + 16 * v) = make_uint4(p1[4 * v], p1[4 * v + 1],
                                                p1[4 * v + 2], p1[4 * v + 3]);
            *(uint4*)(d2 + 16 * v) = make_uint4(p2[4 * v], p2[4 * v + 1],
                                                p2[4 * v + 2], p2[4 * v + 3]);
        }
    }
}

// ---------------------------------------------------------------------------
// Encoder GEMM L1-L3 (M=64, N=128, 3-stage, 256 thr). Proven r5/r6/r7.
// ---------------------------------------------------------------------------
#define E_AH 0
#define E_AL 5120
#define E_BH 10240
#define E_BL 20480
#define E_SZ 30720
#define ENC_SMEM (3 * E_SZ)

__global__ __launch_bounds__(256, 2) void enc_kernel(
    const __nv_bfloat16* __restrict__ Ah, const __nv_bfloat16* __restrict__ Al,
    const __nv_bfloat16* __restrict__ Bh, const __nv_bfloat16* __restrict__ Bl,
    const float* __restrict__ bias,
    __nv_bfloat16* __restrict__ oh, __nv_bfloat16* __restrict__ ol)
{
    extern __shared__ char smem[];
    const uint32_t sbase = smem_u32(smem);
    const int tid = threadIdx.x;
    const int lane = tid & 31, warp = tid >> 5;
    const int m0 = blockIdx.x * 64;
    const int n0 = blockIdx.y * 128;
    const int wm = (warp >> 2) * 32;
    const int wn = (warp & 3) * 32;

    float c[2][4][4];
#pragma unroll
    for (int mf = 0; mf < 2; mf++)
#pragma unroll
        for (int nf = 0; nf < 4; nf++)
#pragma unroll
            for (int q = 0; q < 4; q++) c[mf][nf][q] = 0.f;

    const int crow = tid >> 2;
    const int cu   = tid & 3;
    const int arow = (lane & 7) + ((lane >> 3) & 1) * 8;
    const int acol = (lane >> 4) * 8;
    const int brow = (lane & 7) + (lane >> 4) * 8;
    const int bcol = ((lane >> 3) & 1) * 8;

#define E_ISSUE(CI) do {                                                        \
    const int k0_ = (CI) * 32;                                                  \
    const uint32_t st_ = sbase + ((CI) % 3) * E_SZ;                             \
    const uint32_t da = st_ + crow * 80 + cu * 16;                              \
    const size_t ga = (size_t)(m0 + crow) * 256 + k0_ + cu * 8;                 \
    const size_t gb = (size_t)(n0 + crow) * 256 + k0_ + cu * 8;                 \
    CP_ASYNC16(da,         Ah + ga);                                            \
    CP_ASYNC16(da + E_AL,  Al + ga);                                            \
    CP_ASYNC16(st_ + E_BH + crow * 80 + cu * 16,        Bh + gb);               \
    CP_ASYNC16(st_ + E_BH + (crow + 64) * 80 + cu * 16, Bh + gb + 64 * 256);    \
    CP_ASYNC16(st_ + E_BL + crow * 80 + cu * 16,        Bl + gb);               \
    CP_ASYNC16(st_ + E_BL + (crow + 64) * 80 + cu * 16, Bl + gb + 64 * 256);    \
    CP_COMMIT();                                                                \
} while (0)

    E_ISSUE(0);
    E_ISSUE(1);

#pragma unroll 1
    for (int ci = 0; ci < 8; ci++) {
        if (ci < 7) CP_WAIT1(); else CP_WAIT0();
        __syncthreads();
        if (ci < 6) E_ISSUE(ci + 2);

        const uint32_t st = sbase + (ci % 3) * E_SZ;
#pragma unroll
        for (int kk = 0; kk < 32; kk += 16) {
            uint32_t ah[2][4], al[2][4];
#pragma unroll
            for (int mf = 0; mf < 2; mf++) {
                uint32_t addr = st + (wm + mf * 16 + arow) * 80 + (kk + acol) * 2;
                LDSM4(ah[mf], addr);
                LDSM4(al[mf], addr + E_AL);
            }
            uint32_t bhf[4][2], blf[4][2];
#pragma unroll
            for (int np = 0; np < 2; np++) {
                uint32_t addr = st + E_BH
                              + (wn + np * 16 + brow) * 80 + (kk + bcol) * 2;
                uint32_t r[4];
                LDSM4(r, addr);
                bhf[2 * np][0] = r[0]; bhf[2 * np][1] = r[1];
                bhf[2 * np + 1][0] = r[2]; bhf[2 * np + 1][1] = r[3];
                LDSM4(r, addr + (E_BL - E_BH));
                blf[2 * np][0] = r[0]; blf[2 * np][1] = r[1];
                blf[2 * np + 1][0] = r[2]; blf[2 * np + 1][1] = r[3];
            }
#pragma unroll
            for (int mf = 0; mf < 2; mf++)
#pragma unroll
                for (int nf = 0; nf < 4; nf++) {
                    mma_bf16(c[mf][nf], ah[mf], bhf[nf]);
                    mma_bf16(c[mf][nf], ah[mf], blf[nf]);
                    mma_bf16(c[mf][nf], al[mf], bhf[nf]);
                }
        }
    }
#undef E_ISSUE

    const int erow = lane >> 2;
    const int ecol = (lane & 3) * 2;
#pragma unroll
    for (int mf = 0; mf < 2; mf++) {
        const int gr0 = m0 + wm + mf * 16 + erow;
#pragma unroll
        for (int nf = 0; nf < 4; nf++) {
            const int gc = n0 + wn + nf * 8 + ecol;
            float2 bb = *(const float2*)&bias[gc];
            float v00 = fmaxf(c[mf][nf][0] + bb.x, 0.f);
            float v01 = fmaxf(c[mf][nf][1] + bb.y, 0.f);
            float v10 = fmaxf(c[mf][nf][2] + bb.x, 0.f);
            float v11 = fmaxf(c[mf][nf][3] + bb.y, 0.f);
            const size_t i0 = (size_t)gr0 * 256 + gc;
            const size_t i1 = (size_t)(gr0 + 8) * 256 + gc;
            uint32_t h0, l0, h1, l1;
            split2(v00, v01, h0, l0);
            split2(v10, v11, h1, l1);
            *(uint32_t*)(oh + i0) = h0;
            *(uint32_t*)(oh + i1) = h1;
            *(uint32_t*)(ol + i0) = l0;
            *(uint32_t*)(ol + i1) = l1;
        }
    }
}

// ---------------------------------------------------------------------------
// Encoder L4 (M=64, N=256 full rows, 512 thr, 4-stage) + int8 quantization
// ---------------------------------------------------------------------------
#define E4_STG 51200
#define E4_MAX (4 * E4_STG)
#define E4_SMEM (E4_MAX + 256)

__global__ __launch_bounds__(512, 1) void enc4_kernel(
    const __nv_bfloat16* __restrict__ Ah, const __nv_bfloat16* __restrict__ Al,
    const __nv_bfloat16* __restrict__ Bh, const __nv_bfloat16* __restrict__ Bl,
    const float* __restrict__ bias,
    __nv_bfloat16* __restrict__ oh, __nv_bfloat16* __restrict__ ol,
    int8_t* __restrict__ eq1, int8_t* __restrict__ eq2,
    float* __restrict__ srp)
{
    extern __shared__ char smem[];
    const uint32_t sb = smem_u32(smem);
    const int tid = threadIdx.x;
    const int lane = tid & 31, w = tid >> 5;
    const int m0 = blockIdx.x * 64;
    const int wm = (w >> 3) * 32;
    const int wn = (w & 7) * 32;

    int* smax = (int*)(smem + E4_MAX);
    if (tid < 64) smax[tid] = 0;

    float c[2][4][4];
#pragma unroll
    for (int mf = 0; mf < 2; mf++)
#pragma unroll
        for (int nf = 0; nf < 4; nf++)
#pragma unroll
            for (int q = 0; q < 4; q++) c[mf][nf][q] = 0.f;

    const int arow = (lane & 7) + ((lane >> 3) & 1) * 8;
    const int acol = (lane >> 4) * 8;
    const int brow = (lane & 7) + (lane >> 4) * 8;
    const int bcol = ((lane >> 3) & 1) * 8;

    auto issue = [&](int CI) {
        const int k0_ = CI * 32;
        const uint32_t st_ = sb + (CI % 4) * E4_STG;
        if (tid < 256) {
            const int row = tid >> 2, u = tid & 3;
            const uint32_t d = st_ + row * 80 + u * 16;
            const size_t ga = (size_t)(m0 + row) * 256 + k0_ + u * 8;
            CP_ASYNC16(d, Ah + ga);
            CP_ASYNC16(d + 5120, Al + ga);
        } else {
            const int t2 = tid - 256, u = t2 & 3, r0_ = t2 >> 2;
#pragma unroll
            for (int rep = 0; rep < 4; rep++) {
                const int row = r0_ + rep * 64;
                const uint32_t d = st_ + 10240 + row * 80 + u * 16;
                const size_t gb = (size_t)row * 256 + k0_ + u * 8;
                CP_ASYNC16(d, Bh + gb);
                CP_ASYNC16(d + 20480, Bl + gb);
            }
        }
        CP_COMMIT();
    };

    issue(0); issue(1); issue(2);

#pragma unroll 1
    for (int ci = 0; ci < 8; ci++) {
        const int pend = (2 < 7 - ci) ? 2 : 7 - ci;
        if (pend == 2) CP_WAIT2();
        else if (pend == 1) CP_WAIT1();
        else CP_WAIT0();
        __syncthreads();
        if (ci + 3 < 8) issue(ci + 3);

        const uint32_t st = sb + (ci % 4) * E4_STG;
#pragma unroll
        for (int kk = 0; kk < 32; kk += 16) {
            uint32_t ah[2][4], al[2][4];
#pragma unroll
            for (int mf = 0; mf < 2; mf++) {
                const uint32_t addr = st + (wm + mf * 16 + arow) * 80 + (kk + acol) * 2;
                LDSM4(ah[mf], addr);
                LDSM4(al[mf], addr + 5120);
            }
#pragma unroll
            for (int np = 0; np < 2; np++) {
                const uint32_t baddr = st + 10240
                    + (wn + np * 16 + brow) * 80 + (kk + bcol) * 2;
                uint32_t rh[4], rl[4];
                LDSM4(rh, baddr);
                LDSM4(rl, baddr + 20480);
                uint32_t b0h[2] = {rh[0], rh[1]}, b1h[2] = {rh[2], rh[3]};
                uint32_t b0l[2] = {rl[0], rl[1]}, b1l[2] = {rl[2], rl[3]};
#pragma unroll
                for (int mf = 0; mf < 2; mf++) {
                    mma_bf16(c[mf][2 * np],     ah[mf], b0h);
                    mma_bf16(c[mf][2 * np],     ah[mf], b0l);
                    mma_bf16(c[mf][2 * np],     al[mf], b0h);
                    mma_bf16(c[mf][2 * np + 1], ah[mf], b1h);
                    mma_bf16(c[mf][2 * np + 1], ah[mf], b1l);
                    mma_bf16(c[mf][2 * np + 1], al[mf], b1h);
                }
            }
        }
    }

    const int erow = lane >> 2;
    const int ecol = (lane & 3) * 2;

    // pass 1: bf16 hi/lo stores + per-row max
#pragma unroll
    for (int mf = 0; mf < 2; mf++) {
        const int lr = wm + mf * 16 + erow;
        float mx0 = 0.f, mx1 = 0.f;
#pragma unroll
        for (int nf = 0; nf < 4; nf++) {
            const int gc = wn + nf * 8 + ecol;
            float2 bb = *(const float2*)&bias[gc];
            float v00 = fmaxf(c[mf][nf][0] + bb.x, 0.f);
            float v01 = fmaxf(c[mf][nf][1] + bb.y, 0.f);
            float v10 = fmaxf(c[mf][nf][2] + bb.x, 0.f);
            float v11 = fmaxf(c[mf][nf][3] + bb.y, 0.f);
            mx0 = fmaxf(mx0, fmaxf(v00, v01));
            mx1 = fmaxf(mx1, fmaxf(v10, v11));
            const size_t i0 = (size_t)(m0 + lr) * 256 + gc;
            const size_t i1 = (size_t)(m0 + lr + 8) * 256 + gc;
            uint32_t h0, l0, h1, l1;
            split2(v00, v01, h0, l0);
            split2(v10, v11, h1, l1);
            *(uint32_t*)(oh + i0) = h0;
            *(uint32_t*)(oh + i1) = h1;
            *(uint32_t*)(ol + i0) = l0;
            *(uint32_t*)(ol + i1) = l1;
        }
        mx0 = fmaxf(mx0, __shfl_xor_sync(0xffffffffu, mx0, 1));
        mx0 = fmaxf(mx0, __shfl_xor_sync(0xffffffffu, mx0, 2));
        mx1 = fmaxf(mx1, __shfl_xor_sync(0xffffffffu, mx1, 1));
        mx1 = fmaxf(mx1, __shfl_xor_sync(0xffffffffu, mx1, 2));
        if ((lane & 3) == 0) {
            atomicMax(&smax[lr],     __float_as_int(mx0));
            atomicMax(&smax[lr + 8], __float_as_int(mx1));
        }
    }
    __syncthreads();

    // pass 2: quantize to int8 hi/lo with per-row scale
#pragma unroll
    for (int mf = 0; mf < 2; mf++) {
        const int lr = wm + mf * 16 + erow;
        const float sr0 = fmaxf(__int_as_float(smax[lr]),     1e-20f) * (1.f / 127.f);
        const float sr1 = fmaxf(__int_as_float(smax[lr + 8]), 1e-20f) * (1.f / 127.f);
        const float iv0 = 1.f / sr0, iv1 = 1.f / sr1;
        if ((w & 7) == 0 && (lane & 3) == 0) {
            srp[m0 + lr] = sr0;
            srp[m0 + lr + 8] = sr1;
        }
#pragma unroll
        for (int nf = 0; nf < 4; nf++) {
            const int gc = wn + nf * 8 + ecol;
            float2 bb = *(const float2*)&bias[gc];
            float v00 = fmaxf(c[mf][nf][0] + bb.x, 0.f);
            float v01 = fmaxf(c[mf][nf][1] + bb.y, 0.f);
            float v10 = fmaxf(c[mf][nf][2] + bb.x, 0.f);
            float v11 = fmaxf(c[mf][nf][3] + bb.y, 0.f);
            int8_t a00 = q8(v00 * iv0), a01 = q8(v01 * iv0);
            int8_t a10 = q8(v10 * iv1), a11 = q8(v11 * iv1);
            int8_t b00 = q8((v00 - (float)a00 * sr0) * iv0 * 128.f);
            int8_t b01 = q8((v01 - (float)a01 * sr0) * iv0 * 128.f);
            int8_t b10 = q8((v10 - (float)a10 * sr1) * iv1 * 128.f);
            int8_t b11 = q8((v11 - (float)a11 * sr1) * iv1 * 128.f);
            const size_t i0 = (size_t)(m0 + lr) * 256 + gc;
            const size_t i1 = (size_t)(m0 + lr + 8) * 256 + gc;
            char2 p;
            p.x = a00; p.y = a01; *(char2*)(eq1 + i0) = p;
            p.x = a10; p.y = a11; *(char2*)(eq1 + i1) = p;
            p.x = b00; p.y = b01; *(char2*)(eq2 + i0) = p;
            p.x = b10; p.y = b11; *(char2*)(eq2 + i1) = p;
        }
    }
}

// ---------------------------------------------------------------------------
// Leaf GEMM via int8 IMMA (m16n8k32). M=64, N=128, K=256 in 4 chunks of 64.
// ---------------------------------------------------------------------------
#define LQ_A2  5120
#define LQ_B1  10240
#define LQ_B2  20480
#define LQ_STG 30720
#define LQ_SC  (3 * LQ_STG)
#define LQ_B1S (LQ_SC + 512)
#define LQ_W2S (LQ_B1S + 512)
#define LQ_SMEM (LQ_W2S + 512)

__global__ __launch_bounds__(256, 2) void leaf_i8_kernel(
    const int8_t* __restrict__ Aq1, const int8_t* __restrict__ Aq2,
    const int8_t* __restrict__ Wq1, const int8_t* __restrict__ Wq2,
    const float* __restrict__ srp, const float* __restrict__ wsc,
    const float* __restrict__ b1, const float* __restrict__ w2,
    float* __restrict__ yleaf)
{
    extern __shared__ char smem[];
    const uint32_t sb = smem_u32(smem);
    const int tid = threadIdx.x;
    const int lane = tid & 31, w = tid >> 5;
    const int m0 = blockIdx.x * 64;
    const int n0 = blockIdx.y * 128;
    const int mat = blockIdx.z;
    const int wm = (w >> 2) * 32;
    const int wn = (w & 3) * 32;

    const int8_t* wq1p = Wq1 + ((size_t)mat * 256 + n0) * 256;
    const int8_t* wq2p = Wq2 + ((size_t)mat * 256 + n0) * 256;

    float* s_sc = (float*)(smem + LQ_SC);
    float* s_b1 = (float*)(smem + LQ_B1S);
    float* s_w2 = (float*)(smem + LQ_W2S);
    if (tid < 128) {
        s_sc[tid] = wsc[mat * 256 + n0 + tid];
        s_b1[tid] = b1[(size_t)mat * 256 + n0 + tid];
        s_w2[tid] = w2[(size_t)mat * 256 + n0 + tid];
    }

    int c11[2][4][4], ccr[2][4][4];
#pragma unroll
    for (int mf = 0; mf < 2; mf++)
#pragma unroll
        for (int nf = 0; nf < 4; nf++)
#pragma unroll
            for (int q = 0; q < 4; q++) { c11[mf][nf][q] = 0; ccr[mf][nf][q] = 0; }

    const int arow = (lane & 7) + ((lane >> 3) & 1) * 8;
    const int acolB = (lane >> 4) * 16;
    const int brow = (lane & 7) + (lane >> 4) * 8;
    const int bcolB = ((lane >> 3) & 1) * 16;

    auto issue = [&](int CI) {
        const int k0_ = CI * 64;
        const uint32_t st_ = sb + (CI % 3) * LQ_STG;
        const int row = tid >> 2, u = tid & 3;
        {
            const uint32_t d = st_ + row * 80 + u * 16;
            const size_t ga = (size_t)(m0 + row) * 256 + k0_ + u * 16;
            CP_ASYNC16(d, Aq1 + ga);
            CP_ASYNC16(d + LQ_A2, Aq2 + ga);
        }
        {
#pragma unroll
            for (int rep = 0; rep < 2; rep++) {
                const int r = row + rep * 64;
                const uint32_t d = st_ + LQ_B1 + r * 80 + u * 16;
                const size_t gb = (size_t)r * 256 + k0_ + u * 16;
                CP_ASYNC16(d, wq1p + gb);
                CP_ASYNC16(d + (LQ_B2 - LQ_B1), wq2p + gb);
            }
        }
        CP_COMMIT();
    };

    issue(0);
    issue(1);

#pragma unroll 1
    for (int ci = 0; ci < 4; ci++) {
        if (ci < 3) CP_WAIT1(); else CP_WAIT0();
        __syncthreads();
        if (ci + 2 < 4) issue(ci + 2);

        const uint32_t st = sb + (ci % 3) * LQ_STG;
#pragma unroll
        for (int kk = 0; kk < 64; kk += 32) {
            uint32_t a1[2][4], a2[2][4];
#pragma unroll
            for (int mf = 0; mf < 2; mf++) {
                const uint32_t addr = st + (wm + mf * 16 + arow) * 80 + kk + acolB;
                LDSM4(a1[mf], addr);
                LDSM4(a2[mf], addr + LQ_A2);
            }
#pragma unroll
            for (int np = 0; np < 2; np++) {
                const uint32_t baddr = st + LQ_B1
                    + (wn + np * 16 + brow) * 80 + kk + bcolB;
                uint32_t r1[4], r2[4];
                LDSM4(r1, baddr);
                LDSM4(r2, baddr + (LQ_B2 - LQ_B1));
                uint32_t b01[2] = {r1[0], r1[1]}, b11[2] = {r1[2], r1[3]};
                uint32_t b02[2] = {r2[0], r2[1]}, b12[2] = {r2[2], r2[3]};
#pragma unroll
                for (int mf = 0; mf < 2; mf++) {
                    mma_s8(c11[mf][2 * np],     a1[mf], b01);
                    mma_s8(ccr[mf][2 * np],     a1[mf], b02);
                    mma_s8(ccr[mf][2 * np],     a2[mf], b01);
                    mma_s8(c11[mf][2 * np + 1], a1[mf], b11);
                    mma_s8(ccr[mf][2 * np + 1], a1[mf], b12);
                    mma_s8(ccr[mf][2 * np + 1], a2[mf], b11);
                }
            }
        }
    }

    const int erow = lane >> 2;
    const int ecol = (lane & 3) * 2;
    float part[2][2] = {{0.f, 0.f}, {0.f, 0.f}};
#pragma unroll
    for (int mf = 0; mf < 2; mf++) {
        const int r0 = m0 + wm + mf * 16 + erow;
        const float sr0 = srp[r0], sr1 = srp[r0 + 8];
#pragma unroll
        for (int nf = 0; nf < 4; nf++) {
            const int lc = wn + nf * 8 + ecol;
            const float sc0 = s_sc[lc], sc1 = s_sc[lc + 1];
            const float bb0 = s_b1[lc], bb1 = s_b1[lc + 1];
            const float w0 = s_w2[lc], w1 = s_w2[lc + 1];
            float d00 = ((float)c11[mf][nf][0] + (float)ccr[mf][nf][0] * 0.0078125f) * sr0 * sc0;
            float d01 = ((float)c11[mf][nf][1] + (float)ccr[mf][nf][1] * 0.0078125f) * sr0 * sc1;
            float d10 = ((float)c11[mf][nf][2] + (float)ccr[mf][nf][2] * 0.0078125f) * sr1 * sc0;
            float d11 = ((float)c11[mf][nf][3] + (float)ccr[mf][nf][3] * 0.0078125f) * sr1 * sc1;
            part[mf][0] = fmaf(fmaxf(d00 + bb0, 0.f), w0, part[mf][0]);
            part[mf][0] = fmaf(fmaxf(d01 + bb1, 0.f), w1, part[mf][0]);
            part[mf][1] = fmaf(fmaxf(d10 + bb0, 0.f), w0, part[mf][1]);
            part[mf][1] = fmaf(fmaxf(d11 + bb1, 0.f), w1, part[mf][1]);
        }
    }
#pragma unroll
    for (int mf = 0; mf < 2; mf++)
#pragma unroll
        for (int h = 0; h < 2; h++) {
            part[mf][h] += __shfl_xor_sync(0xffffffffu, part[mf][h], 1);
            part[mf][h] += __shfl_xor_sync(0xffffffffu, part[mf][h], 2);
        }
    if ((lane & 3) == 0) {
#pragma unroll
        for (int mf = 0; mf < 2; mf++)
#pragma unroll
            for (int h = 0; h < 2; h++) {
                const int row = m0 + wm + mf * 16 + h * 8 + erow;
                atomicAdd(&yleaf[(size_t)mat * BATCH + row], part[mf][h]);
            }
    }
}

// ---------------------------------------------------------------------------
// Inner-node kernel (r6 proven, unchanged; bf16 3-MMA)
// ---------------------------------------------------------------------------
#define IA_SZ  20480
#define IB_SZ  24576
#define IN_HH  73728
#define IN_HL  82944
#define IN_RED 92160
#define IN_WBS 93696
#define IN_WBTS 93952
#define IN_SMEM 94208

__global__ __launch_bounds__(256, 2) void inner_mma_kernel(
    const __nv_bfloat16* __restrict__ eh, const __nv_bfloat16* __restrict__ el,
    const __nv_bfloat16* __restrict__ w1h, const __nv_bfloat16* __restrict__ w1l,
    const __nv_bfloat16* __restrict__ wwh, const __nv_bfloat16* __restrict__ wwl,
    const float* __restrict__ x, const float* __restrict__ b1,
    const float* __restrict__ bw, const float* __restrict__ Wb,
    const float* __restrict__ bb, const float* __restrict__ Wbt,
    const float* __restrict__ bbt, float* __restrict__ pR)
{
    extern __shared__ char smem[];
    const uint32_t sb = smem_u32(smem);
    const int tid = threadIdx.x, lane = tid & 31, w = tid >> 5;
    const int n = blockIdx.y, m0 = blockIdx.x * 64;

    float* sWb  = (float*)(smem + IN_WBS);
    float* sWbt = (float*)(smem + IN_WBTS);
    if (tid < HDIM)          sWb[tid] = Wb[n * HDIM + tid];
    else if (tid < 2 * HDIM) sWbt[tid - HDIM] = Wbt[n * HDIM + tid - HDIM];

    const int crow = tid >> 2, cu = tid & 3;
    const __nv_bfloat16* w1hp = w1h + (size_t)n * 64 * 256;
    const __nv_bfloat16* w1lp = w1l + (size_t)n * 64 * 256;
    const __nv_bfloat16* wwhp = wwh + (size_t)n * 256 * 64;
    const __nv_bfloat16* wwlp = wwl + (size_t)n * 256 * 64;

#define IN_ISSUE(CI) do {                                           \
    const int k0_ = (CI) * 32;                                      \
    const uint32_t st_ = sb + ((CI) % 3) * IA_SZ;                   \
    const uint32_t d = st_ + crow * 80 + cu * 16;                   \
    const size_t ga = (size_t)(m0 + crow) * 256 + k0_ + cu * 8;     \
    const size_t gw = (size_t)crow * 256 + k0_ + cu * 8;            \
    CP_ASYNC16(d,         eh + ga);                                 \
    CP_ASYNC16(d + 5120,  el + ga);                                 \
    CP_ASYNC16(d + 10240, w1hp + gw);                               \
    CP_ASYNC16(d + 15360, w1lp + gw);                               \
    CP_COMMIT();                                                    \
} while (0)

    const int arow = (lane & 7) + ((lane >> 3) & 1) * 8;
    const int acol = (lane >> 4) * 8;
    const int brow = (lane & 7) + (lane >> 4) * 8;
    const int bcol = ((lane >> 3) & 1) * 8;

    const int wmA = (w >> 1) * 16, wnA = (w & 1) * 32;
    float accA[4][4];
#pragma unroll
    for (int i = 0; i < 4; i++)
#pragma unroll
        for (int q = 0; q < 4; q++) accA[i][q] = 0.f;

    IN_ISSUE(0);
    IN_ISSUE(1);

#pragma unroll 1
    for (int ci = 0; ci < 8; ci++) {
        if (ci < 7) CP_WAIT1(); else CP_WAIT0();
        __syncthreads();
        if (ci < 6) IN_ISSUE(ci + 2);

        const uint32_t st = sb + (ci % 3) * IA_SZ;
#pragma unroll
        for (int kk = 0; kk < 32; kk += 16) {
            uint32_t ah[4], al[4];
            const uint32_t aaddr = st + (wmA + arow) * 80 + (kk + acol) * 2;
            LDSM4(ah, aaddr);
            LDSM4(al, aaddr + 5120);
            uint32_t bh[4][2], bl[4][2];
#pragma unroll
            for (int g = 0; g < 2; g++) {
                const uint32_t baddr = st + 10240
                    + (wnA + g * 16 + brow) * 80 + (kk + bcol) * 2;
                uint32_t r[4];
                LDSM4(r, baddr);
                bh[2 * g][0] = r[0]; bh[2 * g][1] = r[1];
                bh[2 * g + 1][0] = r[2]; bh[2 * g + 1][1] = r[3];
                LDSM4(r, baddr + 5120);
                bl[2 * g][0] = r[0]; bl[2 * g][1] = r[1];
                bl[2 * g + 1][0] = r[2]; bl[2 * g + 1][1] = r[3];
            }
#pragma unroll
            for (int nf = 0; nf < 4; nf++) {
                mma_bf16(accA[nf], ah, bh[nf]);
                mma_bf16(accA[nf], ah, bl[nf]);
                mma_bf16(accA[nf], al, bh[nf]);
            }
        }
    }
#undef IN_ISSUE

    {
        const int r0 = wmA + (lane >> 2);
#pragma unroll
        for (int nf = 0; nf < 4; nf++) {
            const int col = wnA + nf * 8 + (lane & 3) * 2;
            const float bb0 = (col < HDIM)     ? b1[n * HDIM + col]     : 0.f;
            const float bb1 = (col + 1 < HDIM) ? b1[n * HDIM + col + 1] : 0.f;
            float v00 = fmaxf(accA[nf][0] + bb0, 0.f);
            float v01 = fmaxf(accA[nf][1] + bb1, 0.f);
            float v10 = fmaxf(accA[nf][2] + bb0, 0.f);
            float v11 = fmaxf(accA[nf][3] + bb1, 0.f);
            uint32_t h0, l0, h1, l1;
            split2(v00, v01, h0, l0);
            split2(v10, v11, h1, l1);
            *(uint32_t*)(smem + IN_HH + r0 * 144 + col * 2) = h0;
            *(uint32_t*)(smem + IN_HL + r0 * 144 + col * 2) = l0;
            *(uint32_t*)(smem + IN_HH + (r0 + 8) * 144 + col * 2) = h1;
            *(uint32_t*)(smem + IN_HL + (r0 + 8) * 144 + col * 2) = l1;
        }
    }
    __syncthreads();

#define IN_ISSUE_B(KK) do {                                         \
    const uint32_t st_ = sb + ((KK) % 3) * IB_SZ;                   \
    const uint32_t d = st_ + tid * 48;                              \
    const size_t g = (size_t)tid * 64 + (KK) * 16;                  \
    CP_ASYNC16(d,          wwhp + g);                               \
    CP_ASYNC16(d + 16,     wwhp + g + 8);                           \
    CP_ASYNC16(d + 12288,      wwlp + g);                           \
    CP_ASYNC16(d + 12288 + 16, wwlp + g + 8);                       \
    CP_COMMIT();                                                    \
} while (0)

    const int wmB = (w >> 1) * 16, wnB = (w & 1) * 128;
    float z[16][4];
#pragma unroll
    for (int nf = 0; nf < 16; nf++)
#pragma unroll
        for (int q = 0; q < 4; q++) z[nf][q] = 0.f;

    IN_ISSUE_B(0);
    IN_ISSUE_B(1);

#pragma unroll 1
    for (int kk = 0; kk < 4; kk++) {
        if (kk < 3) CP_WAIT1(); else CP_WAIT0();
        __syncthreads();
        if (kk < 2) IN_ISSUE_B(kk + 2);

        const uint32_t st = sb + (kk % 3) * IB_SZ;
        uint32_t ah[4], al[4];
        const uint32_t aaddr = sb + IN_HH + (wmB + arow) * 144 + (kk * 16 + acol) * 2;
        LDSM4(ah, aaddr);
        LDSM4(al, aaddr + (IN_HL - IN_HH));
#pragma unroll
        for (int g = 0; g < 8; g++) {
            const uint32_t baddr = st + (wnB + g * 16 + brow) * 48 + bcol * 2;
            uint32_t rh[4], rl[4];
            LDSM4(rh, baddr);
            LDSM4(rl, baddr + 12288);
            uint32_t b0h[2] = {rh[0], rh[1]}, b1h[2] = {rh[2], rh[3]};
            uint32_t b0l[2] = {rl[0], rl[1]}, b1l[2] = {rl[2], rl[3]};
            mma_bf16(z[2 * g],     ah, b0h);
            mma_bf16(z[2 * g],     ah, b0l);
            mma_bf16(z[2 * g],     al, b0h);
            mma_bf16(z[2 * g + 1], ah, b1h);
            mma_bf16(z[2 * g + 1], ah, b1l);
            mma_bf16(z[2 * g + 1], al, b1h);
        }
    }
#undef IN_ISSUE_B

    float* redmax = (float*)(smem + IN_RED);
    float* redse  = redmax + 128;
    float* redsx  = redse + 128;

    const int r0 = wmB + (lane >> 2), r1 = r0 + 8;
    float mx0 = -1e30f, mx1 = -1e30f;
#pragma unroll
    for (int nf = 0; nf < 16; nf++) {
        const int col = wnB + nf * 8 + (lane & 3) * 2;
        float2 bwv = *(const float2*)&bw[n * 256 + col];
        z[nf][0] += bwv.x; z[nf][1] += bwv.y;
        z[nf][2] += bwv.x; z[nf][3] += bwv.y;
        mx0 = fmaxf(mx0, fmaxf(z[nf][0], z[nf][1]));
        mx1 = fmaxf(mx1, fmaxf(z[nf][2], z[nf][3]));
    }
    mx0 = fmaxf(mx0, __shfl_xor_sync(0xffffffffu, mx0, 1));
    mx0 = fmaxf(mx0, __shfl_xor_sync(0xffffffffu, mx0, 2));
    mx1 = fmaxf(mx1, __shfl_xor_sync(0xffffffffu, mx1, 1));
    mx1 = fmaxf(mx1, __shfl_xor_sync(0xffffffffu, mx1, 2));
    if ((lane & 3) == 0) {
        redmax[(w & 1) * 64 + r0] = mx0;
        redmax[(w & 1) * 64 + r1] = mx1;
    }
    __syncthreads();
    mx0 = fmaxf(redmax[r0], redmax[64 + r0]);
    mx1 = fmaxf(redmax[r1], redmax[64 + r1]);

    float se0 = 0.f, sx0 = 0.f, se1 = 0.f, sx1 = 0.f;
    const float* x0 = x + (size_t)(m0 + r0) * 256;
    const float* x1 = x + (size_t)(m0 + r1) * 256;
#pragma unroll
    for (int nf = 0; nf < 16; nf++) {
        const int col = wnB + nf * 8 + (lane & 3) * 2;
        float2 xv0 = *(const float2*)&x0[col];
        float2 xv1 = *(const float2*)&x1[col];
        float e;
        e = __expf(z[nf][0] - mx0); se0 += e; sx0 = fmaf(e, xv0.x, sx0);
        e = __expf(z[nf][1] - mx0); se0 += e; sx0 = fmaf(e, xv0.y, sx0);
        e = __expf(z[nf][2] - mx1); se1 += e; sx1 = fmaf(e, xv1.x, sx1);
        e = __expf(z[nf][3] - mx1); se1 += e; sx1 = fmaf(e, xv1.y, sx1);
    }
#pragma unroll
    for (int off = 1; off <= 2; off <<= 1) {
        se0 += __shfl_xor_sync(0xffffffffu, se0, off);
        sx0 += __shfl_xor_sync(0xffffffffu, sx0, off);
        se1 += __shfl_xor_sync(0xffffffffu, se1, off);
        sx1 += __shfl_xor_sync(0xffffffffu, sx1, off);
    }
    if ((lane & 3) == 0) {
        redse[(w & 1) * 64 + r0] = se0; redse[(w & 1) * 64 + r1] = se1;
        redsx[(w & 1) * 64 + r0] = sx0; redsx[(w & 1) * 64 + r1] = sx1;
    }
    __syncthreads();

    if ((w & 1) == 0) {
        float pb0 = 0.f, pbt0 = 0.f, pb1 = 0.f, pbt1 = 0.f;
        for (int j = (lane & 3); j < HDIM; j += 4) {
            float h0 = __bfloat162float(*(const __nv_bfloat16*)(smem + IN_HH + r0 * 144 + j * 2))
                     + __bfloat162float(*(const __nv_bfloat16*)(smem + IN_HL + r0 * 144 + j * 2));
            float h1 = __bfloat162float(*(const __nv_bfloat16*)(smem + IN_HH + r1 * 144 + j * 2))
                     + __bfloat162float(*(const __nv_bfloat16*)(smem + IN_HL + r1 * 144 + j * 2));
            pb0  = fmaf(h0, sWb[j],  pb0);
            pbt0 = fmaf(h0, sWbt[j], pbt0);
            pb1  = fmaf(h1, sWb[j],  pb1);
            pbt1 = fmaf(h1, sWbt[j], pbt1);
        }
#pragma unroll
        for (int off = 1; off <= 2; off <<= 1) {
            pb0  += __shfl_xor_sync(0xffffffffu, pb0, off);
            pbt0 += __shfl_xor_sync(0xffffffffu, pbt0, off);
            pb1  += __shfl_xor_sync(0xffffffffu, pb1, off);
            pbt1 += __shfl_xor_sync(0xffffffffu, pbt1, off);
        }
        if ((lane & 3) == 0) {
            const float bbn = bb[n], bbtn = bbt[n];
            float seA = redse[r0] + redse[64 + r0];
            float sxA = redsx[r0] + redsx[64 + r0];
            float val = (pbt0 + bbtn) * (sxA / seA + pb0 + bbn);
            pR[(size_t)n * BATCH + m0 + r0] = 1.f / (1.f + __expf(-val));
            seA = redse[r1] + redse[64 + r1];
            sxA = redsx[r1] + redsx[64 + r1];
            val = (pbt1 + bbtn) * (sxA / seA + pb1 + bbn);
            pR[(size_t)n * BATCH + m0 + r1] = 1.f / (1.f + __expf(-val));
        }
    }
}

// ---------------------------------------------------------------------------
// Combine
// ---------------------------------------------------------------------------
__global__ __launch_bounds__(256) void combine_kernel(
    const float* __restrict__ pR, const float* __restrict__ yl,
    const float* __restrict__ b2, float* __restrict__ out)
{
    const int b = blockIdx.x * 256 + threadIdx.x;
    float p[N_INNER];
#pragma unroll
    for (int i = 0; i < N_INNER; i++) p[i] = pR[(size_t)i * BATCH + b];

    float prob[N_LEAF];
    prob[0] = 1.f;
#pragma unroll
    for (int lev = 0; lev < 5; lev++) {
        const int cnt = 1 << lev;
        const int off = cnt - 1;
#pragma unroll
        for (int i = N_LEAF - 1; i >= 0; i--) {
            if (i < cnt) {
                float pr   = p[off + i];
                float base = prob[i];
                prob[2 * i]     = base * (1.f - pr);
                prob[2 * i + 1] = base * pr;
            }
        }
    }
    float acc = 0.f;
#pragma unroll
    for (int l = 0; l < N_LEAF; l++)
        acc = fmaf(prob[l], yl[(size_t)l * BATCH + b] + b2[l], acc);
    out[b] = acc;
}

// ---------------------------------------------------------------------------
extern "C" void kernel_launch(void* const* d_in, const int* in_sizes, int n_in,
                              void* d_out, int out_size)
{
    const float* x       = (const float*)d_in[0];
    const float* enc_W   = (const float*)d_in[1];
    const float* enc_b   = (const float*)d_in[2];
    const float* in_W1   = (const float*)d_in[3];
    const float* in_b1   = (const float*)d_in[4];
    const float* in_Ww   = (const float*)d_in[5];
    const float* in_bw   = (const float*)d_in[6];
    const float* in_Wb   = (const float*)d_in[7];
    const float* in_bb   = (const float*)d_in[8];
    const float* in_Wbt  = (const float*)d_in[9];
    const float* in_bbt  = (const float*)d_in[10];
    const float* lf_W1   = (const float*)d_in[11];
    const float* lf_b1   = (const float*)d_in[12];
    const float* lf_W2   = (const float*)d_in[13];
    const float* lf_b2   = (const float*)d_in[14];
    float* out = (float*)d_out;

    float *pR, *yl, *srp, *wscp;
    __nv_bfloat16 *xh, *xl, *e0h, *e0l, *e1h, *e1l, *wth, *wtl;
    __nv_bfloat16 *w1th, *w1tl, *wwth, *wwtl;
    int8_t *eq1, *eq2, *wq1, *wq2;
    cudaGetSymbolAddress((void**)&pR,  g_pR);
    cudaGetSymbolAddress((void**)&yl,  g_yleaf);
    cudaGetSymbolAddress((void**)&xh,  g_xh);
    cudaGetSymbolAddress((void**)&xl,  g_xl);
    cudaGetSymbolAddress((void**)&e0h, g_e0h);
    cudaGetSymbolAddress((void**)&e0l, g_e0l);
    cudaGetSymbolAddress((void**)&e1h, g_e1h);
    cudaGetSymbolAddress((void**)&e1l, g_e1l);
    cudaGetSymbolAddress((void**)&wth, g_wth);
    cudaGetSymbolAddress((void**)&wtl, g_wtl);
    cudaGetSymbolAddress((void**)&w1th, g_w1th);
    cudaGetSymbolAddress((void**)&w1tl, g_w1tl);
    cudaGetSymbolAddress((void**)&wwth, g_wwth);
    cudaGetSymbolAddress((void**)&wwtl, g_wwtl);
    cudaGetSymbolAddress((void**)&eq1, g_eq1);
    cudaGetSymbolAddress((void**)&eq2, g_eq2);
    cudaGetSymbolAddress((void**)&srp, g_sr);
    cudaGetSymbolAddress((void**)&wq1, g_wq1);
    cudaGetSymbolAddress((void**)&wq2, g_wq2);
    cudaGetSymbolAddress((void**)&wscp, g_wsc);

    cudaFuncSetAttribute(enc_kernel,   cudaFuncAttributeMaxDynamicSharedMemorySize, ENC_SMEM);
    cudaFuncSetAttribute(enc4_kernel,  cudaFuncAttributeMaxDynamicSharedMemorySize, E4_SMEM);
    cudaFuncSetAttribute(leaf_i8_kernel, cudaFuncAttributeMaxDynamicSharedMemorySize, LQ_SMEM);
    cudaFuncSetAttribute(inner_mma_kernel, cudaFuncAttributeMaxDynamicSharedMemorySize, IN_SMEM);

    // 1) prep (fixed coalesced leaf-W quantization, 4x parallel tail)
    prep_all_kernel<<<PR_LQ, 256>>>(x, xh, xl, in_W1, w1th, w1tl,
                                    in_Ww, wwth, wwtl, yl,
                                    enc_W, wth, wtl,
                                    lf_W1, wq1, wq2, wscp);

    // 2-4) encoder L1-L3
    enc_kernel<<<dim3(128, 2), 256, ENC_SMEM>>>(xh, xl, wth, wtl,
        enc_b, e0h, e0l);
    enc_kernel<<<dim3(128, 2), 256, ENC_SMEM>>>(e0h, e0l, wth + 65536, wtl + 65536,
        enc_b + 256, e1h, e1l);
    enc_kernel<<<dim3(128, 2), 256, ENC_SMEM>>>(e1h, e1l, wth + 2 * 65536, wtl + 2 * 65536,
        enc_b + 512, e0h, e0l);

    // 5) encoder L4 + int8 quantization of E
    enc4_kernel<<<128, 512, E4_SMEM>>>(e0h, e0l, wth + 3 * 65536, wtl + 3 * 65536,
        enc_b + 768, e1h, e1l, eq1, eq2, srp);

    // 6) leaves via int8 IMMA
    leaf_i8_kernel<<<dim3(128, 2, N_LEAF), 256, LQ_SMEM>>>(
        eq1, eq2, wq1, wq2, srp, wscp, lf_b1, lf_W2, yl);

    // 7) inner gates (bf16)
    inner_mma_kernel<<<dim3(BATCH / 64, N_INNER), 256, IN_SMEM>>>(
        e1h, e1l, w1th, w1tl, wwth, wwtl,
        x, in_b1, in_bw, in_Wb, in_bb, in_Wbt, in_bbt, pR);

    // 8) combine
    combine_kernel<<<BATCH / 256, 256>>>(pR, yl, lf_b2, out);
}

// round 11
// speedup vs baseline: 2.7272x; 2.2015x over previous
#include <cuda_runtime.h>
#include <cuda_bf16.h>
#include <cuda_fp16.h>
#include <cstdint>
#include <math.h>

#define BATCH 8192
#define EDIM  256
#define HDIM  50
#define N_INNER 31
#define N_LEAF  32

// ---------------------------------------------------------------------------
// Device scratch
// ---------------------------------------------------------------------------
__device__ float g_pR[N_INNER * BATCH];
__device__ float g_yleaf[N_LEAF * BATCH];

__device__ __nv_bfloat16 g_xh[BATCH * EDIM];
__device__ __nv_bfloat16 g_xl[BATCH * EDIM];
__device__ __nv_bfloat16 g_e0h[BATCH * EDIM];
__device__ __nv_bfloat16 g_e0l[BATCH * EDIM];
__device__ __nv_bfloat16 g_e1h[BATCH * EDIM];
__device__ __nv_bfloat16 g_e1l[BATCH * EDIM];
__device__ __half g_ef[BATCH * EDIM];                 // final emb, fp16 single
// encoder weights transposed [4][N=256][K=256] bf16 hi/lo
__device__ __nv_bfloat16 g_wth[4 * 65536];
__device__ __nv_bfloat16 g_wtl[4 * 65536];
// leaf weights transposed [32][N=256][K=256] fp16 hi/lo
__device__ __half g_lwh[N_LEAF * 65536];
__device__ __half g_lwl[N_LEAF * 65536];
// inner W1 transposed [31][64][256] fp16 hi/lo, Ww transposed [31][256][64]
__device__ __half g_w1h[N_INNER * 64 * 256];
__device__ __half g_w1l[N_INNER * 64 * 256];
__device__ __half g_wwh[N_INNER * 256 * 64];
__device__ __half g_wwl[N_INNER * 256 * 64];

// ---------------------------------------------------------------------------
// Helpers
// ---------------------------------------------------------------------------
__device__ __forceinline__ uint32_t smem_u32(const void* p) {
    uint32_t a;
    asm("{ .reg .u64 t; cvta.to.shared.u64 t, %1; cvt.u32.u64 %0, t; }" : "=r"(a) : "l"(p));
    return a;
}
#define CP_ASYNC16(dst, src) \
    asm volatile("cp.async.cg.shared.global [%0], [%1], 16;" :: "r"(dst), "l"(src) : "memory")
#define CP_COMMIT() asm volatile("cp.async.commit_group;" ::: "memory")
#define CP_WAIT1()  asm volatile("cp.async.wait_group 1;" ::: "memory")
#define CP_WAIT0()  asm volatile("cp.async.wait_group 0;" ::: "memory")

#define LDSM4(r, addr) \
    asm volatile("ldmatrix.sync.aligned.m8n8.x4.shared.b16 {%0,%1,%2,%3}, [%4];" \
        : "=r"((r)[0]), "=r"((r)[1]), "=r"((r)[2]), "=r"((r)[3]) : "r"(addr))

__device__ __forceinline__ void mma_bf16(float* c, const uint32_t* a, const uint32_t* b) {
    asm volatile(
        "mma.sync.aligned.m16n8k16.row.col.f32.bf16.bf16.f32 "
        "{%0,%1,%2,%3}, {%4,%5,%6,%7}, {%8,%9}, {%0,%1,%2,%3};"
        : "+f"(c[0]), "+f"(c[1]), "+f"(c[2]), "+f"(c[3])
        : "r"(a[0]), "r"(a[1]), "r"(a[2]), "r"(a[3]), "r"(b[0]), "r"(b[1]));
}

__device__ __forceinline__ void mma_f16(float* c, const uint32_t* a, const uint32_t* b) {
    asm volatile(
        "mma.sync.aligned.m16n8k16.row.col.f32.f16.f16.f32 "
        "{%0,%1,%2,%3}, {%4,%5,%6,%7}, {%8,%9}, {%0,%1,%2,%3};"
        : "+f"(c[0]), "+f"(c[1]), "+f"(c[2]), "+f"(c[3])
        : "r"(a[0]), "r"(a[1]), "r"(a[2]), "r"(a[3]), "r"(b[0]), "r"(b[1]));
}

__device__ __forceinline__ void split2(float a, float b, uint32_t& hi, uint32_t& lo) {
    __nv_bfloat16 h0 = __float2bfloat16(a), h1 = __float2bfloat16(b);
    __nv_bfloat16 l0 = __float2bfloat16(a - __bfloat162float(h0));
    __nv_bfloat16 l1 = __float2bfloat16(b - __bfloat162float(h1));
    __nv_bfloat16 hh[2] = {h0, h1}, ll[2] = {l0, l1};
    hi = *(uint32_t*)hh;
    lo = *(uint32_t*)ll;
}

// ---------------------------------------------------------------------------
// Mega-prep. Regions by blockIdx.x:
// x split bf16 | W1 fp16 hi/lo | Ww fp16 hi/lo | zero yl |
// enc-W transpose bf16 (4x64) | leaf-W transpose fp16 (32x64)
// ---------------------------------------------------------------------------
#define PR_X   2048
#define PR_W1  (PR_X + 1984)
#define PR_WW  (PR_W1 + 1984)
#define PR_Z   (PR_WW + 256)
#define PR_WTE (PR_Z + 4 * 64)
#define PR_WTL (PR_WTE + 32 * 64)

__global__ __launch_bounds__(256) void prep_all_kernel(
    const float* __restrict__ x, __nv_bfloat16* __restrict__ xh,
    __nv_bfloat16* __restrict__ xl,
    const float* __restrict__ W1, __half* __restrict__ w1h,
    __half* __restrict__ w1l,
    const float* __restrict__ Ww, __half* __restrict__ wwh,
    __half* __restrict__ wwl,
    float* __restrict__ yl,
    const float* __restrict__ encW, __nv_bfloat16* __restrict__ wth,
    __nv_bfloat16* __restrict__ wtl,
    const float* __restrict__ lfW, __half* __restrict__ lwh,
    __half* __restrict__ lwl)
{
    const int bid = blockIdx.x;
    const int t = threadIdx.x;
    if (bid < PR_X) {
        int i = bid * 256 + t;
        float4 v = ((const float4*)x)[i];
        float f[4] = {v.x, v.y, v.z, v.w};
        __nv_bfloat16 h[4], l[4];
#pragma unroll
        for (int j = 0; j < 4; j++) {
            h[j] = __float2bfloat16(f[j]);
            l[j] = __float2bfloat16(f[j] - __bfloat162float(h[j]));
        }
        *(uint2*)(xh + 4 * (size_t)i) = *(uint2*)h;
        *(uint2*)(xl + 4 * (size_t)i) = *(uint2*)l;
    } else if (bid < PR_W1) {
        int idx = (bid - PR_X) * 256 + t;
        int k = idx & 255, j = (idx >> 8) & 63, n = idx >> 14;
        float v = (j < HDIM) ? W1[((size_t)n * 256 + k) * HDIM + j] : 0.f;
        __half h = __float2half(v);
        w1h[idx] = h;
        w1l[idx] = __float2half(v - __half2float(h));
    } else if (bid < PR_WW) {
        int idx = (bid - PR_W1) * 256 + t;
        int j = idx & 63, d = (idx >> 6) & 255, n = idx >> 14;
        float v = (j < HDIM) ? Ww[((size_t)n * HDIM + j) * 256 + d] : 0.f;
        __half h = __float2half(v);
        wwh[idx] = h;
        wwl[idx] = __float2half(v - __half2float(h));
    } else if (bid < PR_Z) {
        int i = (bid - PR_WW) * 256 + t;
        ((float4*)yl)[i] = make_float4(0.f, 0.f, 0.f, 0.f);
    } else if (bid < PR_WTE) {
        __shared__ float tt[32][33];
        const int rel = bid - PR_Z;
        const int mat = rel >> 6;
        const int sub = rel & 63;
        const int nb = (sub & 7) * 32, kb = (sub >> 3) * 32;
        const int tx = t & 31, ty = t >> 5;
        const float* src = encW + (size_t)mat * 65536;
#pragma unroll
        for (int i = 0; i < 4; i++)
            tt[ty + 8 * i][tx] = src[(size_t)(kb + ty + 8 * i) * 256 + nb + tx];
        __syncthreads();
#pragma unroll
        for (int i = 0; i < 4; i++) {
            float v = tt[tx][ty + 8 * i];
            size_t idx = (size_t)mat * 65536 + (size_t)(nb + ty + 8 * i) * 256 + kb + tx;
            __nv_bfloat16 h = __float2bfloat16(v);
            wth[idx] = h;
            wtl[idx] = __float2bfloat16(v - __bfloat162float(h));
        }
    } else {
        __shared__ float tt[32][33];
        const int rel = bid - PR_WTE;
        const int mat = rel >> 6;
        const int sub = rel & 63;
        const int nb = (sub & 7) * 32, kb = (sub >> 3) * 32;
        const int tx = t & 31, ty = t >> 5;
        const float* src = lfW + (size_t)mat * 65536;
#pragma unroll
        for (int i = 0; i < 4; i++)
            tt[ty + 8 * i][tx] = src[(size_t)(kb + ty + 8 * i) * 256 + nb + tx];
        __syncthreads();
#pragma unroll
        for (int i = 0; i < 4; i++) {
            float v = tt[tx][ty + 8 * i];
            size_t idx = (size_t)mat * 65536 + (size_t)(nb + ty + 8 * i) * 256 + kb + tx;
            __half h = __float2half(v);
            lwh[idx] = h;
            lwl[idx] = __float2half(v - __half2float(h));
        }
    }
}

// ---------------------------------------------------------------------------
// Encoder GEMM (M=64, N=128, 3-stage, 256 thr, bf16 3-MMA). Proven.
// MODE 0: emit bf16 hi/lo.  MODE 1 (L4): emit fp16 single.
// ---------------------------------------------------------------------------
#define E_AH 0
#define E_AL 5120
#define E_BH 10240
#define E_BL 20480
#define E_SZ 30720
#define ENC_SMEM (3 * E_SZ)

template <int MODE>
__global__ __launch_bounds__(256, 2) void enc_kernel(
    const __nv_bfloat16* __restrict__ Ah, const __nv_bfloat16* __restrict__ Al,
    const __nv_bfloat16* __restrict__ Bh, const __nv_bfloat16* __restrict__ Bl,
    const float* __restrict__ bias,
    __nv_bfloat16* __restrict__ oh, __nv_bfloat16* __restrict__ ol,
    __half* __restrict__ ef)
{
    extern __shared__ char smem[];
    const uint32_t sbase = smem_u32(smem);
    const int tid = threadIdx.x;
    const int lane = tid & 31, warp = tid >> 5;
    const int m0 = blockIdx.x * 64;
    const int n0 = blockIdx.y * 128;
    const int wm = (warp >> 2) * 32;
    const int wn = (warp & 3) * 32;

    float c[2][4][4];
#pragma unroll
    for (int mf = 0; mf < 2; mf++)
#pragma unroll
        for (int nf = 0; nf < 4; nf++)
#pragma unroll
            for (int q = 0; q < 4; q++) c[mf][nf][q] = 0.f;

    const int crow = tid >> 2;
    const int cu   = tid & 3;
    const int arow = (lane & 7) + ((lane >> 3) & 1) * 8;
    const int acol = (lane >> 4) * 8;
    const int brow = (lane & 7) + (lane >> 4) * 8;
    const int bcol = ((lane >> 3) & 1) * 8;

#define E_ISSUE(CI) do {                                                        \
    const int k0_ = (CI) * 32;                                                  \
    const uint32_t st_ = sbase + ((CI) % 3) * E_SZ;                             \
    const uint32_t da = st_ + crow * 80 + cu * 16;                              \
    const size_t ga = (size_t)(m0 + crow) * 256 + k0_ + cu * 8;                 \
    const size_t gb = (size_t)(n0 + crow) * 256 + k0_ + cu * 8;                 \
    CP_ASYNC16(da,         Ah + ga);                                            \
    CP_ASYNC16(da + E_AL,  Al + ga);                                            \
    CP_ASYNC16(st_ + E_BH + crow * 80 + cu * 16,        Bh + gb);               \
    CP_ASYNC16(st_ + E_BH + (crow + 64) * 80 + cu * 16, Bh + gb + 64 * 256);    \
    CP_ASYNC16(st_ + E_BL + crow * 80 + cu * 16,        Bl + gb);               \
    CP_ASYNC16(st_ + E_BL + (crow + 64) * 80 + cu * 16, Bl + gb + 64 * 256);    \
    CP_COMMIT();                                                                \
} while (0)

    E_ISSUE(0);
    E_ISSUE(1);

#pragma unroll 1
    for (int ci = 0; ci < 8; ci++) {
        if (ci < 7) CP_WAIT1(); else CP_WAIT0();
        __syncthreads();
        if (ci < 6) E_ISSUE(ci + 2);

        const uint32_t st = sbase + (ci % 3) * E_SZ;
#pragma unroll
        for (int kk = 0; kk < 32; kk += 16) {
            uint32_t ah[2][4], al[2][4];
#pragma unroll
            for (int mf = 0; mf < 2; mf++) {
                uint32_t addr = st + (wm + mf * 16 + arow) * 80 + (kk + acol) * 2;
                LDSM4(ah[mf], addr);
                LDSM4(al[mf], addr + E_AL);
            }
            uint32_t bhf[4][2], blf[4][2];
#pragma unroll
            for (int np = 0; np < 2; np++) {
                uint32_t addr = st + E_BH
                              + (wn + np * 16 + brow) * 80 + (kk + bcol) * 2;
                uint32_t r[4];
                LDSM4(r, addr);
                bhf[2 * np][0] = r[0]; bhf[2 * np][1] = r[1];
                bhf[2 * np + 1][0] = r[2]; bhf[2 * np + 1][1] = r[3];
                LDSM4(r, addr + (E_BL - E_BH));
                blf[2 * np][0] = r[0]; blf[2 * np][1] = r[1];
                blf[2 * np + 1][0] = r[2]; blf[2 * np + 1][1] = r[3];
            }
#pragma unroll
            for (int mf = 0; mf < 2; mf++)
#pragma unroll
                for (int nf = 0; nf < 4; nf++) {
                    mma_bf16(c[mf][nf], ah[mf], bhf[nf]);
                    mma_bf16(c[mf][nf], ah[mf], blf[nf]);
                    mma_bf16(c[mf][nf], al[mf], bhf[nf]);
                }
        }
    }
#undef E_ISSUE

    const int erow = lane >> 2;
    const int ecol = (lane & 3) * 2;
#pragma unroll
    for (int mf = 0; mf < 2; mf++) {
        const int gr0 = m0 + wm + mf * 16 + erow;
#pragma unroll
        for (int nf = 0; nf < 4; nf++) {
            const int gc = n0 + wn + nf * 8 + ecol;
            float2 bb = *(const float2*)&bias[gc];
            float v00 = fmaxf(c[mf][nf][0] + bb.x, 0.f);
            float v01 = fmaxf(c[mf][nf][1] + bb.y, 0.f);
            float v10 = fmaxf(c[mf][nf][2] + bb.x, 0.f);
            float v11 = fmaxf(c[mf][nf][3] + bb.y, 0.f);
            const size_t i0 = (size_t)gr0 * 256 + gc;
            const size_t i1 = (size_t)(gr0 + 8) * 256 + gc;
            if (MODE == 0) {
                uint32_t h0, l0, h1, l1;
                split2(v00, v01, h0, l0);
                split2(v10, v11, h1, l1);
                *(uint32_t*)(oh + i0) = h0;
                *(uint32_t*)(oh + i1) = h1;
                *(uint32_t*)(ol + i0) = l0;
                *(uint32_t*)(ol + i1) = l1;
            } else {
                __half p0[2] = {__float2half(v00), __float2half(v01)};
                __half p1[2] = {__float2half(v10), __float2half(v11)};
                *(uint32_t*)(ef + i0) = *(uint32_t*)p0;
                *(uint32_t*)(ef + i1) = *(uint32_t*)p1;
            }
        }
    }
}

// ---------------------------------------------------------------------------
// TAIL kernel: inner (blockIdx.x < 31) + leaf (blockIdx.x >= 31).
// Both paths fp16: activations single fp16, weights fp16 hi/lo, 2-MMA.
// grid (63, 128), block 256.
// ---------------------------------------------------------------------------
// leaf layout: stage = A(10240) Bh(10240) Bl(10240)
#define L_A   0
#define L_BH  10240
#define L_BL  20480
#define L_STG 30720
#define L_SC  (2 * L_STG)
// inner layout
#define IA_SZ  15360       // A 0 | W1h 5120 | W1l 10240
#define IB_SZ  24576       // Bh 0 | Bl 12288
#define IN_HF  73728       // H single fp16, 64 x 144
#define IN_RED 82944
#define IN_WBS 84480
#define IN_WBTS 84736
#define TAIL_SMEM 86016

__global__ __launch_bounds__(256, 2) void tail_kernel(
    const __half* __restrict__ ef,
    // inner params
    const __half* __restrict__ w1h, const __half* __restrict__ w1l,
    const __half* __restrict__ wwh, const __half* __restrict__ wwl,
    const float* __restrict__ x, const float* __restrict__ b1,
    const float* __restrict__ bw, const float* __restrict__ Wb,
    const float* __restrict__ bb, const float* __restrict__ Wbt,
    const float* __restrict__ bbt, float* __restrict__ pR,
    // leaf params
    const __half* __restrict__ Lwh, const __half* __restrict__ Lwl,
    const float* __restrict__ lbias, const float* __restrict__ w2,
    float* __restrict__ yleaf)
{
    extern __shared__ char smem[];
    const uint32_t sb = smem_u32(smem);
    const int tid = threadIdx.x, lane = tid & 31, w = tid >> 5;

    const int arow = (lane & 7) + ((lane >> 3) & 1) * 8;
    const int acol = (lane >> 4) * 8;
    const int brow = (lane & 7) + (lane >> 4) * 8;
    const int bcol = ((lane >> 3) & 1) * 8;
    const int crow = tid >> 2, cu = tid & 3;

    if (blockIdx.x < N_INNER) {
        // ================= INNER path (fp16 2-MMA) =================
        const int n = blockIdx.x, m0 = blockIdx.y * 64;

        float* sWb  = (float*)(smem + IN_WBS);
        float* sWbt = (float*)(smem + IN_WBTS);
        if (tid < HDIM)          sWb[tid] = Wb[n * HDIM + tid];
        else if (tid < 2 * HDIM) sWbt[tid - HDIM] = Wbt[n * HDIM + tid - HDIM];

        const __half* w1hp = w1h + (size_t)n * 64 * 256;
        const __half* w1lp = w1l + (size_t)n * 64 * 256;
        const __half* wwhp = wwh + (size_t)n * 256 * 64;
        const __half* wwlp = wwl + (size_t)n * 256 * 64;

#define IN_ISSUE(CI) do {                                           \
    const int k0_ = (CI) * 32;                                      \
    const uint32_t st_ = sb + ((CI) % 3) * IA_SZ;                   \
    const uint32_t d = st_ + crow * 80 + cu * 16;                   \
    const size_t ga = (size_t)(m0 + crow) * 256 + k0_ + cu * 8;     \
    const size_t gw = (size_t)crow * 256 + k0_ + cu * 8;            \
    CP_ASYNC16(d,         ef + ga);                                 \
    CP_ASYNC16(d + 5120,  w1hp + gw);                               \
    CP_ASYNC16(d + 10240, w1lp + gw);                               \
    CP_COMMIT();                                                    \
} while (0)

        // ---- Phase A: H = relu(emb @ W1^T + b1) ----
        const int wmA = (w >> 1) * 16, wnA = (w & 1) * 32;
        float accA[4][4];
#pragma unroll
        for (int i = 0; i < 4; i++)
#pragma unroll
            for (int q = 0; q < 4; q++) accA[i][q] = 0.f;

        IN_ISSUE(0);
        IN_ISSUE(1);

#pragma unroll 1
        for (int ci = 0; ci < 8; ci++) {
            if (ci < 7) CP_WAIT1(); else CP_WAIT0();
            __syncthreads();
            if (ci < 6) IN_ISSUE(ci + 2);

            const uint32_t st = sb + (ci % 3) * IA_SZ;
#pragma unroll
            for (int kk = 0; kk < 32; kk += 16) {
                uint32_t a[4];
                LDSM4(a, st + (wmA + arow) * 80 + (kk + acol) * 2);
                uint32_t bh[4][2], bl[4][2];
#pragma unroll
                for (int g = 0; g < 2; g++) {
                    const uint32_t baddr = st + 5120
                        + (wnA + g * 16 + brow) * 80 + (kk + bcol) * 2;
                    uint32_t r[4];
                    LDSM4(r, baddr);
                    bh[2 * g][0] = r[0]; bh[2 * g][1] = r[1];
                    bh[2 * g + 1][0] = r[2]; bh[2 * g + 1][1] = r[3];
                    LDSM4(r, baddr + 5120);
                    bl[2 * g][0] = r[0]; bl[2 * g][1] = r[1];
                    bl[2 * g + 1][0] = r[2]; bl[2 * g + 1][1] = r[3];
                }
#pragma unroll
                for (int nf = 0; nf < 4; nf++) {
                    mma_f16(accA[nf], a, bh[nf]);
                    mma_f16(accA[nf], a, bl[nf]);
                }
            }
        }
#undef IN_ISSUE

        // Phase A epilogue: relu(+b1) -> H fp16 single in smem
        {
            const int r0 = wmA + (lane >> 2);
#pragma unroll
            for (int nf = 0; nf < 4; nf++) {
                const int col = wnA + nf * 8 + (lane & 3) * 2;
                const float bb0 = (col < HDIM)     ? b1[n * HDIM + col]     : 0.f;
                const float bb1 = (col + 1 < HDIM) ? b1[n * HDIM + col + 1] : 0.f;
                __half p0[2] = {__float2half(fmaxf(accA[nf][0] + bb0, 0.f)),
                                __float2half(fmaxf(accA[nf][1] + bb1, 0.f))};
                __half p1[2] = {__float2half(fmaxf(accA[nf][2] + bb0, 0.f)),
                                __float2half(fmaxf(accA[nf][3] + bb1, 0.f))};
                *(uint32_t*)(smem + IN_HF + r0 * 144 + col * 2) = *(uint32_t*)p0;
                *(uint32_t*)(smem + IN_HF + (r0 + 8) * 144 + col * 2) = *(uint32_t*)p1;
            }
        }
        __syncthreads();

        // ---- Phase B: z = H @ Ww^T + bw ----
#define IN_ISSUE_B(KK) do {                                         \
    const uint32_t st_ = sb + ((KK) % 3) * IB_SZ;                   \
    const uint32_t d = st_ + tid * 48;                              \
    const size_t g = (size_t)tid * 64 + (KK) * 16;                  \
    CP_ASYNC16(d,          wwhp + g);                               \
    CP_ASYNC16(d + 16,     wwhp + g + 8);                           \
    CP_ASYNC16(d + 12288,      wwlp + g);                           \
    CP_ASYNC16(d + 12288 + 16, wwlp + g + 8);                       \
    CP_COMMIT();                                                    \
} while (0)

        const int wmB = (w >> 1) * 16, wnB = (w & 1) * 128;
        float z[16][4];
#pragma unroll
        for (int nf = 0; nf < 16; nf++)
#pragma unroll
            for (int q = 0; q < 4; q++) z[nf][q] = 0.f;

        IN_ISSUE_B(0);
        IN_ISSUE_B(1);

#pragma unroll 1
        for (int kk = 0; kk < 4; kk++) {
            if (kk < 3) CP_WAIT1(); else CP_WAIT0();
            __syncthreads();
            if (kk < 2) IN_ISSUE_B(kk + 2);

            const uint32_t st = sb + (kk % 3) * IB_SZ;
            uint32_t a[4];
            LDSM4(a, sb + IN_HF + (wmB + arow) * 144 + (kk * 16 + acol) * 2);
#pragma unroll
            for (int g = 0; g < 8; g++) {
                const uint32_t baddr = st + (wnB + g * 16 + brow) * 48 + bcol * 2;
                uint32_t rh[4], rl[4];
                LDSM4(rh, baddr);
                LDSM4(rl, baddr + 12288);
                uint32_t b0h[2] = {rh[0], rh[1]}, b1h[2] = {rh[2], rh[3]};
                uint32_t b0l[2] = {rl[0], rl[1]}, b1l[2] = {rl[2], rl[3]};
                mma_f16(z[2 * g],     a, b0h);
                mma_f16(z[2 * g],     a, b0l);
                mma_f16(z[2 * g + 1], a, b1h);
                mma_f16(z[2 * g + 1], a, b1l);
            }
        }
#undef IN_ISSUE_B

        // ---- Phase B epilogue ----
        float* redmax = (float*)(smem + IN_RED);
        float* redse  = redmax + 128;
        float* redsx  = redse + 128;

        const int r0 = wmB + (lane >> 2), r1 = r0 + 8;
        float mx0 = -1e30f, mx1 = -1e30f;
#pragma unroll
        for (int nf = 0; nf < 16; nf++) {
            const int col = wnB + nf * 8 + (lane & 3) * 2;
            float2 bwv = *(const float2*)&bw[n * 256 + col];
            z[nf][0] += bwv.x; z[nf][1] += bwv.y;
            z[nf][2] += bwv.x; z[nf][3] += bwv.y;
            mx0 = fmaxf(mx0, fmaxf(z[nf][0], z[nf][1]));
            mx1 = fmaxf(mx1, fmaxf(z[nf][2], z[nf][3]));
        }
        mx0 = fmaxf(mx0, __shfl_xor_sync(0xffffffffu, mx0, 1));
        mx0 = fmaxf(mx0, __shfl_xor_sync(0xffffffffu, mx0, 2));
        mx1 = fmaxf(mx1, __shfl_xor_sync(0xffffffffu, mx1, 1));
        mx1 = fmaxf(mx1, __shfl_xor_sync(0xffffffffu, mx1, 2));
        if ((lane & 3) == 0) {
            redmax[(w & 1) * 64 + r0] = mx0;
            redmax[(w & 1) * 64 + r1] = mx1;
        }
        __syncthreads();
        mx0 = fmaxf(redmax[r0], redmax[64 + r0]);
        mx1 = fmaxf(redmax[r1], redmax[64 + r1]);

        float se0 = 0.f, sx0 = 0.f, se1 = 0.f, sx1 = 0.f;
        const float* x0 = x + (size_t)(m0 + r0) * 256;
        const float* x1 = x + (size_t)(m0 + r1) * 256;
#pragma unroll
        for (int nf = 0; nf < 16; nf++) {
            const int col = wnB + nf * 8 + (lane & 3) * 2;
            float2 xv0 = *(const float2*)&x0[col];
            float2 xv1 = *(const float2*)&x1[col];
            float e;
            e = __expf(z[nf][0] - mx0); se0 += e; sx0 = fmaf(e, xv0.x, sx0);
            e = __expf(z[nf][1] - mx0); se0 += e; sx0 = fmaf(e, xv0.y, sx0);
            e = __expf(z[nf][2] - mx1); se1 += e; sx1 = fmaf(e, xv1.x, sx1);
            e = __expf(z[nf][3] - mx1); se1 += e; sx1 = fmaf(e, xv1.y, sx1);
        }
#pragma unroll
        for (int off = 1; off <= 2; off <<= 1) {
            se0 += __shfl_xor_sync(0xffffffffu, se0, off);
            sx0 += __shfl_xor_sync(0xffffffffu, sx0, off);
            se1 += __shfl_xor_sync(0xffffffffu, se1, off);
            sx1 += __shfl_xor_sync(0xffffffffu, sx1, off);
        }
        if ((lane & 3) == 0) {
            redse[(w & 1) * 64 + r0] = se0; redse[(w & 1) * 64 + r1] = se1;
            redsx[(w & 1) * 64 + r0] = sx0; redsx[(w & 1) * 64 + r1] = sx1;
        }
        __syncthreads();

        if ((w & 1) == 0) {
            float pb0 = 0.f, pbt0 = 0.f, pb1 = 0.f, pbt1 = 0.f;
            for (int j = (lane & 3); j < HDIM; j += 4) {
                float h0 = __half2float(*(const __half*)(smem + IN_HF + r0 * 144 + j * 2));
                float h1 = __half2float(*(const __half*)(smem + IN_HF + r1 * 144 + j * 2));
                pb0  = fmaf(h0, sWb[j],  pb0);
                pbt0 = fmaf(h0, sWbt[j], pbt0);
                pb1  = fmaf(h1, sWb[j],  pb1);
                pbt1 = fmaf(h1, sWbt[j], pbt1);
            }
#pragma unroll
            for (int off = 1; off <= 2; off <<= 1) {
                pb0  += __shfl_xor_sync(0xffffffffu, pb0, off);
                pbt0 += __shfl_xor_sync(0xffffffffu, pbt0, off);
                pb1  += __shfl_xor_sync(0xffffffffu, pb1, off);
                pbt1 += __shfl_xor_sync(0xffffffffu, pbt1, off);
            }
            if ((lane & 3) == 0) {
                const float bbn = bb[n], bbtn = bbt[n];
                float seA = redse[r0] + redse[64 + r0];
                float sxA = redsx[r0] + redsx[64 + r0];
                float val = (pbt0 + bbtn) * (sxA / seA + pb0 + bbn);
                pR[(size_t)n * BATCH + m0 + r0] = 1.f / (1.f + __expf(-val));
                seA = redse[r1] + redse[64 + r1];
                sxA = redsx[r1] + redsx[64 + r1];
                val = (pbt1 + bbtn) * (sxA / seA + pb1 + bbn);
                pR[(size_t)n * BATCH + m0 + r1] = 1.f / (1.f + __expf(-val));
            }
        }
    } else {
        // ================= LEAF path (fp16 2-MMA) =================
        const int mat = blockIdx.x - N_INNER;
        const int m0 = (blockIdx.y >> 1) * 128;
        const int n0 = (blockIdx.y & 1) * 128;
        const int wm = (w >> 1) * 32;
        const int wn = (w & 1) * 64;

        const __half* bhp = Lwh + (size_t)mat * 65536;
        const __half* blp = Lwl + (size_t)mat * 65536;

        float* s_bias = (float*)(smem + L_SC);
        float* s_w2   = (float*)(smem + L_SC + 512);
        if (tid < 128) {
            s_bias[tid] = lbias[(size_t)mat * 256 + n0 + tid];
            s_w2[tid]   = w2[(size_t)mat * 256 + n0 + tid];
        }

        float c[2][8][4];
#pragma unroll
        for (int mf = 0; mf < 2; mf++)
#pragma unroll
            for (int nf = 0; nf < 8; nf++)
#pragma unroll
                for (int q = 0; q < 4; q++) c[mf][nf][q] = 0.f;

#define L_ISSUE(CI) do {                                                        \
    const int k0_ = (CI) * 32;                                                  \
    const uint32_t st_ = sb + ((CI) & 1) * L_STG;                               \
    const uint32_t d0 = st_ + crow * 80 + cu * 16;                              \
    const uint32_t d1 = st_ + (crow + 64) * 80 + cu * 16;                       \
    const size_t ga = (size_t)(m0 + crow) * 256 + k0_ + cu * 8;                 \
    const size_t gb = (size_t)(n0 + crow) * 256 + k0_ + cu * 8;                 \
    CP_ASYNC16(d0,         ef + ga);                                            \
    CP_ASYNC16(d1,         ef + ga + 64 * 256);                                 \
    CP_ASYNC16(d0 + L_BH,  bhp + gb);                                           \
    CP_ASYNC16(d1 + L_BH,  bhp + gb + 64 * 256);                                \
    CP_ASYNC16(d0 + L_BL,  blp + gb);                                           \
    CP_ASYNC16(d1 + L_BL,  blp + gb + 64 * 256);                                \
    CP_COMMIT();                                                                \
} while (0)

        L_ISSUE(0);

#pragma unroll 1
        for (int ci = 0; ci < 8; ci++) {
            if (ci < 7) { L_ISSUE(ci + 1); CP_WAIT1(); }
            else        { CP_WAIT0(); }
            __syncthreads();

            const uint32_t st = sb + (ci & 1) * L_STG;
#pragma unroll
            for (int kk = 0; kk < 32; kk += 16) {
                uint32_t a[2][4];
#pragma unroll
                for (int mf = 0; mf < 2; mf++)
                    LDSM4(a[mf], st + (wm + mf * 16 + arow) * 80 + (kk + acol) * 2);
                uint32_t bhf[8][2], blf[8][2];
#pragma unroll
                for (int np = 0; np < 4; np++) {
                    const uint32_t addr = st + L_BH
                                  + (wn + np * 16 + brow) * 80 + (kk + bcol) * 2;
                    uint32_t r[4];
                    LDSM4(r, addr);
                    bhf[2 * np][0] = r[0]; bhf[2 * np][1] = r[1];
                    bhf[2 * np + 1][0] = r[2]; bhf[2 * np + 1][1] = r[3];
                    LDSM4(r, addr + (L_BL - L_BH));
                    blf[2 * np][0] = r[0]; blf[2 * np][1] = r[1];
                    blf[2 * np + 1][0] = r[2]; blf[2 * np + 1][1] = r[3];
                }
#pragma unroll
                for (int mf = 0; mf < 2; mf++)
#pragma unroll
                    for (int nf = 0; nf < 8; nf++) {
                        mma_f16(c[mf][nf], a[mf], bhf[nf]);
                        mma_f16(c[mf][nf], a[mf], blf[nf]);
                    }
            }
            __syncthreads();
        }
#undef L_ISSUE

        const int erow = lane >> 2;
        const int ecol = (lane & 3) * 2;
        float part[2][2] = {{0.f, 0.f}, {0.f, 0.f}};
#pragma unroll
        for (int mf = 0; mf < 2; mf++)
#pragma unroll
            for (int nf = 0; nf < 8; nf++) {
                const int lc = wn + nf * 8 + ecol;
                const float b0s = s_bias[lc], b1s = s_bias[lc + 1];
                const float w0 = s_w2[lc], w1 = s_w2[lc + 1];
                part[mf][0] = fmaf(fmaxf(c[mf][nf][0] + b0s, 0.f), w0, part[mf][0]);
                part[mf][0] = fmaf(fmaxf(c[mf][nf][1] + b1s, 0.f), w1, part[mf][0]);
                part[mf][1] = fmaf(fmaxf(c[mf][nf][2] + b0s, 0.f), w0, part[mf][1]);
                part[mf][1] = fmaf(fmaxf(c[mf][nf][3] + b1s, 0.f), w1, part[mf][1]);
            }
#pragma unroll
        for (int mf = 0; mf < 2; mf++)
#pragma unroll
            for (int h = 0; h < 2; h++) {
                part[mf][h] += __shfl_xor_sync(0xffffffffu, part[mf][h], 1);
                part[mf][h] += __shfl_xor_sync(0xffffffffu, part[mf][h], 2);
            }
        if ((lane & 3) == 0) {
#pragma unroll
            for (int mf = 0; mf < 2; mf++)
#pragma unroll
                for (int h = 0; h < 2; h++) {
                    const int row = m0 + wm + mf * 16 + h * 8 + erow;
                    atomicAdd(&yleaf[(size_t)mat * BATCH + row], part[mf][h]);
                }
        }
    }
}

// ---------------------------------------------------------------------------
// Combine
// ---------------------------------------------------------------------------
__global__ __launch_bounds__(256) void combine_kernel(
    const float* __restrict__ pR, const float* __restrict__ yl,
    const float* __restrict__ b2, float* __restrict__ out)
{
    const int b = blockIdx.x * 256 + threadIdx.x;
    float p[N_INNER];
#pragma unroll
    for (int i = 0; i < N_INNER; i++) p[i] = pR[(size_t)i * BATCH + b];

    float prob[N_LEAF];
    prob[0] = 1.f;
#pragma unroll
    for (int lev = 0; lev < 5; lev++) {
        const int cnt = 1 << lev;
        const int off = cnt - 1;
#pragma unroll
        for (int i = N_LEAF - 1; i >= 0; i--) {
            if (i < cnt) {
                float pr   = p[off + i];
                float base = prob[i];
                prob[2 * i]     = base * (1.f - pr);
                prob[2 * i + 1] = base * pr;
            }
        }
    }
    float acc = 0.f;
#pragma unroll
    for (int l = 0; l < N_LEAF; l++)
        acc = fmaf(prob[l], yl[(size_t)l * BATCH + b] + b2[l], acc);
    out[b] = acc;
}

// ---------------------------------------------------------------------------
extern "C" void kernel_launch(void* const* d_in, const int* in_sizes, int n_in,
                              void* d_out, int out_size)
{
    const float* x       = (const float*)d_in[0];
    const float* enc_W   = (const float*)d_in[1];
    const float* enc_b   = (const float*)d_in[2];
    const float* in_W1   = (const float*)d_in[3];
    const float* in_b1   = (const float*)d_in[4];
    const float* in_Ww   = (const float*)d_in[5];
    const float* in_bw   = (const float*)d_in[6];
    const float* in_Wb   = (const float*)d_in[7];
    const float* in_bb   = (const float*)d_in[8];
    const float* in_Wbt  = (const float*)d_in[9];
    const float* in_bbt  = (const float*)d_in[10];
    const float* lf_W1   = (const float*)d_in[11];
    const float* lf_b1   = (const float*)d_in[12];
    const float* lf_W2   = (const float*)d_in[13];
    const float* lf_b2   = (const float*)d_in[14];
    float* out = (float*)d_out;

    float *pR, *yl;
    __nv_bfloat16 *xh, *xl, *e0h, *e0l, *e1h, *e1l, *wth, *wtl;
    __half *ef, *lwh, *lwl, *w1h, *w1l, *wwh, *wwl;
    cudaGetSymbolAddress((void**)&pR,  g_pR);
    cudaGetSymbolAddress((void**)&yl,  g_yleaf);
    cudaGetSymbolAddress((void**)&xh,  g_xh);
    cudaGetSymbolAddress((void**)&xl,  g_xl);
    cudaGetSymbolAddress((void**)&e0h, g_e0h);
    cudaGetSymbolAddress((void**)&e0l, g_e0l);
    cudaGetSymbolAddress((void**)&e1h, g_e1h);
    cudaGetSymbolAddress((void**)&e1l, g_e1l);
    cudaGetSymbolAddress((void**)&wth, g_wth);
    cudaGetSymbolAddress((void**)&wtl, g_wtl);
    cudaGetSymbolAddress((void**)&ef,  g_ef);
    cudaGetSymbolAddress((void**)&lwh, g_lwh);
    cudaGetSymbolAddress((void**)&lwl, g_lwl);
    cudaGetSymbolAddress((void**)&w1h, g_w1h);
    cudaGetSymbolAddress((void**)&w1l, g_w1l);
    cudaGetSymbolAddress((void**)&wwh, g_wwh);
    cudaGetSymbolAddress((void**)&wwl, g_wwl);

    cudaFuncSetAttribute(enc_kernel<0>, cudaFuncAttributeMaxDynamicSharedMemorySize, ENC_SMEM);
    cudaFuncSetAttribute(enc_kernel<1>, cudaFuncAttributeMaxDynamicSharedMemorySize, ENC_SMEM);
    cudaFuncSetAttribute(tail_kernel,   cudaFuncAttributeMaxDynamicSharedMemorySize, TAIL_SMEM);

    // 1) all prep in one launch
    prep_all_kernel<<<PR_WTL, 256>>>(x, xh, xl, in_W1, w1h, w1l,
                                     in_Ww, wwh, wwl, yl,
                                     enc_W, wth, wtl, lf_W1, lwh, lwl);

    // 2-5) encoder (L1-L3 bf16 hi/lo; L4 emits fp16 single)
    enc_kernel<0><<<dim3(128, 2), 256, ENC_SMEM>>>(xh, xl, wth, wtl,
        enc_b, e0h, e0l, nullptr);
    enc_kernel<0><<<dim3(128, 2), 256, ENC_SMEM>>>(e0h, e0l, wth + 65536, wtl + 65536,
        enc_b + 256, e1h, e1l, nullptr);
    enc_kernel<0><<<dim3(128, 2), 256, ENC_SMEM>>>(e1h, e1l, wth + 2 * 65536, wtl + 2 * 65536,
        enc_b + 512, e0h, e0l, nullptr);
    enc_kernel<1><<<dim3(128, 2), 256, ENC_SMEM>>>(e0h, e0l, wth + 3 * 65536, wtl + 3 * 65536,
        enc_b + 768, nullptr, nullptr, ef);

    // 6) merged inner + leaf (fp16 2-MMA)
    tail_kernel<<<dim3(63, 128), 256, TAIL_SMEM>>>(
        ef,
        w1h, w1l, wwh, wwl, x, in_b1, in_bw, in_Wb, in_bb, in_Wbt, in_bbt, pR,
        lwh, lwl, lf_b1, lf_W2, yl);

    // 7) combine
    combine_kernel<<<BATCH / 256, 256>>>(pR, yl, lf_b2, out);
}

// round 12
// speedup vs baseline: 3.8618x; 1.4160x over previous
#include <cuda_runtime.h>
#include <cuda_bf16.h>
#include <cuda_fp16.h>
#include <cstdint>
#include <math.h>

#define BATCH 8192
#define EDIM  256
#define HDIM  50
#define N_INNER 31
#define N_LEAF  32

// ---------------------------------------------------------------------------
// Device scratch
// ---------------------------------------------------------------------------
__device__ float g_pR[N_INNER * BATCH];
__device__ float g_yleaf[N_LEAF * BATCH];

__device__ __nv_bfloat16 g_xh[BATCH * EDIM];
__device__ __nv_bfloat16 g_xl[BATCH * EDIM];
__device__ __nv_bfloat16 g_e0h[BATCH * EDIM];
__device__ __nv_bfloat16 g_e0l[BATCH * EDIM];
__device__ __nv_bfloat16 g_e1h[BATCH * EDIM];
__device__ __nv_bfloat16 g_e1l[BATCH * EDIM];
__device__ __half g_ef[BATCH * EDIM];                 // final emb, fp16 single
// encoder weights transposed [4][N=256][K=256] bf16 hi/lo
__device__ __nv_bfloat16 g_wth[4 * 65536];
__device__ __nv_bfloat16 g_wtl[4 * 65536];
// leaf weights transposed [32][N=256][K=256] fp16 single
__device__ __half g_lwh[N_LEAF * 65536];
// inner W1 transposed [31][64][256] fp16 single, Ww transposed [31][256][64]
__device__ __half g_w1h[N_INNER * 64 * 256];
__device__ __half g_wwh[N_INNER * 256 * 64];

// ---------------------------------------------------------------------------
// Helpers
// ---------------------------------------------------------------------------
__device__ __forceinline__ uint32_t smem_u32(const void* p) {
    uint32_t a;
    asm("{ .reg .u64 t; cvta.to.shared.u64 t, %1; cvt.u32.u64 %0, t; }" : "=r"(a) : "l"(p));
    return a;
}
#define CP_ASYNC16(dst, src) \
    asm volatile("cp.async.cg.shared.global [%0], [%1], 16;" :: "r"(dst), "l"(src) : "memory")
#define CP_COMMIT() asm volatile("cp.async.commit_group;" ::: "memory")
#define CP_WAIT1()  asm volatile("cp.async.wait_group 1;" ::: "memory")
#define CP_WAIT0()  asm volatile("cp.async.wait_group 0;" ::: "memory")

#define LDSM4(r, addr) \
    asm volatile("ldmatrix.sync.aligned.m8n8.x4.shared.b16 {%0,%1,%2,%3}, [%4];" \
        : "=r"((r)[0]), "=r"((r)[1]), "=r"((r)[2]), "=r"((r)[3]) : "r"(addr))

__device__ __forceinline__ void mma_bf16(float* c, const uint32_t* a, const uint32_t* b) {
    asm volatile(
        "mma.sync.aligned.m16n8k16.row.col.f32.bf16.bf16.f32 "
        "{%0,%1,%2,%3}, {%4,%5,%6,%7}, {%8,%9}, {%0,%1,%2,%3};"
        : "+f"(c[0]), "+f"(c[1]), "+f"(c[2]), "+f"(c[3])
        : "r"(a[0]), "r"(a[1]), "r"(a[2]), "r"(a[3]), "r"(b[0]), "r"(b[1]));
}

__device__ __forceinline__ void mma_f16(float* c, const uint32_t* a, const uint32_t* b) {
    asm volatile(
        "mma.sync.aligned.m16n8k16.row.col.f32.f16.f16.f32 "
        "{%0,%1,%2,%3}, {%4,%5,%6,%7}, {%8,%9}, {%0,%1,%2,%3};"
        : "+f"(c[0]), "+f"(c[1]), "+f"(c[2]), "+f"(c[3])
        : "r"(a[0]), "r"(a[1]), "r"(a[2]), "r"(a[3]), "r"(b[0]), "r"(b[1]));
}

__device__ __forceinline__ void split2(float a, float b, uint32_t& hi, uint32_t& lo) {
    __nv_bfloat16 h0 = __float2bfloat16(a), h1 = __float2bfloat16(b);
    __nv_bfloat16 l0 = __float2bfloat16(a - __bfloat162float(h0));
    __nv_bfloat16 l1 = __float2bfloat16(b - __bfloat162float(h1));
    __nv_bfloat16 hh[2] = {h0, h1}, ll[2] = {l0, l1};
    hi = *(uint32_t*)hh;
    lo = *(uint32_t*)ll;
}

// ---------------------------------------------------------------------------
// Mega-prep. Regions by blockIdx.x:
// x split bf16 | W1 fp16 | Ww fp16 | zero yl |
// enc-W transpose bf16 (4x64) | leaf-W transpose fp16 (32x64)
// ---------------------------------------------------------------------------
#define PR_X   2048
#define PR_W1  (PR_X + 1984)
#define PR_WW  (PR_W1 + 1984)
#define PR_Z   (PR_WW + 256)
#define PR_WTE (PR_Z + 4 * 64)
#define PR_WTL (PR_WTE + 32 * 64)

__global__ __launch_bounds__(256) void prep_all_kernel(
    const float* __restrict__ x, __nv_bfloat16* __restrict__ xh,
    __nv_bfloat16* __restrict__ xl,
    const float* __restrict__ W1, __half* __restrict__ w1h,
    const float* __restrict__ Ww, __half* __restrict__ wwh,
    float* __restrict__ yl,
    const float* __restrict__ encW, __nv_bfloat16* __restrict__ wth,
    __nv_bfloat16* __restrict__ wtl,
    const float* __restrict__ lfW, __half* __restrict__ lwh)
{
    const int bid = blockIdx.x;
    const int t = threadIdx.x;
    if (bid < PR_X) {
        int i = bid * 256 + t;
        float4 v = ((const float4*)x)[i];
        float f[4] = {v.x, v.y, v.z, v.w};
        __nv_bfloat16 h[4], l[4];
#pragma unroll
        for (int j = 0; j < 4; j++) {
            h[j] = __float2bfloat16(f[j]);
            l[j] = __float2bfloat16(f[j] - __bfloat162float(h[j]));
        }
        *(uint2*)(xh + 4 * (size_t)i) = *(uint2*)h;
        *(uint2*)(xl + 4 * (size_t)i) = *(uint2*)l;
    } else if (bid < PR_W1) {
        int idx = (bid - PR_X) * 256 + t;
        int k = idx & 255, j = (idx >> 8) & 63, n = idx >> 14;
        float v = (j < HDIM) ? W1[((size_t)n * 256 + k) * HDIM + j] : 0.f;
        w1h[idx] = __float2half(v);
    } else if (bid < PR_WW) {
        int idx = (bid - PR_W1) * 256 + t;
        int j = idx & 63, d = (idx >> 6) & 255, n = idx >> 14;
        float v = (j < HDIM) ? Ww[((size_t)n * HDIM + j) * 256 + d] : 0.f;
        wwh[idx] = __float2half(v);
    } else if (bid < PR_Z) {
        int i = (bid - PR_WW) * 256 + t;
        ((float4*)yl)[i] = make_float4(0.f, 0.f, 0.f, 0.f);
    } else if (bid < PR_WTE) {
        __shared__ float tt[32][33];
        const int rel = bid - PR_Z;
        const int mat = rel >> 6;
        const int sub = rel & 63;
        const int nb = (sub & 7) * 32, kb = (sub >> 3) * 32;
        const int tx = t & 31, ty = t >> 5;
        const float* src = encW + (size_t)mat * 65536;
#pragma unroll
        for (int i = 0; i < 4; i++)
            tt[ty + 8 * i][tx] = src[(size_t)(kb + ty + 8 * i) * 256 + nb + tx];
        __syncthreads();
#pragma unroll
        for (int i = 0; i < 4; i++) {
            float v = tt[tx][ty + 8 * i];
            size_t idx = (size_t)mat * 65536 + (size_t)(nb + ty + 8 * i) * 256 + kb + tx;
            __nv_bfloat16 h = __float2bfloat16(v);
            wth[idx] = h;
            wtl[idx] = __float2bfloat16(v - __bfloat162float(h));
        }
    } else {
        __shared__ float tt[32][33];
        const int rel = bid - PR_WTE;
        const int mat = rel >> 6;
        const int sub = rel & 63;
        const int nb = (sub & 7) * 32, kb = (sub >> 3) * 32;
        const int tx = t & 31, ty = t >> 5;
        const float* src = lfW + (size_t)mat * 65536;
#pragma unroll
        for (int i = 0; i < 4; i++)
            tt[ty + 8 * i][tx] = src[(size_t)(kb + ty + 8 * i) * 256 + nb + tx];
        __syncthreads();
#pragma unroll
        for (int i = 0; i < 4; i++) {
            float v = tt[tx][ty + 8 * i];
            size_t idx = (size_t)mat * 65536 + (size_t)(nb + ty + 8 * i) * 256 + kb + tx;
            lwh[idx] = __float2half(v);
        }
    }
}

// ---------------------------------------------------------------------------
// Encoder GEMM (M=64, N=128, 3-stage, 256 thr, bf16 3-MMA). Proven.
// MODE 0: emit bf16 hi/lo.  MODE 1 (L4): emit fp16 single.
// ---------------------------------------------------------------------------
#define E_AL 5120
#define E_BH 10240
#define E_BL 20480
#define E_SZ 30720
#define ENC_SMEM (3 * E_SZ)

template <int MODE>
__global__ __launch_bounds__(256, 2) void enc_kernel(
    const __nv_bfloat16* __restrict__ Ah, const __nv_bfloat16* __restrict__ Al,
    const __nv_bfloat16* __restrict__ Bh, const __nv_bfloat16* __restrict__ Bl,
    const float* __restrict__ bias,
    __nv_bfloat16* __restrict__ oh, __nv_bfloat16* __restrict__ ol,
    __half* __restrict__ ef)
{
    extern __shared__ char smem[];
    const uint32_t sbase = smem_u32(smem);
    const int tid = threadIdx.x;
    const int lane = tid & 31, warp = tid >> 5;
    const int m0 = blockIdx.x * 64;
    const int n0 = blockIdx.y * 128;
    const int wm = (warp >> 2) * 32;
    const int wn = (warp & 3) * 32;

    float c[2][4][4];
#pragma unroll
    for (int mf = 0; mf < 2; mf++)
#pragma unroll
        for (int nf = 0; nf < 4; nf++)
#pragma unroll
            for (int q = 0; q < 4; q++) c[mf][nf][q] = 0.f;

    const int crow = tid >> 2;
    const int cu   = tid & 3;
    const int arow = (lane & 7) + ((lane >> 3) & 1) * 8;
    const int acol = (lane >> 4) * 8;
    const int brow = (lane & 7) + (lane >> 4) * 8;
    const int bcol = ((lane >> 3) & 1) * 8;

#define E_ISSUE(CI) do {                                                        \
    const int k0_ = (CI) * 32;                                                  \
    const uint32_t st_ = sbase + ((CI) % 3) * E_SZ;                             \
    const uint32_t da = st_ + crow * 80 + cu * 16;                              \
    const size_t ga = (size_t)(m0 + crow) * 256 + k0_ + cu * 8;                 \
    const size_t gb = (size_t)(n0 + crow) * 256 + k0_ + cu * 8;                 \
    CP_ASYNC16(da,         Ah + ga);                                            \
    CP_ASYNC16(da + E_AL,  Al + ga);                                            \
    CP_ASYNC16(st_ + E_BH + crow * 80 + cu * 16,        Bh + gb);               \
    CP_ASYNC16(st_ + E_BH + (crow + 64) * 80 + cu * 16, Bh + gb + 64 * 256);    \
    CP_ASYNC16(st_ + E_BL + crow * 80 + cu * 16,        Bl + gb);               \
    CP_ASYNC16(st_ + E_BL + (crow + 64) * 80 + cu * 16, Bl + gb + 64 * 256);    \
    CP_COMMIT();                                                                \
} while (0)

    E_ISSUE(0);
    E_ISSUE(1);

#pragma unroll 1
    for (int ci = 0; ci < 8; ci++) {
        if (ci < 7) CP_WAIT1(); else CP_WAIT0();
        __syncthreads();
        if (ci < 6) E_ISSUE(ci + 2);

        const uint32_t st = sbase + (ci % 3) * E_SZ;
#pragma unroll
        for (int kk = 0; kk < 32; kk += 16) {
            uint32_t ah[2][4], al[2][4];
#pragma unroll
            for (int mf = 0; mf < 2; mf++) {
                uint32_t addr = st + (wm + mf * 16 + arow) * 80 + (kk + acol) * 2;
                LDSM4(ah[mf], addr);
                LDSM4(al[mf], addr + E_AL);
            }
            uint32_t bhf[4][2], blf[4][2];
#pragma unroll
            for (int np = 0; np < 2; np++) {
                uint32_t addr = st + E_BH
                              + (wn + np * 16 + brow) * 80 + (kk + bcol) * 2;
                uint32_t r[4];
                LDSM4(r, addr);
                bhf[2 * np][0] = r[0]; bhf[2 * np][1] = r[1];
                bhf[2 * np + 1][0] = r[2]; bhf[2 * np + 1][1] = r[3];
                LDSM4(r, addr + (E_BL - E_BH));
                blf[2 * np][0] = r[0]; blf[2 * np][1] = r[1];
                blf[2 * np + 1][0] = r[2]; blf[2 * np + 1][1] = r[3];
            }
#pragma unroll
            for (int mf = 0; mf < 2; mf++)
#pragma unroll
                for (int nf = 0; nf < 4; nf++) {
                    mma_bf16(c[mf][nf], ah[mf], bhf[nf]);
                    mma_bf16(c[mf][nf], ah[mf], blf[nf]);
                    mma_bf16(c[mf][nf], al[mf], bhf[nf]);
                }
        }
    }
#undef E_ISSUE

    const int erow = lane >> 2;
    const int ecol = (lane & 3) * 2;
#pragma unroll
    for (int mf = 0; mf < 2; mf++) {
        const int gr0 = m0 + wm + mf * 16 + erow;
#pragma unroll
        for (int nf = 0; nf < 4; nf++) {
            const int gc = n0 + wn + nf * 8 + ecol;
            float2 bb = *(const float2*)&bias[gc];
            float v00 = fmaxf(c[mf][nf][0] + bb.x, 0.f);
            float v01 = fmaxf(c[mf][nf][1] + bb.y, 0.f);
            float v10 = fmaxf(c[mf][nf][2] + bb.x, 0.f);
            float v11 = fmaxf(c[mf][nf][3] + bb.y, 0.f);
            const size_t i0 = (size_t)gr0 * 256 + gc;
            const size_t i1 = (size_t)(gr0 + 8) * 256 + gc;
            if (MODE == 0) {
                uint32_t h0, l0, h1, l1;
                split2(v00, v01, h0, l0);
                split2(v10, v11, h1, l1);
                *(uint32_t*)(oh + i0) = h0;
                *(uint32_t*)(oh + i1) = h1;
                *(uint32_t*)(ol + i0) = l0;
                *(uint32_t*)(ol + i1) = l1;
            } else {
                __half p0[2] = {__float2half(v00), __float2half(v01)};
                __half p1[2] = {__float2half(v10), __float2half(v11)};
                *(uint32_t*)(ef + i0) = *(uint32_t*)p0;
                *(uint32_t*)(ef + i1) = *(uint32_t*)p1;
            }
        }
    }
}

// ---------------------------------------------------------------------------
// TAIL kernel: inner (blockIdx.x < 31) + leaf (blockIdx.x >= 31).
// Pure fp16 single x single: 1 MMA per k-step. grid (63, 128), block 256.
// ---------------------------------------------------------------------------
// inner: phase A stage = A(5120) W1(5120); phase B stage = Ww(12288)
#define IA_SZ  10240
#define IB_SZ  12288
#define IN_HF  36864       // H fp16 single, 64 x 144
#define IN_RED 46080       // 3 x 2 x 64 floats
#define IN_WBS 47616
#define IN_WBTS 47872
// leaf: stage = A(10240) B(10240), 3 stages
#define L_B   10240
#define L_STG 20480
#define L_SC  (3 * L_STG)
#define TAIL_SMEM (L_SC + 1024)

__global__ __launch_bounds__(256, 2) void tail_kernel(
    const __half* __restrict__ ef,
    // inner params
    const __half* __restrict__ w1h, const __half* __restrict__ wwh,
    const float* __restrict__ x, const float* __restrict__ b1,
    const float* __restrict__ bw, const float* __restrict__ Wb,
    const float* __restrict__ bb, const float* __restrict__ Wbt,
    const float* __restrict__ bbt, float* __restrict__ pR,
    // leaf params
    const __half* __restrict__ Lwh,
    const float* __restrict__ lbias, const float* __restrict__ w2,
    float* __restrict__ yleaf)
{
    extern __shared__ char smem[];
    const uint32_t sb = smem_u32(smem);
    const int tid = threadIdx.x, lane = tid & 31, w = tid >> 5;

    const int arow = (lane & 7) + ((lane >> 3) & 1) * 8;
    const int acol = (lane >> 4) * 8;
    const int brow = (lane & 7) + (lane >> 4) * 8;
    const int bcol = ((lane >> 3) & 1) * 8;
    const int crow = tid >> 2, cu = tid & 3;

    if (blockIdx.x < N_INNER) {
        // ================= INNER path =================
        const int n = blockIdx.x, m0 = blockIdx.y * 64;

        float* sWb  = (float*)(smem + IN_WBS);
        float* sWbt = (float*)(smem + IN_WBTS);
        if (tid < HDIM)          sWb[tid] = Wb[n * HDIM + tid];
        else if (tid < 2 * HDIM) sWbt[tid - HDIM] = Wbt[n * HDIM + tid - HDIM];

        const __half* w1p = w1h + (size_t)n * 64 * 256;
        const __half* wwp = wwh + (size_t)n * 256 * 64;

#define IN_ISSUE(CI) do {                                           \
    const int k0_ = (CI) * 32;                                      \
    const uint32_t st_ = sb + ((CI) % 3) * IA_SZ;                   \
    const uint32_t d = st_ + crow * 80 + cu * 16;                   \
    const size_t ga = (size_t)(m0 + crow) * 256 + k0_ + cu * 8;     \
    const size_t gw = (size_t)crow * 256 + k0_ + cu * 8;            \
    CP_ASYNC16(d,        ef + ga);                                  \
    CP_ASYNC16(d + 5120, w1p + gw);                                 \
    CP_COMMIT();                                                    \
} while (0)

        // ---- Phase A: H = relu(emb @ W1^T + b1) ----
        const int wmA = (w >> 1) * 16, wnA = (w & 1) * 32;
        float accA[4][4];
#pragma unroll
        for (int i = 0; i < 4; i++)
#pragma unroll
            for (int q = 0; q < 4; q++) accA[i][q] = 0.f;

        IN_ISSUE(0);
        IN_ISSUE(1);

#pragma unroll 1
        for (int ci = 0; ci < 8; ci++) {
            if (ci < 7) CP_WAIT1(); else CP_WAIT0();
            __syncthreads();
            if (ci < 6) IN_ISSUE(ci + 2);

            const uint32_t st = sb + (ci % 3) * IA_SZ;
#pragma unroll
            for (int kk = 0; kk < 32; kk += 16) {
                uint32_t a[4];
                LDSM4(a, st + (wmA + arow) * 80 + (kk + acol) * 2);
                uint32_t bf[4][2];
#pragma unroll
                for (int g = 0; g < 2; g++) {
                    uint32_t r[4];
                    LDSM4(r, st + 5120 + (wnA + g * 16 + brow) * 80 + (kk + bcol) * 2);
                    bf[2 * g][0] = r[0]; bf[2 * g][1] = r[1];
                    bf[2 * g + 1][0] = r[2]; bf[2 * g + 1][1] = r[3];
                }
#pragma unroll
                for (int nf = 0; nf < 4; nf++)
                    mma_f16(accA[nf], a, bf[nf]);
            }
        }
#undef IN_ISSUE

        // Phase A epilogue: relu(+b1) -> H fp16 single in smem
        {
            const int r0 = wmA + (lane >> 2);
#pragma unroll
            for (int nf = 0; nf < 4; nf++) {
                const int col = wnA + nf * 8 + (lane & 3) * 2;
                const float bb0 = (col < HDIM)     ? b1[n * HDIM + col]     : 0.f;
                const float bb1 = (col + 1 < HDIM) ? b1[n * HDIM + col + 1] : 0.f;
                __half p0[2] = {__float2half(fmaxf(accA[nf][0] + bb0, 0.f)),
                                __float2half(fmaxf(accA[nf][1] + bb1, 0.f))};
                __half p1[2] = {__float2half(fmaxf(accA[nf][2] + bb0, 0.f)),
                                __float2half(fmaxf(accA[nf][3] + bb1, 0.f))};
                *(uint32_t*)(smem + IN_HF + r0 * 144 + col * 2) = *(uint32_t*)p0;
                *(uint32_t*)(smem + IN_HF + (r0 + 8) * 144 + col * 2) = *(uint32_t*)p1;
            }
        }
        __syncthreads();

        // ---- Phase B: z = H @ Ww^T + bw ----
#define IN_ISSUE_B(KK) do {                                         \
    const uint32_t st_ = sb + ((KK) % 3) * IB_SZ;                   \
    const uint32_t d = st_ + tid * 48;                              \
    const size_t g = (size_t)tid * 64 + (KK) * 16;                  \
    CP_ASYNC16(d,      wwp + g);                                    \
    CP_ASYNC16(d + 16, wwp + g + 8);                                \
    CP_COMMIT();                                                    \
} while (0)

        const int wmB = (w >> 1) * 16, wnB = (w & 1) * 128;
        float z[16][4];
#pragma unroll
        for (int nf = 0; nf < 16; nf++)
#pragma unroll
            for (int q = 0; q < 4; q++) z[nf][q] = 0.f;

        IN_ISSUE_B(0);
        IN_ISSUE_B(1);

#pragma unroll 1
        for (int kk = 0; kk < 4; kk++) {
            if (kk < 3) CP_WAIT1(); else CP_WAIT0();
            __syncthreads();
            if (kk < 2) IN_ISSUE_B(kk + 2);

            const uint32_t st = sb + (kk % 3) * IB_SZ;
            uint32_t a[4];
            LDSM4(a, sb + IN_HF + (wmB + arow) * 144 + (kk * 16 + acol) * 2);
#pragma unroll
            for (int g = 0; g < 8; g++) {
                uint32_t r[4];
                LDSM4(r, st + (wnB + g * 16 + brow) * 48 + bcol * 2);
                uint32_t b0[2] = {r[0], r[1]}, b1f[2] = {r[2], r[3]};
                mma_f16(z[2 * g],     a, b0);
                mma_f16(z[2 * g + 1], a, b1f);
            }
        }
#undef IN_ISSUE_B

        // ---- Phase B epilogue ----
        float* redmax = (float*)(smem + IN_RED);
        float* redse  = redmax + 128;
        float* redsx  = redse + 128;

        const int r0 = wmB + (lane >> 2), r1 = r0 + 8;
        float mx0 = -1e30f, mx1 = -1e30f;
#pragma unroll
        for (int nf = 0; nf < 16; nf++) {
            const int col = wnB + nf * 8 + (lane & 3) * 2;
            float2 bwv = *(const float2*)&bw[n * 256 + col];
            z[nf][0] += bwv.x; z[nf][1] += bwv.y;
            z[nf][2] += bwv.x; z[nf][3] += bwv.y;
            mx0 = fmaxf(mx0, fmaxf(z[nf][0], z[nf][1]));
            mx1 = fmaxf(mx1, fmaxf(z[nf][2], z[nf][3]));
        }
        mx0 = fmaxf(mx0, __shfl_xor_sync(0xffffffffu, mx0, 1));
        mx0 = fmaxf(mx0, __shfl_xor_sync(0xffffffffu, mx0, 2));
        mx1 = fmaxf(mx1, __shfl_xor_sync(0xffffffffu, mx1, 1));
        mx1 = fmaxf(mx1, __shfl_xor_sync(0xffffffffu, mx1, 2));
        if ((lane & 3) == 0) {
            redmax[(w & 1) * 64 + r0] = mx0;
            redmax[(w & 1) * 64 + r1] = mx1;
        }
        __syncthreads();
        mx0 = fmaxf(redmax[r0], redmax[64 + r0]);
        mx1 = fmaxf(redmax[r1], redmax[64 + r1]);

        float se0 = 0.f, sx0 = 0.f, se1 = 0.f, sx1 = 0.f;
        const float* x0 = x + (size_t)(m0 + r0) * 256;
        const float* x1 = x + (size_t)(m0 + r1) * 256;
#pragma unroll
        for (int nf = 0; nf < 16; nf++) {
            const int col = wnB + nf * 8 + (lane & 3) * 2;
            float2 xv0 = *(const float2*)&x0[col];
            float2 xv1 = *(const float2*)&x1[col];
            float e;
            e = __expf(z[nf][0] - mx0); se0 += e; sx0 = fmaf(e, xv0.x, sx0);
            e = __expf(z[nf][1] - mx0); se0 += e; sx0 = fmaf(e, xv0.y, sx0);
            e = __expf(z[nf][2] - mx1); se1 += e; sx1 = fmaf(e, xv1.x, sx1);
            e = __expf(z[nf][3] - mx1); se1 += e; sx1 = fmaf(e, xv1.y, sx1);
        }
#pragma unroll
        for (int off = 1; off <= 2; off <<= 1) {
            se0 += __shfl_xor_sync(0xffffffffu, se0, off);
            sx0 += __shfl_xor_sync(0xffffffffu, sx0, off);
            se1 += __shfl_xor_sync(0xffffffffu, se1, off);
            sx1 += __shfl_xor_sync(0xffffffffu, sx1, off);
        }
        if ((lane & 3) == 0) {
            redse[(w & 1) * 64 + r0] = se0; redse[(w & 1) * 64 + r1] = se1;
            redsx[(w & 1) * 64 + r0] = sx0; redsx[(w & 1) * 64 + r1] = sx1;
        }
        __syncthreads();

        if ((w & 1) == 0) {
            float pb0 = 0.f, pbt0 = 0.f, pb1 = 0.f, pbt1 = 0.f;
            for (int j = (lane & 3); j < HDIM; j += 4) {
                float h0 = __half2float(*(const __half*)(smem + IN_HF + r0 * 144 + j * 2));
                float h1 = __half2float(*(const __half*)(smem + IN_HF + r1 * 144 + j * 2));
                pb0  = fmaf(h0, sWb[j],  pb0);
                pbt0 = fmaf(h0, sWbt[j], pbt0);
                pb1  = fmaf(h1, sWb[j],  pb1);
                pbt1 = fmaf(h1, sWbt[j], pbt1);
            }
#pragma unroll
            for (int off = 1; off <= 2; off <<= 1) {
                pb0  += __shfl_xor_sync(0xffffffffu, pb0, off);
                pbt0 += __shfl_xor_sync(0xffffffffu, pbt0, off);
                pb1  += __shfl_xor_sync(0xffffffffu, pb1, off);
                pbt1 += __shfl_xor_sync(0xffffffffu, pbt1, off);
            }
            if ((lane & 3) == 0) {
                const float bbn = bb[n], bbtn = bbt[n];
                float seA = redse[r0] + redse[64 + r0];
                float sxA = redsx[r0] + redsx[64 + r0];
                float val = (pbt0 + bbtn) * (sxA / seA + pb0 + bbn);
                pR[(size_t)n * BATCH + m0 + r0] = 1.f / (1.f + __expf(-val));
                seA = redse[r1] + redse[64 + r1];
                sxA = redsx[r1] + redsx[64 + r1];
                val = (pbt1 + bbtn) * (sxA / seA + pb1 + bbn);
                pR[(size_t)n * BATCH + m0 + r1] = 1.f / (1.f + __expf(-val));
            }
        }
    } else {
        // ================= LEAF path =================
        const int mat = blockIdx.x - N_INNER;
        const int m0 = (blockIdx.y >> 1) * 128;
        const int n0 = (blockIdx.y & 1) * 128;
        const int wm = (w >> 1) * 32;
        const int wn = (w & 1) * 64;

        const __half* bp = Lwh + (size_t)mat * 65536;

        float* s_bias = (float*)(smem + L_SC);
        float* s_w2   = (float*)(smem + L_SC + 512);
        if (tid < 128) {
            s_bias[tid] = lbias[(size_t)mat * 256 + n0 + tid];
            s_w2[tid]   = w2[(size_t)mat * 256 + n0 + tid];
        }

        float c[2][8][4];
#pragma unroll
        for (int mf = 0; mf < 2; mf++)
#pragma unroll
            for (int nf = 0; nf < 8; nf++)
#pragma unroll
                for (int q = 0; q < 4; q++) c[mf][nf][q] = 0.f;

#define L_ISSUE(CI) do {                                                        \
    const int k0_ = (CI) * 32;                                                  \
    const uint32_t st_ = sb + ((CI) % 3) * L_STG;                               \
    const uint32_t d0 = st_ + crow * 80 + cu * 16;                              \
    const uint32_t d1 = st_ + (crow + 64) * 80 + cu * 16;                       \
    const size_t ga = (size_t)(m0 + crow) * 256 + k0_ + cu * 8;                 \
    const size_t gb = (size_t)(n0 + crow) * 256 + k0_ + cu * 8;                 \
    CP_ASYNC16(d0,        ef + ga);                                             \
    CP_ASYNC16(d1,        ef + ga + 64 * 256);                                  \
    CP_ASYNC16(d0 + L_B,  bp + gb);                                             \
    CP_ASYNC16(d1 + L_B,  bp + gb + 64 * 256);                                  \
    CP_COMMIT();                                                                \
} while (0)

        L_ISSUE(0);
        L_ISSUE(1);

#pragma unroll 1
        for (int ci = 0; ci < 8; ci++) {
            if (ci < 7) CP_WAIT1(); else CP_WAIT0();
            __syncthreads();
            if (ci < 6) L_ISSUE(ci + 2);

            const uint32_t st = sb + (ci % 3) * L_STG;
#pragma unroll
            for (int kk = 0; kk < 32; kk += 16) {
                uint32_t a[2][4];
#pragma unroll
                for (int mf = 0; mf < 2; mf++)
                    LDSM4(a[mf], st + (wm + mf * 16 + arow) * 80 + (kk + acol) * 2);
                uint32_t bf[8][2];
#pragma unroll
                for (int np = 0; np < 4; np++) {
                    uint32_t r[4];
                    LDSM4(r, st + L_B + (wn + np * 16 + brow) * 80 + (kk + bcol) * 2);
                    bf[2 * np][0] = r[0]; bf[2 * np][1] = r[1];
                    bf[2 * np + 1][0] = r[2]; bf[2 * np + 1][1] = r[3];
                }
#pragma unroll
                for (int mf = 0; mf < 2; mf++)
#pragma unroll
                    for (int nf = 0; nf < 8; nf++)
                        mma_f16(c[mf][nf], a[mf], bf[nf]);
            }
        }
#undef L_ISSUE

        const int erow = lane >> 2;
        const int ecol = (lane & 3) * 2;
        float part[2][2] = {{0.f, 0.f}, {0.f, 0.f}};
#pragma unroll
        for (int mf = 0; mf < 2; mf++)
#pragma unroll
            for (int nf = 0; nf < 8; nf++) {
                const int lc = wn + nf * 8 + ecol;
                const float b0s = s_bias[lc], b1s = s_bias[lc + 1];
                const float w0 = s_w2[lc], w1 = s_w2[lc + 1];
                part[mf][0] = fmaf(fmaxf(c[mf][nf][0] + b0s, 0.f), w0, part[mf][0]);
                part[mf][0] = fmaf(fmaxf(c[mf][nf][1] + b1s, 0.f), w1, part[mf][0]);
                part[mf][1] = fmaf(fmaxf(c[mf][nf][2] + b0s, 0.f), w0, part[mf][1]);
                part[mf][1] = fmaf(fmaxf(c[mf][nf][3] + b1s, 0.f), w1, part[mf][1]);
            }
#pragma unroll
        for (int mf = 0; mf < 2; mf++)
#pragma unroll
            for (int h = 0; h < 2; h++) {
                part[mf][h] += __shfl_xor_sync(0xffffffffu, part[mf][h], 1);
                part[mf][h] += __shfl_xor_sync(0xffffffffu, part[mf][h], 2);
            }
        if ((lane & 3) == 0) {
#pragma unroll
            for (int mf = 0; mf < 2; mf++)
#pragma unroll
                for (int h = 0; h < 2; h++) {
                    const int row = m0 + wm + mf * 16 + h * 8 + erow;
                    atomicAdd(&yleaf[(size_t)mat * BATCH + row], part[mf][h]);
                }
        }
    }
}

// ---------------------------------------------------------------------------
// Combine
// ---------------------------------------------------------------------------
__global__ __launch_bounds__(256) void combine_kernel(
    const float* __restrict__ pR, const float* __restrict__ yl,
    const float* __restrict__ b2, float* __restrict__ out)
{
    const int b = blockIdx.x * 256 + threadIdx.x;
    float p[N_INNER];
#pragma unroll
    for (int i = 0; i < N_INNER; i++) p[i] = pR[(size_t)i * BATCH + b];

    float prob[N_LEAF];
    prob[0] = 1.f;
#pragma unroll
    for (int lev = 0; lev < 5; lev++) {
        const int cnt = 1 << lev;
        const int off = cnt - 1;
#pragma unroll
        for (int i = N_LEAF - 1; i >= 0; i--) {
            if (i < cnt) {
                float pr   = p[off + i];
                float base = prob[i];
                prob[2 * i]     = base * (1.f - pr);
                prob[2 * i + 1] = base * pr;
            }
        }
    }
    float acc = 0.f;
#pragma unroll
    for (int l = 0; l < N_LEAF; l++)
        acc = fmaf(prob[l], yl[(size_t)l * BATCH + b] + b2[l], acc);
    out[b] = acc;
}

// ---------------------------------------------------------------------------
extern "C" void kernel_launch(void* const* d_in, const int* in_sizes, int n_in,
                              void* d_out, int out_size)
{
    const float* x       = (const float*)d_in[0];
    const float* enc_W   = (const float*)d_in[1];
    const float* enc_b   = (const float*)d_in[2];
    const float* in_W1   = (const float*)d_in[3];
    const float* in_b1   = (const float*)d_in[4];
    const float* in_Ww   = (const float*)d_in[5];
    const float* in_bw   = (const float*)d_in[6];
    const float* in_Wb   = (const float*)d_in[7];
    const float* in_bb   = (const float*)d_in[8];
    const float* in_Wbt  = (const float*)d_in[9];
    const float* in_bbt  = (const float*)d_in[10];
    const float* lf_W1   = (const float*)d_in[11];
    const float* lf_b1   = (const float*)d_in[12];
    const float* lf_W2   = (const float*)d_in[13];
    const float* lf_b2   = (const float*)d_in[14];
    float* out = (float*)d_out;

    float *pR, *yl;
    __nv_bfloat16 *xh, *xl, *e0h, *e0l, *e1h, *e1l, *wth, *wtl;
    __half *ef, *lwh, *w1h, *wwh;
    cudaGetSymbolAddress((void**)&pR,  g_pR);
    cudaGetSymbolAddress((void**)&yl,  g_yleaf);
    cudaGetSymbolAddress((void**)&xh,  g_xh);
    cudaGetSymbolAddress((void**)&xl,  g_xl);
    cudaGetSymbolAddress((void**)&e0h, g_e0h);
    cudaGetSymbolAddress((void**)&e0l, g_e0l);
    cudaGetSymbolAddress((void**)&e1h, g_e1h);
    cudaGetSymbolAddress((void**)&e1l, g_e1l);
    cudaGetSymbolAddress((void**)&wth, g_wth);
    cudaGetSymbolAddress((void**)&wtl, g_wtl);
    cudaGetSymbolAddress((void**)&ef,  g_ef);
    cudaGetSymbolAddress((void**)&lwh, g_lwh);
    cudaGetSymbolAddress((void**)&w1h, g_w1h);
    cudaGetSymbolAddress((void**)&wwh, g_wwh);

    cudaFuncSetAttribute(enc_kernel<0>, cudaFuncAttributeMaxDynamicSharedMemorySize, ENC_SMEM);
    cudaFuncSetAttribute(enc_kernel<1>, cudaFuncAttributeMaxDynamicSharedMemorySize, ENC_SMEM);
    cudaFuncSetAttribute(tail_kernel,   cudaFuncAttributeMaxDynamicSharedMemorySize, TAIL_SMEM);

    // 1) all prep in one launch
    prep_all_kernel<<<PR_WTL, 256>>>(x, xh, xl, in_W1, w1h,
                                     in_Ww, wwh, yl,
                                     enc_W, wth, wtl, lf_W1, lwh);

    // 2-5) encoder (L1-L3 bf16 hi/lo; L4 emits fp16 single)
    enc_kernel<0><<<dim3(128, 2), 256, ENC_SMEM>>>(xh, xl, wth, wtl,
        enc_b, e0h, e0l, nullptr);
    enc_kernel<0><<<dim3(128, 2), 256, ENC_SMEM>>>(e0h, e0l, wth + 65536, wtl + 65536,
        enc_b + 256, e1h, e1l, nullptr);
    enc_kernel<0><<<dim3(128, 2), 256, ENC_SMEM>>>(e1h, e1l, wth + 2 * 65536, wtl + 2 * 65536,
        enc_b + 512, e0h, e0l, nullptr);
    enc_kernel<1><<<dim3(128, 2), 256, ENC_SMEM>>>(e0h, e0l, wth + 3 * 65536, wtl + 3 * 65536,
        enc_b + 768, nullptr, nullptr, ef);

    // 6) merged inner + leaf (fp16 single x single, 1 MMA/k-step)
    tail_kernel<<<dim3(63, 128), 256, TAIL_SMEM>>>(
        ef,
        w1h, wwh, x, in_b1, in_bw, in_Wb, in_bb, in_Wbt, in_bbt, pR,
        lwh, lf_b1, lf_W2, yl);

    // 7) combine
    combine_kernel<<<BATCH / 256, 256>>>(pR, yl, lf_b2, out);
}

// round 13
// speedup vs baseline: 4.0600x; 1.0513x over previous
#include <cuda_runtime.h>
#include <cuda_bf16.h>
#include <cuda_fp16.h>
#include <cstdint>
#include <math.h>

#define BATCH 8192
#define EDIM  256
#define HDIM  50
#define N_INNER 31
#define N_LEAF  32

// ---------------------------------------------------------------------------
// Device scratch
// ---------------------------------------------------------------------------
__device__ float g_pR[N_INNER * BATCH];
__device__ float g_yleaf[N_LEAF * BATCH];

__device__ __half g_xh[BATCH * EDIM];      // x fp16 hi
__device__ __half g_xl[BATCH * EDIM];      // x fp16 lo
__device__ __half g_e0h[BATCH * EDIM];
__device__ __half g_e0l[BATCH * EDIM];
__device__ __half g_e1h[BATCH * EDIM];
__device__ __half g_e1l[BATCH * EDIM];
__device__ __half g_ef[BATCH * EDIM];      // final emb, fp16 single
// encoder weights transposed [4][N=256][K=256] fp16 single
__device__ __half g_wte[4 * 65536];
// leaf weights transposed [32][N=256][K=256] fp16 single
__device__ __half g_lwh[N_LEAF * 65536];
// inner W1 transposed [31][64][256] fp16 single, Ww transposed [31][256][64]
__device__ __half g_w1h[N_INNER * 64 * 256];
__device__ __half g_wwh[N_INNER * 256 * 64];

// ---------------------------------------------------------------------------
// Helpers
// ---------------------------------------------------------------------------
__device__ __forceinline__ uint32_t smem_u32(const void* p) {
    uint32_t a;
    asm("{ .reg .u64 t; cvta.to.shared.u64 t, %1; cvt.u32.u64 %0, t; }" : "=r"(a) : "l"(p));
    return a;
}
#define CP_ASYNC16(dst, src) \
    asm volatile("cp.async.cg.shared.global [%0], [%1], 16;" :: "r"(dst), "l"(src) : "memory")
#define CP_COMMIT() asm volatile("cp.async.commit_group;" ::: "memory")
#define CP_WAIT1()  asm volatile("cp.async.wait_group 1;" ::: "memory")
#define CP_WAIT0()  asm volatile("cp.async.wait_group 0;" ::: "memory")

#define LDSM4(r, addr) \
    asm volatile("ldmatrix.sync.aligned.m8n8.x4.shared.b16 {%0,%1,%2,%3}, [%4];" \
        : "=r"((r)[0]), "=r"((r)[1]), "=r"((r)[2]), "=r"((r)[3]) : "r"(addr))

__device__ __forceinline__ void mma_f16(float* c, const uint32_t* a, const uint32_t* b) {
    asm volatile(
        "mma.sync.aligned.m16n8k16.row.col.f32.f16.f16.f32 "
        "{%0,%1,%2,%3}, {%4,%5,%6,%7}, {%8,%9}, {%0,%1,%2,%3};"
        : "+f"(c[0]), "+f"(c[1]), "+f"(c[2]), "+f"(c[3])
        : "r"(a[0]), "r"(a[1]), "r"(a[2]), "r"(a[3]), "r"(b[0]), "r"(b[1]));
}

// fp16 hi/lo split of a pair of floats
__device__ __forceinline__ void split2h(float a, float b, uint32_t& hi, uint32_t& lo) {
    __half h0 = __float2half(a), h1 = __float2half(b);
    __half l0 = __float2half(a - __half2float(h0));
    __half l1 = __float2half(b - __half2float(h1));
    __half hh[2] = {h0, h1}, ll[2] = {l0, l1};
    hi = *(uint32_t*)hh;
    lo = *(uint32_t*)ll;
}

// ---------------------------------------------------------------------------
// Mega-prep. Regions by blockIdx.x:
// x split fp16 | W1 fp16 | Ww fp16 | zero yl |
// enc-W transpose fp16 (4x64) | leaf-W transpose fp16 (32x64)
// ---------------------------------------------------------------------------
#define PR_X   2048
#define PR_W1  (PR_X + 1984)
#define PR_WW  (PR_W1 + 1984)
#define PR_Z   (PR_WW + 256)
#define PR_WTE (PR_Z + 4 * 64)
#define PR_WTL (PR_WTE + 32 * 64)

__global__ __launch_bounds__(256) void prep_all_kernel(
    const float* __restrict__ x, __half* __restrict__ xh,
    __half* __restrict__ xl,
    const float* __restrict__ W1, __half* __restrict__ w1h,
    const float* __restrict__ Ww, __half* __restrict__ wwh,
    float* __restrict__ yl,
    const float* __restrict__ encW, __half* __restrict__ wte,
    const float* __restrict__ lfW, __half* __restrict__ lwh)
{
    const int bid = blockIdx.x;
    const int t = threadIdx.x;
    if (bid < PR_X) {
        int i = bid * 256 + t;
        float4 v = ((const float4*)x)[i];
        float f[4] = {v.x, v.y, v.z, v.w};
        __half h[4], l[4];
#pragma unroll
        for (int j = 0; j < 4; j++) {
            h[j] = __float2half(f[j]);
            l[j] = __float2half(f[j] - __half2float(h[j]));
        }
        *(uint2*)(xh + 4 * (size_t)i) = *(uint2*)h;
        *(uint2*)(xl + 4 * (size_t)i) = *(uint2*)l;
    } else if (bid < PR_W1) {
        int idx = (bid - PR_X) * 256 + t;
        int k = idx & 255, j = (idx >> 8) & 63, n = idx >> 14;
        float v = (j < HDIM) ? W1[((size_t)n * 256 + k) * HDIM + j] : 0.f;
        w1h[idx] = __float2half(v);
    } else if (bid < PR_WW) {
        int idx = (bid - PR_W1) * 256 + t;
        int j = idx & 63, d = (idx >> 6) & 255, n = idx >> 14;
        float v = (j < HDIM) ? Ww[((size_t)n * HDIM + j) * 256 + d] : 0.f;
        wwh[idx] = __float2half(v);
    } else if (bid < PR_Z) {
        int i = (bid - PR_WW) * 256 + t;
        ((float4*)yl)[i] = make_float4(0.f, 0.f, 0.f, 0.f);
    } else if (bid < PR_WTE) {
        __shared__ float tt[32][33];
        const int rel = bid - PR_Z;
        const int mat = rel >> 6;
        const int sub = rel & 63;
        const int nb = (sub & 7) * 32, kb = (sub >> 3) * 32;
        const int tx = t & 31, ty = t >> 5;
        const float* src = encW + (size_t)mat * 65536;
#pragma unroll
        for (int i = 0; i < 4; i++)
            tt[ty + 8 * i][tx] = src[(size_t)(kb + ty + 8 * i) * 256 + nb + tx];
        __syncthreads();
#pragma unroll
        for (int i = 0; i < 4; i++) {
            float v = tt[tx][ty + 8 * i];
            size_t idx = (size_t)mat * 65536 + (size_t)(nb + ty + 8 * i) * 256 + kb + tx;
            wte[idx] = __float2half(v);
        }
    } else {
        __shared__ float tt[32][33];
        const int rel = bid - PR_WTE;
        const int mat = rel >> 6;
        const int sub = rel & 63;
        const int nb = (sub & 7) * 32, kb = (sub >> 3) * 32;
        const int tx = t & 31, ty = t >> 5;
        const float* src = lfW + (size_t)mat * 65536;
#pragma unroll
        for (int i = 0; i < 4; i++)
            tt[ty + 8 * i][tx] = src[(size_t)(kb + ty + 8 * i) * 256 + nb + tx];
        __syncthreads();
#pragma unroll
        for (int i = 0; i < 4; i++) {
            float v = tt[tx][ty + 8 * i];
            size_t idx = (size_t)mat * 65536 + (size_t)(nb + ty + 8 * i) * 256 + kb + tx;
            lwh[idx] = __float2half(v);
        }
    }
}

// ---------------------------------------------------------------------------
// Encoder GEMM: fp16, activation hi/lo x weight single (2 MMA/k-step).
// M=64, N=128, 3-stage, 256 thr.
// MODE 0: emit fp16 hi/lo.  MODE 1 (L4): emit fp16 single.
// ---------------------------------------------------------------------------
#define E_AL 5120
#define E_B  10240
#define E_SZ 20480
#define ENC_SMEM (3 * E_SZ)

template <int MODE>
__global__ __launch_bounds__(256, 2) void enc_kernel(
    const __half* __restrict__ Ah, const __half* __restrict__ Al,
    const __half* __restrict__ B,
    const float* __restrict__ bias,
    __half* __restrict__ oh, __half* __restrict__ ol,
    __half* __restrict__ ef)
{
    extern __shared__ char smem[];
    const uint32_t sbase = smem_u32(smem);
    const int tid = threadIdx.x;
    const int lane = tid & 31, warp = tid >> 5;
    const int m0 = blockIdx.x * 64;
    const int n0 = blockIdx.y * 128;
    const int wm = (warp >> 2) * 32;
    const int wn = (warp & 3) * 32;

    float c[2][4][4];
#pragma unroll
    for (int mf = 0; mf < 2; mf++)
#pragma unroll
        for (int nf = 0; nf < 4; nf++)
#pragma unroll
            for (int q = 0; q < 4; q++) c[mf][nf][q] = 0.f;

    const int crow = tid >> 2;
    const int cu   = tid & 3;
    const int arow = (lane & 7) + ((lane >> 3) & 1) * 8;
    const int acol = (lane >> 4) * 8;
    const int brow = (lane & 7) + (lane >> 4) * 8;
    const int bcol = ((lane >> 3) & 1) * 8;

#define E_ISSUE(CI) do {                                                        \
    const int k0_ = (CI) * 32;                                                  \
    const uint32_t st_ = sbase + ((CI) % 3) * E_SZ;                             \
    const uint32_t da = st_ + crow * 80 + cu * 16;                              \
    const size_t ga = (size_t)(m0 + crow) * 256 + k0_ + cu * 8;                 \
    const size_t gb = (size_t)(n0 + crow) * 256 + k0_ + cu * 8;                 \
    CP_ASYNC16(da,         Ah + ga);                                            \
    CP_ASYNC16(da + E_AL,  Al + ga);                                            \
    CP_ASYNC16(st_ + E_B + crow * 80 + cu * 16,        B + gb);                 \
    CP_ASYNC16(st_ + E_B + (crow + 64) * 80 + cu * 16, B + gb + 64 * 256);      \
    CP_COMMIT();                                                                \
} while (0)

    E_ISSUE(0);
    E_ISSUE(1);

#pragma unroll 1
    for (int ci = 0; ci < 8; ci++) {
        if (ci < 7) CP_WAIT1(); else CP_WAIT0();
        __syncthreads();
        if (ci < 6) E_ISSUE(ci + 2);

        const uint32_t st = sbase + (ci % 3) * E_SZ;
#pragma unroll
        for (int kk = 0; kk < 32; kk += 16) {
            uint32_t ah[2][4], al[2][4];
#pragma unroll
            for (int mf = 0; mf < 2; mf++) {
                uint32_t addr = st + (wm + mf * 16 + arow) * 80 + (kk + acol) * 2;
                LDSM4(ah[mf], addr);
                LDSM4(al[mf], addr + E_AL);
            }
            uint32_t bf[4][2];
#pragma unroll
            for (int np = 0; np < 2; np++) {
                uint32_t r[4];
                LDSM4(r, st + E_B + (wn + np * 16 + brow) * 80 + (kk + bcol) * 2);
                bf[2 * np][0] = r[0]; bf[2 * np][1] = r[1];
                bf[2 * np + 1][0] = r[2]; bf[2 * np + 1][1] = r[3];
            }
#pragma unroll
            for (int mf = 0; mf < 2; mf++)
#pragma unroll
                for (int nf = 0; nf < 4; nf++) {
                    mma_f16(c[mf][nf], ah[mf], bf[nf]);
                    mma_f16(c[mf][nf], al[mf], bf[nf]);
                }
        }
    }
#undef E_ISSUE

    const int erow = lane >> 2;
    const int ecol = (lane & 3) * 2;
#pragma unroll
    for (int mf = 0; mf < 2; mf++) {
        const int gr0 = m0 + wm + mf * 16 + erow;
#pragma unroll
        for (int nf = 0; nf < 4; nf++) {
            const int gc = n0 + wn + nf * 8 + ecol;
            float2 bb = *(const float2*)&bias[gc];
            float v00 = fmaxf(c[mf][nf][0] + bb.x, 0.f);
            float v01 = fmaxf(c[mf][nf][1] + bb.y, 0.f);
            float v10 = fmaxf(c[mf][nf][2] + bb.x, 0.f);
            float v11 = fmaxf(c[mf][nf][3] + bb.y, 0.f);
            const size_t i0 = (size_t)gr0 * 256 + gc;
            const size_t i1 = (size_t)(gr0 + 8) * 256 + gc;
            if (MODE == 0) {
                uint32_t h0, l0, h1, l1;
                split2h(v00, v01, h0, l0);
                split2h(v10, v11, h1, l1);
                *(uint32_t*)(oh + i0) = h0;
                *(uint32_t*)(oh + i1) = h1;
                *(uint32_t*)(ol + i0) = l0;
                *(uint32_t*)(ol + i1) = l1;
            } else {
                __half p0[2] = {__float2half(v00), __float2half(v01)};
                __half p1[2] = {__float2half(v10), __float2half(v11)};
                *(uint32_t*)(ef + i0) = *(uint32_t*)p0;
                *(uint32_t*)(ef + i1) = *(uint32_t*)p1;
            }
        }
    }
}

// ---------------------------------------------------------------------------
// TAIL kernel: inner (blockIdx.x < 31) + leaf (blockIdx.x >= 31).
// Pure fp16 single x single: 1 MMA per k-step. grid (63, 128), block 256.
// (Unchanged from round 12 — proven.)
// ---------------------------------------------------------------------------
#define IA_SZ  10240
#define IB_SZ  12288
#define IN_HF  36864
#define IN_RED 46080
#define IN_WBS 47616
#define IN_WBTS 47872
#define L_B   10240
#define L_STG 20480
#define L_SC  (3 * L_STG)
#define TAIL_SMEM (L_SC + 1024)

__global__ __launch_bounds__(256, 2) void tail_kernel(
    const __half* __restrict__ ef,
    const __half* __restrict__ w1h, const __half* __restrict__ wwh,
    const float* __restrict__ x, const float* __restrict__ b1,
    const float* __restrict__ bw, const float* __restrict__ Wb,
    const float* __restrict__ bb, const float* __restrict__ Wbt,
    const float* __restrict__ bbt, float* __restrict__ pR,
    const __half* __restrict__ Lwh,
    const float* __restrict__ lbias, const float* __restrict__ w2,
    float* __restrict__ yleaf)
{
    extern __shared__ char smem[];
    const uint32_t sb = smem_u32(smem);
    const int tid = threadIdx.x, lane = tid & 31, w = tid >> 5;

    const int arow = (lane & 7) + ((lane >> 3) & 1) * 8;
    const int acol = (lane >> 4) * 8;
    const int brow = (lane & 7) + (lane >> 4) * 8;
    const int bcol = ((lane >> 3) & 1) * 8;
    const int crow = tid >> 2, cu = tid & 3;

    if (blockIdx.x < N_INNER) {
        // ================= INNER path =================
        const int n = blockIdx.x, m0 = blockIdx.y * 64;

        float* sWb  = (float*)(smem + IN_WBS);
        float* sWbt = (float*)(smem + IN_WBTS);
        if (tid < HDIM)          sWb[tid] = Wb[n * HDIM + tid];
        else if (tid < 2 * HDIM) sWbt[tid - HDIM] = Wbt[n * HDIM + tid - HDIM];

        const __half* w1p = w1h + (size_t)n * 64 * 256;
        const __half* wwp = wwh + (size_t)n * 256 * 64;

#define IN_ISSUE(CI) do {                                           \
    const int k0_ = (CI) * 32;                                      \
    const uint32_t st_ = sb + ((CI) % 3) * IA_SZ;                   \
    const uint32_t d = st_ + crow * 80 + cu * 16;                   \
    const size_t ga = (size_t)(m0 + crow) * 256 + k0_ + cu * 8;     \
    const size_t gw = (size_t)crow * 256 + k0_ + cu * 8;            \
    CP_ASYNC16(d,        ef + ga);                                  \
    CP_ASYNC16(d + 5120, w1p + gw);                                 \
    CP_COMMIT();                                                    \
} while (0)

        const int wmA = (w >> 1) * 16, wnA = (w & 1) * 32;
        float accA[4][4];
#pragma unroll
        for (int i = 0; i < 4; i++)
#pragma unroll
            for (int q = 0; q < 4; q++) accA[i][q] = 0.f;

        IN_ISSUE(0);
        IN_ISSUE(1);

#pragma unroll 1
        for (int ci = 0; ci < 8; ci++) {
            if (ci < 7) CP_WAIT1(); else CP_WAIT0();
            __syncthreads();
            if (ci < 6) IN_ISSUE(ci + 2);

            const uint32_t st = sb + (ci % 3) * IA_SZ;
#pragma unroll
            for (int kk = 0; kk < 32; kk += 16) {
                uint32_t a[4];
                LDSM4(a, st + (wmA + arow) * 80 + (kk + acol) * 2);
                uint32_t bf[4][2];
#pragma unroll
                for (int g = 0; g < 2; g++) {
                    uint32_t r[4];
                    LDSM4(r, st + 5120 + (wnA + g * 16 + brow) * 80 + (kk + bcol) * 2);
                    bf[2 * g][0] = r[0]; bf[2 * g][1] = r[1];
                    bf[2 * g + 1][0] = r[2]; bf[2 * g + 1][1] = r[3];
                }
#pragma unroll
                for (int nf = 0; nf < 4; nf++)
                    mma_f16(accA[nf], a, bf[nf]);
            }
        }
#undef IN_ISSUE

        {
            const int r0 = wmA + (lane >> 2);
#pragma unroll
            for (int nf = 0; nf < 4; nf++) {
                const int col = wnA + nf * 8 + (lane & 3) * 2;
                const float bb0 = (col < HDIM)     ? b1[n * HDIM + col]     : 0.f;
                const float bb1 = (col + 1 < HDIM) ? b1[n * HDIM + col + 1] : 0.f;
                __half p0[2] = {__float2half(fmaxf(accA[nf][0] + bb0, 0.f)),
                                __float2half(fmaxf(accA[nf][1] + bb1, 0.f))};
                __half p1[2] = {__float2half(fmaxf(accA[nf][2] + bb0, 0.f)),
                                __float2half(fmaxf(accA[nf][3] + bb1, 0.f))};
                *(uint32_t*)(smem + IN_HF + r0 * 144 + col * 2) = *(uint32_t*)p0;
                *(uint32_t*)(smem + IN_HF + (r0 + 8) * 144 + col * 2) = *(uint32_t*)p1;
            }
        }
        __syncthreads();

#define IN_ISSUE_B(KK) do {                                         \
    const uint32_t st_ = sb + ((KK) % 3) * IB_SZ;                   \
    const uint32_t d = st_ + tid * 48;                              \
    const size_t g = (size_t)tid * 64 + (KK) * 16;                  \
    CP_ASYNC16(d,      wwp + g);                                    \
    CP_ASYNC16(d + 16, wwp + g + 8);                                \
    CP_COMMIT();                                                    \
} while (0)

        const int wmB = (w >> 1) * 16, wnB = (w & 1) * 128;
        float z[16][4];
#pragma unroll
        for (int nf = 0; nf < 16; nf++)
#pragma unroll
            for (int q = 0; q < 4; q++) z[nf][q] = 0.f;

        IN_ISSUE_B(0);
        IN_ISSUE_B(1);

#pragma unroll 1
        for (int kk = 0; kk < 4; kk++) {
            if (kk < 3) CP_WAIT1(); else CP_WAIT0();
            __syncthreads();
            if (kk < 2) IN_ISSUE_B(kk + 2);

            const uint32_t st = sb + (kk % 3) * IB_SZ;
            uint32_t a[4];
            LDSM4(a, sb + IN_HF + (wmB + arow) * 144 + (kk * 16 + acol) * 2);
#pragma unroll
            for (int g = 0; g < 8; g++) {
                uint32_t r[4];
                LDSM4(r, st + (wnB + g * 16 + brow) * 48 + bcol * 2);
                uint32_t b0[2] = {r[0], r[1]}, b1f[2] = {r[2], r[3]};
                mma_f16(z[2 * g],     a, b0);
                mma_f16(z[2 * g + 1], a, b1f);
            }
        }
#undef IN_ISSUE_B

        float* redmax = (float*)(smem + IN_RED);
        float* redse  = redmax + 128;
        float* redsx  = redse + 128;

        const int r0 = wmB + (lane >> 2), r1 = r0 + 8;
        float mx0 = -1e30f, mx1 = -1e30f;
#pragma unroll
        for (int nf = 0; nf < 16; nf++) {
            const int col = wnB + nf * 8 + (lane & 3) * 2;
            float2 bwv = *(const float2*)&bw[n * 256 + col];
            z[nf][0] += bwv.x; z[nf][1] += bwv.y;
            z[nf][2] += bwv.x; z[nf][3] += bwv.y;
            mx0 = fmaxf(mx0, fmaxf(z[nf][0], z[nf][1]));
            mx1 = fmaxf(mx1, fmaxf(z[nf][2], z[nf][3]));
        }
        mx0 = fmaxf(mx0, __shfl_xor_sync(0xffffffffu, mx0, 1));
        mx0 = fmaxf(mx0, __shfl_xor_sync(0xffffffffu, mx0, 2));
        mx1 = fmaxf(mx1, __shfl_xor_sync(0xffffffffu, mx1, 1));
        mx1 = fmaxf(mx1, __shfl_xor_sync(0xffffffffu, mx1, 2));
        if ((lane & 3) == 0) {
            redmax[(w & 1) * 64 + r0] = mx0;
            redmax[(w & 1) * 64 + r1] = mx1;
        }
        __syncthreads();
        mx0 = fmaxf(redmax[r0], redmax[64 + r0]);
        mx1 = fmaxf(redmax[r1], redmax[64 + r1]);

        float se0 = 0.f, sx0 = 0.f, se1 = 0.f, sx1 = 0.f;
        const float* x0 = x + (size_t)(m0 + r0) * 256;
        const float* x1 = x + (size_t)(m0 + r1) * 256;
#pragma unroll
        for (int nf = 0; nf < 16; nf++) {
            const int col = wnB + nf * 8 + (lane & 3) * 2;
            float2 xv0 = *(const float2*)&x0[col];
            float2 xv1 = *(const float2*)&x1[col];
            float e;
            e = __expf(z[nf][0] - mx0); se0 += e; sx0 = fmaf(e, xv0.x, sx0);
            e = __expf(z[nf][1] - mx0); se0 += e; sx0 = fmaf(e, xv0.y, sx0);
            e = __expf(z[nf][2] - mx1); se1 += e; sx1 = fmaf(e, xv1.x, sx1);
            e = __expf(z[nf][3] - mx1); se1 += e; sx1 = fmaf(e, xv1.y, sx1);
        }
#pragma unroll
        for (int off = 1; off <= 2; off <<= 1) {
            se0 += __shfl_xor_sync(0xffffffffu, se0, off);
            sx0 += __shfl_xor_sync(0xffffffffu, sx0, off);
            se1 += __shfl_xor_sync(0xffffffffu, se1, off);
            sx1 += __shfl_xor_sync(0xffffffffu, sx1, off);
        }
        if ((lane & 3) == 0) {
            redse[(w & 1) * 64 + r0] = se0; redse[(w & 1) * 64 + r1] = se1;
            redsx[(w & 1) * 64 + r0] = sx0; redsx[(w & 1) * 64 + r1] = sx1;
        }
        __syncthreads();

        if ((w & 1) == 0) {
            float pb0 = 0.f, pbt0 = 0.f, pb1 = 0.f, pbt1 = 0.f;
            for (int j = (lane & 3); j < HDIM; j += 4) {
                float h0 = __half2float(*(const __half*)(smem + IN_HF + r0 * 144 + j * 2));
                float h1 = __half2float(*(const __half*)(smem + IN_HF + r1 * 144 + j * 2));
                pb0  = fmaf(h0, sWb[j],  pb0);
                pbt0 = fmaf(h0, sWbt[j], pbt0);
                pb1  = fmaf(h1, sWb[j],  pb1);
                pbt1 = fmaf(h1, sWbt[j], pbt1);
            }
#pragma unroll
            for (int off = 1; off <= 2; off <<= 1) {
                pb0  += __shfl_xor_sync(0xffffffffu, pb0, off);
                pbt0 += __shfl_xor_sync(0xffffffffu, pbt0, off);
                pb1  += __shfl_xor_sync(0xffffffffu, pb1, off);
                pbt1 += __shfl_xor_sync(0xffffffffu, pbt1, off);
            }
            if ((lane & 3) == 0) {
                const float bbn = bb[n], bbtn = bbt[n];
                float seA = redse[r0] + redse[64 + r0];
                float sxA = redsx[r0] + redsx[64 + r0];
                float val = (pbt0 + bbtn) * (sxA / seA + pb0 + bbn);
                pR[(size_t)n * BATCH + m0 + r0] = 1.f / (1.f + __expf(-val));
                seA = redse[r1] + redse[64 + r1];
                sxA = redsx[r1] + redsx[64 + r1];
                val = (pbt1 + bbtn) * (sxA / seA + pb1 + bbn);
                pR[(size_t)n * BATCH + m0 + r1] = 1.f / (1.f + __expf(-val));
            }
        }
    } else {
        // ================= LEAF path =================
        const int mat = blockIdx.x - N_INNER;
        const int m0 = (blockIdx.y >> 1) * 128;
        const int n0 = (blockIdx.y & 1) * 128;
        const int wm = (w >> 1) * 32;
        const int wn = (w & 1) * 64;

        const __half* bp = Lwh + (size_t)mat * 65536;

        float* s_bias = (float*)(smem + L_SC);
        float* s_w2   = (float*)(smem + L_SC + 512);
        if (tid < 128) {
            s_bias[tid] = lbias[(size_t)mat * 256 + n0 + tid];
            s_w2[tid]   = w2[(size_t)mat * 256 + n0 + tid];
        }

        float c[2][8][4];
#pragma unroll
        for (int mf = 0; mf < 2; mf++)
#pragma unroll
            for (int nf = 0; nf < 8; nf++)
#pragma unroll
                for (int q = 0; q < 4; q++) c[mf][nf][q] = 0.f;

#define L_ISSUE(CI) do {                                                        \
    const int k0_ = (CI) * 32;                                                  \
    const uint32_t st_ = sb + ((CI) % 3) * L_STG;                               \
    const uint32_t d0 = st_ + crow * 80 + cu * 16;                              \
    const uint32_t d1 = st_ + (crow + 64) * 80 + cu * 16;                       \
    const size_t ga = (size_t)(m0 + crow) * 256 + k0_ + cu * 8;                 \
    const size_t gb = (size_t)(n0 + crow) * 256 + k0_ + cu * 8;                 \
    CP_ASYNC16(d0,        ef + ga);                                             \
    CP_ASYNC16(d1,        ef + ga + 64 * 256);                                  \
    CP_ASYNC16(d0 + L_B,  bp + gb);                                             \
    CP_ASYNC16(d1 + L_B,  bp + gb + 64 * 256);                                  \
    CP_COMMIT();                                                                \
} while (0)

        L_ISSUE(0);
        L_ISSUE(1);

#pragma unroll 1
        for (int ci = 0; ci < 8; ci++) {
            if (ci < 7) CP_WAIT1(); else CP_WAIT0();
            __syncthreads();
            if (ci < 6) L_ISSUE(ci + 2);

            const uint32_t st = sb + (ci % 3) * L_STG;
#pragma unroll
            for (int kk = 0; kk < 32; kk += 16) {
                uint32_t a[2][4];
#pragma unroll
                for (int mf = 0; mf < 2; mf++)
                    LDSM4(a[mf], st + (wm + mf * 16 + arow) * 80 + (kk + acol) * 2);
                uint32_t bf[8][2];
#pragma unroll
                for (int np = 0; np < 4; np++) {
                    uint32_t r[4];
                    LDSM4(r, st + L_B + (wn + np * 16 + brow) * 80 + (kk + bcol) * 2);
                    bf[2 * np][0] = r[0]; bf[2 * np][1] = r[1];
                    bf[2 * np + 1][0] = r[2]; bf[2 * np + 1][1] = r[3];
                }
#pragma unroll
                for (int mf = 0; mf < 2; mf++)
#pragma unroll
                    for (int nf = 0; nf < 8; nf++)
                        mma_f16(c[mf][nf], a[mf], bf[nf]);
            }
        }
#undef L_ISSUE

        const int erow = lane >> 2;
        const int ecol = (lane & 3) * 2;
        float part[2][2] = {{0.f, 0.f}, {0.f, 0.f}};
#pragma unroll
        for (int mf = 0; mf < 2; mf++)
#pragma unroll
            for (int nf = 0; nf < 8; nf++) {
                const int lc = wn + nf * 8 + ecol;
                const float b0s = s_bias[lc], b1s = s_bias[lc + 1];
                const float w0 = s_w2[lc], w1 = s_w2[lc + 1];
                part[mf][0] = fmaf(fmaxf(c[mf][nf][0] + b0s, 0.f), w0, part[mf][0]);
                part[mf][0] = fmaf(fmaxf(c[mf][nf][1] + b1s, 0.f), w1, part[mf][0]);
                part[mf][1] = fmaf(fmaxf(c[mf][nf][2] + b0s, 0.f), w0, part[mf][1]);
                part[mf][1] = fmaf(fmaxf(c[mf][nf][3] + b1s, 0.f), w1, part[mf][1]);
            }
#pragma unroll
        for (int mf = 0; mf < 2; mf++)
#pragma unroll
            for (int h = 0; h < 2; h++) {
                part[mf][h] += __shfl_xor_sync(0xffffffffu, part[mf][h], 1);
                part[mf][h] += __shfl_xor_sync(0xffffffffu, part[mf][h], 2);
            }
        if ((lane & 3) == 0) {
#pragma unroll
            for (int mf = 0; mf < 2; mf++)
#pragma unroll
                for (int h = 0; h < 2; h++) {
                    const int row = m0 + wm + mf * 16 + h * 8 + erow;
                    atomicAdd(&yleaf[(size_t)mat * BATCH + row], part[mf][h]);
                }
        }
    }
}

// ---------------------------------------------------------------------------
// Combine
// ---------------------------------------------------------------------------
__global__ __launch_bounds__(256) void combine_kernel(
    const float* __restrict__ pR, const float* __restrict__ yl,
    const float* __restrict__ b2, float* __restrict__ out)
{
    const int b = blockIdx.x * 256 + threadIdx.x;
    float p[N_INNER];
#pragma unroll
    for (int i = 0; i < N_INNER; i++) p[i] = pR[(size_t)i * BATCH + b];

    float prob[N_LEAF];
    prob[0] = 1.f;
#pragma unroll
    for (int lev = 0; lev < 5; lev++) {
        const int cnt = 1 << lev;
        const int off = cnt - 1;
#pragma unroll
        for (int i = N_LEAF - 1; i >= 0; i--) {
            if (i < cnt) {
                float pr   = p[off + i];
                float base = prob[i];
                prob[2 * i]     = base * (1.f - pr);
                prob[2 * i + 1] = base * pr;
            }
        }
    }
    float acc = 0.f;
#pragma unroll
    for (int l = 0; l < N_LEAF; l++)
        acc = fmaf(prob[l], yl[(size_t)l * BATCH + b] + b2[l], acc);
    out[b] = acc;
}

// ---------------------------------------------------------------------------
extern "C" void kernel_launch(void* const* d_in, const int* in_sizes, int n_in,
                              void* d_out, int out_size)
{
    const float* x       = (const float*)d_in[0];
    const float* enc_W   = (const float*)d_in[1];
    const float* enc_b   = (const float*)d_in[2];
    const float* in_W1   = (const float*)d_in[3];
    const float* in_b1   = (const float*)d_in[4];
    const float* in_Ww   = (const float*)d_in[5];
    const float* in_bw   = (const float*)d_in[6];
    const float* in_Wb   = (const float*)d_in[7];
    const float* in_bb   = (const float*)d_in[8];
    const float* in_Wbt  = (const float*)d_in[9];
    const float* in_bbt  = (const float*)d_in[10];
    const float* lf_W1   = (const float*)d_in[11];
    const float* lf_b1   = (const float*)d_in[12];
    const float* lf_W2   = (const float*)d_in[13];
    const float* lf_b2   = (const float*)d_in[14];
    float* out = (float*)d_out;

    float *pR, *yl;
    __half *xh, *xl, *e0h, *e0l, *e1h, *e1l, *wte;
    __half *ef, *lwh, *w1h, *wwh;
    cudaGetSymbolAddress((void**)&pR,  g_pR);
    cudaGetSymbolAddress((void**)&yl,  g_yleaf);
    cudaGetSymbolAddress((void**)&xh,  g_xh);
    cudaGetSymbolAddress((void**)&xl,  g_xl);
    cudaGetSymbolAddress((void**)&e0h, g_e0h);
    cudaGetSymbolAddress((void**)&e0l, g_e0l);
    cudaGetSymbolAddress((void**)&e1h, g_e1h);
    cudaGetSymbolAddress((void**)&e1l, g_e1l);
    cudaGetSymbolAddress((void**)&wte, g_wte);
    cudaGetSymbolAddress((void**)&ef,  g_ef);
    cudaGetSymbolAddress((void**)&lwh, g_lwh);
    cudaGetSymbolAddress((void**)&w1h, g_w1h);
    cudaGetSymbolAddress((void**)&wwh, g_wwh);

    cudaFuncSetAttribute(enc_kernel<0>, cudaFuncAttributeMaxDynamicSharedMemorySize, ENC_SMEM);
    cudaFuncSetAttribute(enc_kernel<1>, cudaFuncAttributeMaxDynamicSharedMemorySize, ENC_SMEM);
    cudaFuncSetAttribute(tail_kernel,   cudaFuncAttributeMaxDynamicSharedMemorySize, TAIL_SMEM);

    // 1) all prep in one launch
    prep_all_kernel<<<PR_WTL, 256>>>(x, xh, xl, in_W1, w1h,
                                     in_Ww, wwh, yl,
                                     enc_W, wte, lf_W1, lwh);

    // 2-5) encoder (fp16 act-hi/lo x weight-single, 2 MMA/k-step)
    enc_kernel<0><<<dim3(128, 2), 256, ENC_SMEM>>>(xh, xl, wte,
        enc_b, e0h, e0l, nullptr);
    enc_kernel<0><<<dim3(128, 2), 256, ENC_SMEM>>>(e0h, e0l, wte + 65536,
        enc_b + 256, e1h, e1l, nullptr);
    enc_kernel<0><<<dim3(128, 2), 256, ENC_SMEM>>>(e1h, e1l, wte + 2 * 65536,
        enc_b + 512, e0h, e0l, nullptr);
    enc_kernel<1><<<dim3(128, 2), 256, ENC_SMEM>>>(e0h, e0l, wte + 3 * 65536,
        enc_b + 768, nullptr, nullptr, ef);

    // 6) merged inner + leaf (fp16 single x single)
    tail_kernel<<<dim3(63, 128), 256, TAIL_SMEM>>>(
        ef,
        w1h, wwh, x, in_b1, in_bw, in_Wb, in_bb, in_Wbt, in_bbt, pR,
        lwh, lf_b1, lf_W2, yl);

    // 7) combine
    combine_kernel<<<BATCH / 256, 256>>>(pR, yl, lf_b2, out);
}

// round 14
// speedup vs baseline: 4.0650x; 1.0012x over previous
#include <cuda_runtime.h>
#include <cuda_bf16.h>
#include <cuda_fp16.h>
#include <cstdint>
#include <math.h>

#define BATCH 8192
#define EDIM  256
#define HDIM  50
#define N_INNER 31
#define N_LEAF  32

// ---------------------------------------------------------------------------
// Device scratch
// ---------------------------------------------------------------------------
__device__ float g_pR[N_INNER * BATCH];
__device__ float g_yleaf[N_LEAF * BATCH];

__device__ __half g_xh[BATCH * EDIM];      // x fp16 hi
__device__ __half g_xl[BATCH * EDIM];      // x fp16 lo
__device__ __half g_e0h[BATCH * EDIM];
__device__ __half g_e0l[BATCH * EDIM];
__device__ __half g_e1h[BATCH * EDIM];
__device__ __half g_e1l[BATCH * EDIM];
__device__ __half g_ef[BATCH * EDIM];      // final emb, fp16 single
// encoder weights transposed [4][N=256][K=256] fp16 single
__device__ __half g_wte[4 * 65536];
// leaf weights transposed [32][N=256][K=256] fp16 single
__device__ __half g_lwh[N_LEAF * 65536];
// inner W1 transposed [31][64][256] fp16 single, Ww transposed [31][256][64]
__device__ __half g_w1h[N_INNER * 64 * 256];
__device__ __half g_wwh[N_INNER * 256 * 64];

// ---------------------------------------------------------------------------
// Helpers
// ---------------------------------------------------------------------------
__device__ __forceinline__ uint32_t smem_u32(const void* p) {
    uint32_t a;
    asm("{ .reg .u64 t; cvta.to.shared.u64 t, %1; cvt.u32.u64 %0, t; }" : "=r"(a) : "l"(p));
    return a;
}
#define CP_ASYNC16(dst, src) \
    asm volatile("cp.async.cg.shared.global [%0], [%1], 16;" :: "r"(dst), "l"(src) : "memory")
#define CP_COMMIT() asm volatile("cp.async.commit_group;" ::: "memory")
#define CP_WAIT1()  asm volatile("cp.async.wait_group 1;" ::: "memory")
#define CP_WAIT0()  asm volatile("cp.async.wait_group 0;" ::: "memory")

#define LDSM4(r, addr) \
    asm volatile("ldmatrix.sync.aligned.m8n8.x4.shared.b16 {%0,%1,%2,%3}, [%4];" \
        : "=r"((r)[0]), "=r"((r)[1]), "=r"((r)[2]), "=r"((r)[3]) : "r"(addr))

__device__ __forceinline__ void mma_f16(float* c, const uint32_t* a, const uint32_t* b) {
    asm volatile(
        "mma.sync.aligned.m16n8k16.row.col.f32.f16.f16.f32 "
        "{%0,%1,%2,%3}, {%4,%5,%6,%7}, {%8,%9}, {%0,%1,%2,%3};"
        : "+f"(c[0]), "+f"(c[1]), "+f"(c[2]), "+f"(c[3])
        : "r"(a[0]), "r"(a[1]), "r"(a[2]), "r"(a[3]), "r"(b[0]), "r"(b[1]));
}

// fp16 hi/lo split of a pair of floats
__device__ __forceinline__ void split2h(float a, float b, uint32_t& hi, uint32_t& lo) {
    __half h0 = __float2half(a), h1 = __float2half(b);
    __half l0 = __float2half(a - __half2float(h0));
    __half l1 = __float2half(b - __half2float(h1));
    __half hh[2] = {h0, h1}, ll[2] = {l0, l1};
    hi = *(uint32_t*)hh;
    lo = *(uint32_t*)ll;
}

// ---------------------------------------------------------------------------
// Mega-prep. Regions by blockIdx.x:
// x split fp16 | W1 fp16 | Ww fp16 | zero yl |
// enc-W transpose fp16 (4x64) | leaf-W transpose fp16 (32x64)
// ---------------------------------------------------------------------------
#define PR_X   2048
#define PR_W1  (PR_X + 1984)
#define PR_WW  (PR_W1 + 1984)
#define PR_Z   (PR_WW + 256)
#define PR_WTE (PR_Z + 4 * 64)
#define PR_WTL (PR_WTE + 32 * 64)

__global__ __launch_bounds__(256) void prep_all_kernel(
    const float* __restrict__ x, __half* __restrict__ xh,
    __half* __restrict__ xl,
    const float* __restrict__ W1, __half* __restrict__ w1h,
    const float* __restrict__ Ww, __half* __restrict__ wwh,
    float* __restrict__ yl,
    const float* __restrict__ encW, __half* __restrict__ wte,
    const float* __restrict__ lfW, __half* __restrict__ lwh)
{
    const int bid = blockIdx.x;
    const int t = threadIdx.x;
    if (bid < PR_X) {
        int i = bid * 256 + t;
        float4 v = ((const float4*)x)[i];
        float f[4] = {v.x, v.y, v.z, v.w};
        __half h[4], l[4];
#pragma unroll
        for (int j = 0; j < 4; j++) {
            h[j] = __float2half(f[j]);
            l[j] = __float2half(f[j] - __half2float(h[j]));
        }
        *(uint2*)(xh + 4 * (size_t)i) = *(uint2*)h;
        *(uint2*)(xl + 4 * (size_t)i) = *(uint2*)l;
    } else if (bid < PR_W1) {
        int idx = (bid - PR_X) * 256 + t;
        int k = idx & 255, j = (idx >> 8) & 63, n = idx >> 14;
        float v = (j < HDIM) ? W1[((size_t)n * 256 + k) * HDIM + j] : 0.f;
        w1h[idx] = __float2half(v);
    } else if (bid < PR_WW) {
        int idx = (bid - PR_W1) * 256 + t;
        int j = idx & 63, d = (idx >> 6) & 255, n = idx >> 14;
        float v = (j < HDIM) ? Ww[((size_t)n * HDIM + j) * 256 + d] : 0.f;
        wwh[idx] = __float2half(v);
    } else if (bid < PR_Z) {
        int i = (bid - PR_WW) * 256 + t;
        ((float4*)yl)[i] = make_float4(0.f, 0.f, 0.f, 0.f);
    } else if (bid < PR_WTE) {
        __shared__ float tt[32][33];
        const int rel = bid - PR_Z;
        const int mat = rel >> 6;
        const int sub = rel & 63;
        const int nb = (sub & 7) * 32, kb = (sub >> 3) * 32;
        const int tx = t & 31, ty = t >> 5;
        const float* src = encW + (size_t)mat * 65536;
#pragma unroll
        for (int i = 0; i < 4; i++)
            tt[ty + 8 * i][tx] = src[(size_t)(kb + ty + 8 * i) * 256 + nb + tx];
        __syncthreads();
#pragma unroll
        for (int i = 0; i < 4; i++) {
            float v = tt[tx][ty + 8 * i];
            size_t idx = (size_t)mat * 65536 + (size_t)(nb + ty + 8 * i) * 256 + kb + tx;
            wte[idx] = __float2half(v);
        }
    } else {
        __shared__ float tt[32][33];
        const int rel = bid - PR_WTE;
        const int mat = rel >> 6;
        const int sub = rel & 63;
        const int nb = (sub & 7) * 32, kb = (sub >> 3) * 32;
        const int tx = t & 31, ty = t >> 5;
        const float* src = lfW + (size_t)mat * 65536;
#pragma unroll
        for (int i = 0; i < 4; i++)
            tt[ty + 8 * i][tx] = src[(size_t)(kb + ty + 8 * i) * 256 + nb + tx];
        __syncthreads();
#pragma unroll
        for (int i = 0; i < 4; i++) {
            float v = tt[tx][ty + 8 * i];
            size_t idx = (size_t)mat * 65536 + (size_t)(nb + ty + 8 * i) * 256 + kb + tx;
            lwh[idx] = __float2half(v);
        }
    }
}

// ---------------------------------------------------------------------------
// Encoder GEMM: fp16, activation hi/lo x weight single (2 MMA/k-step).
// M=64, N=128, 3-stage, 256 thr, 3 CTAs/SM (register-capped, 24 warps/SM).
// MODE 0: emit fp16 hi/lo.  MODE 1 (L4): emit fp16 single.
// ---------------------------------------------------------------------------
#define E_AL 5120
#define E_B  10240
#define E_SZ 20480
#define ENC_SMEM (3 * E_SZ)

template <int MODE>
__global__ __launch_bounds__(256, 3) void enc_kernel(
    const __half* __restrict__ Ah, const __half* __restrict__ Al,
    const __half* __restrict__ B,
    const float* __restrict__ bias,
    __half* __restrict__ oh, __half* __restrict__ ol,
    __half* __restrict__ ef)
{
    extern __shared__ char smem[];
    const uint32_t sbase = smem_u32(smem);
    const int tid = threadIdx.x;
    const int lane = tid & 31, warp = tid >> 5;
    const int m0 = blockIdx.x * 64;
    const int n0 = blockIdx.y * 128;
    const int wm = (warp >> 2) * 32;
    const int wn = (warp & 3) * 32;

    float c[2][4][4];
#pragma unroll
    for (int mf = 0; mf < 2; mf++)
#pragma unroll
        for (int nf = 0; nf < 4; nf++)
#pragma unroll
            for (int q = 0; q < 4; q++) c[mf][nf][q] = 0.f;

    const int crow = tid >> 2;
    const int cu   = tid & 3;
    const int arow = (lane & 7) + ((lane >> 3) & 1) * 8;
    const int acol = (lane >> 4) * 8;
    const int brow = (lane & 7) + (lane >> 4) * 8;
    const int bcol = ((lane >> 3) & 1) * 8;

#define E_ISSUE(CI) do {                                                        \
    const int k0_ = (CI) * 32;                                                  \
    const uint32_t st_ = sbase + ((CI) % 3) * E_SZ;                             \
    const uint32_t da = st_ + crow * 80 + cu * 16;                              \
    const size_t ga = (size_t)(m0 + crow) * 256 + k0_ + cu * 8;                 \
    const size_t gb = (size_t)(n0 + crow) * 256 + k0_ + cu * 8;                 \
    CP_ASYNC16(da,         Ah + ga);                                            \
    CP_ASYNC16(da + E_AL,  Al + ga);                                            \
    CP_ASYNC16(st_ + E_B + crow * 80 + cu * 16,        B + gb);                 \
    CP_ASYNC16(st_ + E_B + (crow + 64) * 80 + cu * 16, B + gb + 64 * 256);      \
    CP_COMMIT();                                                                \
} while (0)

    E_ISSUE(0);
    E_ISSUE(1);

#pragma unroll 1
    for (int ci = 0; ci < 8; ci++) {
        if (ci < 7) CP_WAIT1(); else CP_WAIT0();
        __syncthreads();
        if (ci < 6) E_ISSUE(ci + 2);

        const uint32_t st = sbase + (ci % 3) * E_SZ;
#pragma unroll
        for (int kk = 0; kk < 32; kk += 16) {
            uint32_t ah[2][4], al[2][4];
#pragma unroll
            for (int mf = 0; mf < 2; mf++) {
                uint32_t addr = st + (wm + mf * 16 + arow) * 80 + (kk + acol) * 2;
                LDSM4(ah[mf], addr);
                LDSM4(al[mf], addr + E_AL);
            }
            uint32_t bf[4][2];
#pragma unroll
            for (int np = 0; np < 2; np++) {
                uint32_t r[4];
                LDSM4(r, st + E_B + (wn + np * 16 + brow) * 80 + (kk + bcol) * 2);
                bf[2 * np][0] = r[0]; bf[2 * np][1] = r[1];
                bf[2 * np + 1][0] = r[2]; bf[2 * np + 1][1] = r[3];
            }
#pragma unroll
            for (int mf = 0; mf < 2; mf++)
#pragma unroll
                for (int nf = 0; nf < 4; nf++) {
                    mma_f16(c[mf][nf], ah[mf], bf[nf]);
                    mma_f16(c[mf][nf], al[mf], bf[nf]);
                }
        }
    }
#undef E_ISSUE

    const int erow = lane >> 2;
    const int ecol = (lane & 3) * 2;
#pragma unroll
    for (int mf = 0; mf < 2; mf++) {
        const int gr0 = m0 + wm + mf * 16 + erow;
#pragma unroll
        for (int nf = 0; nf < 4; nf++) {
            const int gc = n0 + wn + nf * 8 + ecol;
            float2 bb = *(const float2*)&bias[gc];
            float v00 = fmaxf(c[mf][nf][0] + bb.x, 0.f);
            float v01 = fmaxf(c[mf][nf][1] + bb.y, 0.f);
            float v10 = fmaxf(c[mf][nf][2] + bb.x, 0.f);
            float v11 = fmaxf(c[mf][nf][3] + bb.y, 0.f);
            const size_t i0 = (size_t)gr0 * 256 + gc;
            const size_t i1 = (size_t)(gr0 + 8) * 256 + gc;
            if (MODE == 0) {
                uint32_t h0, l0, h1, l1;
                split2h(v00, v01, h0, l0);
                split2h(v10, v11, h1, l1);
                *(uint32_t*)(oh + i0) = h0;
                *(uint32_t*)(oh + i1) = h1;
                *(uint32_t*)(ol + i0) = l0;
                *(uint32_t*)(ol + i1) = l1;
            } else {
                __half p0[2] = {__float2half(v00), __float2half(v01)};
                __half p1[2] = {__float2half(v10), __float2half(v11)};
                *(uint32_t*)(ef + i0) = *(uint32_t*)p0;
                *(uint32_t*)(ef + i1) = *(uint32_t*)p1;
            }
        }
    }
}

// ---------------------------------------------------------------------------
// TAIL kernel: inner (blockIdx.x < 31) + leaf (blockIdx.x >= 31).
// Pure fp16 single x single: 1 MMA per k-step. grid (63, 128), block 256.
// (Unchanged from round 12/13 — proven; register budget forbids occ=3 here.)
// ---------------------------------------------------------------------------
#define IA_SZ  10240
#define IB_SZ  12288
#define IN_HF  36864
#define IN_RED 46080
#define IN_WBS 47616
#define IN_WBTS 47872
#define L_B   10240
#define L_STG 20480
#define L_SC  (3 * L_STG)
#define TAIL_SMEM (L_SC + 1024)

__global__ __launch_bounds__(256, 2) void tail_kernel(
    const __half* __restrict__ ef,
    const __half* __restrict__ w1h, const __half* __restrict__ wwh,
    const float* __restrict__ x, const float* __restrict__ b1,
    const float* __restrict__ bw, const float* __restrict__ Wb,
    const float* __restrict__ bb, const float* __restrict__ Wbt,
    const float* __restrict__ bbt, float* __restrict__ pR,
    const __half* __restrict__ Lwh,
    const float* __restrict__ lbias, const float* __restrict__ w2,
    float* __restrict__ yleaf)
{
    extern __shared__ char smem[];
    const uint32_t sb = smem_u32(smem);
    const int tid = threadIdx.x, lane = tid & 31, w = tid >> 5;

    const int arow = (lane & 7) + ((lane >> 3) & 1) * 8;
    const int acol = (lane >> 4) * 8;
    const int brow = (lane & 7) + (lane >> 4) * 8;
    const int bcol = ((lane >> 3) & 1) * 8;
    const int crow = tid >> 2, cu = tid & 3;

    if (blockIdx.x < N_INNER) {
        // ================= INNER path =================
        const int n = blockIdx.x, m0 = blockIdx.y * 64;

        float* sWb  = (float*)(smem + IN_WBS);
        float* sWbt = (float*)(smem + IN_WBTS);
        if (tid < HDIM)          sWb[tid] = Wb[n * HDIM + tid];
        else if (tid < 2 * HDIM) sWbt[tid - HDIM] = Wbt[n * HDIM + tid - HDIM];

        const __half* w1p = w1h + (size_t)n * 64 * 256;
        const __half* wwp = wwh + (size_t)n * 256 * 64;

#define IN_ISSUE(CI) do {                                           \
    const int k0_ = (CI) * 32;                                      \
    const uint32_t st_ = sb + ((CI) % 3) * IA_SZ;                   \
    const uint32_t d = st_ + crow * 80 + cu * 16;                   \
    const size_t ga = (size_t)(m0 + crow) * 256 + k0_ + cu * 8;     \
    const size_t gw = (size_t)crow * 256 + k0_ + cu * 8;            \
    CP_ASYNC16(d,        ef + ga);                                  \
    CP_ASYNC16(d + 5120, w1p + gw);                                 \
    CP_COMMIT();                                                    \
} while (0)

        const int wmA = (w >> 1) * 16, wnA = (w & 1) * 32;
        float accA[4][4];
#pragma unroll
        for (int i = 0; i < 4; i++)
#pragma unroll
            for (int q = 0; q < 4; q++) accA[i][q] = 0.f;

        IN_ISSUE(0);
        IN_ISSUE(1);

#pragma unroll 1
        for (int ci = 0; ci < 8; ci++) {
            if (ci < 7) CP_WAIT1(); else CP_WAIT0();
            __syncthreads();
            if (ci < 6) IN_ISSUE(ci + 2);

            const uint32_t st = sb + (ci % 3) * IA_SZ;
#pragma unroll
            for (int kk = 0; kk < 32; kk += 16) {
                uint32_t a[4];
                LDSM4(a, st + (wmA + arow) * 80 + (kk + acol) * 2);
                uint32_t bf[4][2];
#pragma unroll
                for (int g = 0; g < 2; g++) {
                    uint32_t r[4];
                    LDSM4(r, st + 5120 + (wnA + g * 16 + brow) * 80 + (kk + bcol) * 2);
                    bf[2 * g][0] = r[0]; bf[2 * g][1] = r[1];
                    bf[2 * g + 1][0] = r[2]; bf[2 * g + 1][1] = r[3];
                }
#pragma unroll
                for (int nf = 0; nf < 4; nf++)
                    mma_f16(accA[nf], a, bf[nf]);
            }
        }
#undef IN_ISSUE

        {
            const int r0 = wmA + (lane >> 2);
#pragma unroll
            for (int nf = 0; nf < 4; nf++) {
                const int col = wnA + nf * 8 + (lane & 3) * 2;
                const float bb0 = (col < HDIM)     ? b1[n * HDIM + col]     : 0.f;
                const float bb1 = (col + 1 < HDIM) ? b1[n * HDIM + col + 1] : 0.f;
                __half p0[2] = {__float2half(fmaxf(accA[nf][0] + bb0, 0.f)),
                                __float2half(fmaxf(accA[nf][1] + bb1, 0.f))};
                __half p1[2] = {__float2half(fmaxf(accA[nf][2] + bb0, 0.f)),
                                __float2half(fmaxf(accA[nf][3] + bb1, 0.f))};
                *(uint32_t*)(smem + IN_HF + r0 * 144 + col * 2) = *(uint32_t*)p0;
                *(uint32_t*)(smem + IN_HF + (r0 + 8) * 144 + col * 2) = *(uint32_t*)p1;
            }
        }
        __syncthreads();

#define IN_ISSUE_B(KK) do {                                         \
    const uint32_t st_ = sb + ((KK) % 3) * IB_SZ;                   \
    const uint32_t d = st_ + tid * 48;                              \
    const size_t g = (size_t)tid * 64 + (KK) * 16;                  \
    CP_ASYNC16(d,      wwp + g);                                    \
    CP_ASYNC16(d + 16, wwp + g + 8);                                \
    CP_COMMIT();                                                    \
} while (0)

        const int wmB = (w >> 1) * 16, wnB = (w & 1) * 128;
        float z[16][4];
#pragma unroll
        for (int nf = 0; nf < 16; nf++)
#pragma unroll
            for (int q = 0; q < 4; q++) z[nf][q] = 0.f;

        IN_ISSUE_B(0);
        IN_ISSUE_B(1);

#pragma unroll 1
        for (int kk = 0; kk < 4; kk++) {
            if (kk < 3) CP_WAIT1(); else CP_WAIT0();
            __syncthreads();
            if (kk < 2) IN_ISSUE_B(kk + 2);

            const uint32_t st = sb + (kk % 3) * IB_SZ;
            uint32_t a[4];
            LDSM4(a, sb + IN_HF + (wmB + arow) * 144 + (kk * 16 + acol) * 2);
#pragma unroll
            for (int g = 0; g < 8; g++) {
                uint32_t r[4];
                LDSM4(r, st + (wnB + g * 16 + brow) * 48 + bcol * 2);
                uint32_t b0[2] = {r[0], r[1]}, b1f[2] = {r[2], r[3]};
                mma_f16(z[2 * g],     a, b0);
                mma_f16(z[2 * g + 1], a, b1f);
            }
        }
#undef IN_ISSUE_B

        float* redmax = (float*)(smem + IN_RED);
        float* redse  = redmax + 128;
        float* redsx  = redse + 128;

        const int r0 = wmB + (lane >> 2), r1 = r0 + 8;
        float mx0 = -1e30f, mx1 = -1e30f;
#pragma unroll
        for (int nf = 0; nf < 16; nf++) {
            const int col = wnB + nf * 8 + (lane & 3) * 2;
            float2 bwv = *(const float2*)&bw[n * 256 + col];
            z[nf][0] += bwv.x; z[nf][1] += bwv.y;
            z[nf][2] += bwv.x; z[nf][3] += bwv.y;
            mx0 = fmaxf(mx0, fmaxf(z[nf][0], z[nf][1]));
            mx1 = fmaxf(mx1, fmaxf(z[nf][2], z[nf][3]));
        }
        mx0 = fmaxf(mx0, __shfl_xor_sync(0xffffffffu, mx0, 1));
        mx0 = fmaxf(mx0, __shfl_xor_sync(0xffffffffu, mx0, 2));
        mx1 = fmaxf(mx1, __shfl_xor_sync(0xffffffffu, mx1, 1));
        mx1 = fmaxf(mx1, __shfl_xor_sync(0xffffffffu, mx1, 2));
        if ((lane & 3) == 0) {
            redmax[(w & 1) * 64 + r0] = mx0;
            redmax[(w & 1) * 64 + r1] = mx1;
        }
        __syncthreads();
        mx0 = fmaxf(redmax[r0], redmax[64 + r0]);
        mx1 = fmaxf(redmax[r1], redmax[64 + r1]);

        float se0 = 0.f, sx0 = 0.f, se1 = 0.f, sx1 = 0.f;
        const float* x0 = x + (size_t)(m0 + r0) * 256;
        const float* x1 = x + (size_t)(m0 + r1) * 256;
#pragma unroll
        for (int nf = 0; nf < 16; nf++) {
            const int col = wnB + nf * 8 + (lane & 3) * 2;
            float2 xv0 = *(const float2*)&x0[col];
            float2 xv1 = *(const float2*)&x1[col];
            float e;
            e = __expf(z[nf][0] - mx0); se0 += e; sx0 = fmaf(e, xv0.x, sx0);
            e = __expf(z[nf][1] - mx0); se0 += e; sx0 = fmaf(e, xv0.y, sx0);
            e = __expf(z[nf][2] - mx1); se1 += e; sx1 = fmaf(e, xv1.x, sx1);
            e = __expf(z[nf][3] - mx1); se1 += e; sx1 = fmaf(e, xv1.y, sx1);
        }
#pragma unroll
        for (int off = 1; off <= 2; off <<= 1) {
            se0 += __shfl_xor_sync(0xffffffffu, se0, off);
            sx0 += __shfl_xor_sync(0xffffffffu, sx0, off);
            se1 += __shfl_xor_sync(0xffffffffu, se1, off);
            sx1 += __shfl_xor_sync(0xffffffffu, sx1, off);
        }
        if ((lane & 3) == 0) {
            redse[(w & 1) * 64 + r0] = se0; redse[(w & 1) * 64 + r1] = se1;
            redsx[(w & 1) * 64 + r0] = sx0; redsx[(w & 1) * 64 + r1] = sx1;
        }
        __syncthreads();

        if ((w & 1) == 0) {
            float pb0 = 0.f, pbt0 = 0.f, pb1 = 0.f, pbt1 = 0.f;
            for (int j = (lane & 3); j < HDIM; j += 4) {
                float h0 = __half2float(*(const __half*)(smem + IN_HF + r0 * 144 + j * 2));
                float h1 = __half2float(*(const __half*)(smem + IN_HF + r1 * 144 + j * 2));
                pb0  = fmaf(h0, sWb[j],  pb0);
                pbt0 = fmaf(h0, sWbt[j], pbt0);
                pb1  = fmaf(h1, sWb[j],  pb1);
                pbt1 = fmaf(h1, sWbt[j], pbt1);
            }
#pragma unroll
            for (int off = 1; off <= 2; off <<= 1) {
                pb0  += __shfl_xor_sync(0xffffffffu, pb0, off);
                pbt0 += __shfl_xor_sync(0xffffffffu, pbt0, off);
                pb1  += __shfl_xor_sync(0xffffffffu, pb1, off);
                pbt1 += __shfl_xor_sync(0xffffffffu, pbt1, off);
            }
            if ((lane & 3) == 0) {
                const float bbn = bb[n], bbtn = bbt[n];
                float seA = redse[r0] + redse[64 + r0];
                float sxA = redsx[r0] + redsx[64 + r0];
                float val = (pbt0 + bbtn) * (sxA / seA + pb0 + bbn);
                pR[(size_t)n * BATCH + m0 + r0] = 1.f / (1.f + __expf(-val));
                seA = redse[r1] + redse[64 + r1];
                sxA = redsx[r1] + redsx[64 + r1];
                val = (pbt1 + bbtn) * (sxA / seA + pb1 + bbn);
                pR[(size_t)n * BATCH + m0 + r1] = 1.f / (1.f + __expf(-val));
            }
        }
    } else {
        // ================= LEAF path =================
        const int mat = blockIdx.x - N_INNER;
        const int m0 = (blockIdx.y >> 1) * 128;
        const int n0 = (blockIdx.y & 1) * 128;
        const int wm = (w >> 1) * 32;
        const int wn = (w & 1) * 64;

        const __half* bp = Lwh + (size_t)mat * 65536;

        float* s_bias = (float*)(smem + L_SC);
        float* s_w2   = (float*)(smem + L_SC + 512);
        if (tid < 128) {
            s_bias[tid] = lbias[(size_t)mat * 256 + n0 + tid];
            s_w2[tid]   = w2[(size_t)mat * 256 + n0 + tid];
        }

        float c[2][8][4];
#pragma unroll
        for (int mf = 0; mf < 2; mf++)
#pragma unroll
            for (int nf = 0; nf < 8; nf++)
#pragma unroll
                for (int q = 0; q < 4; q++) c[mf][nf][q] = 0.f;

#define L_ISSUE(CI) do {                                                        \
    const int k0_ = (CI) * 32;                                                  \
    const uint32_t st_ = sb + ((CI) % 3) * L_STG;                               \
    const uint32_t d0 = st_ + crow * 80 + cu * 16;                              \
    const uint32_t d1 = st_ + (crow + 64) * 80 + cu * 16;                       \
    const size_t ga = (size_t)(m0 + crow) * 256 + k0_ + cu * 8;                 \
    const size_t gb = (size_t)(n0 + crow) * 256 + k0_ + cu * 8;                 \
    CP_ASYNC16(d0,        ef + ga);                                             \
    CP_ASYNC16(d1,        ef + ga + 64 * 256);                                  \
    CP_ASYNC16(d0 + L_B,  bp + gb);                                             \
    CP_ASYNC16(d1 + L_B,  bp + gb + 64 * 256);                                  \
    CP_COMMIT();                                                                \
} while (0)

        L_ISSUE(0);
        L_ISSUE(1);

#pragma unroll 1
        for (int ci = 0; ci < 8; ci++) {
            if (ci < 7) CP_WAIT1(); else CP_WAIT0();
            __syncthreads();
            if (ci < 6) L_ISSUE(ci + 2);

            const uint32_t st = sb + (ci % 3) * L_STG;
#pragma unroll
            for (int kk = 0; kk < 32; kk += 16) {
                uint32_t a[2][4];
#pragma unroll
                for (int mf = 0; mf < 2; mf++)
                    LDSM4(a[mf], st + (wm + mf * 16 + arow) * 80 + (kk + acol) * 2);
                uint32_t bf[8][2];
#pragma unroll
                for (int np = 0; np < 4; np++) {
                    uint32_t r[4];
                    LDSM4(r, st + L_B + (wn + np * 16 + brow) * 80 + (kk + bcol) * 2);
                    bf[2 * np][0] = r[0]; bf[2 * np][1] = r[1];
                    bf[2 * np + 1][0] = r[2]; bf[2 * np + 1][1] = r[3];
                }
#pragma unroll
                for (int mf = 0; mf < 2; mf++)
#pragma unroll
                    for (int nf = 0; nf < 8; nf++)
                        mma_f16(c[mf][nf], a[mf], bf[nf]);
            }
        }
#undef L_ISSUE

        const int erow = lane >> 2;
        const int ecol = (lane & 3) * 2;
        float part[2][2] = {{0.f, 0.f}, {0.f, 0.f}};
#pragma unroll
        for (int mf = 0; mf < 2; mf++)
#pragma unroll
            for (int nf = 0; nf < 8; nf++) {
                const int lc = wn + nf * 8 + ecol;
                const float b0s = s_bias[lc], b1s = s_bias[lc + 1];
                const float w0 = s_w2[lc], w1 = s_w2[lc + 1];
                part[mf][0] = fmaf(fmaxf(c[mf][nf][0] + b0s, 0.f), w0, part[mf][0]);
                part[mf][0] = fmaf(fmaxf(c[mf][nf][1] + b1s, 0.f), w1, part[mf][0]);
                part[mf][1] = fmaf(fmaxf(c[mf][nf][2] + b0s, 0.f), w0, part[mf][1]);
                part[mf][1] = fmaf(fmaxf(c[mf][nf][3] + b1s, 0.f), w1, part[mf][1]);
            }
#pragma unroll
        for (int mf = 0; mf < 2; mf++)
#pragma unroll
            for (int h = 0; h < 2; h++) {
                part[mf][h] += __shfl_xor_sync(0xffffffffu, part[mf][h], 1);
                part[mf][h] += __shfl_xor_sync(0xffffffffu, part[mf][h], 2);
            }
        if ((lane & 3) == 0) {
#pragma unroll
            for (int mf = 0; mf < 2; mf++)
#pragma unroll
                for (int h = 0; h < 2; h++) {
                    const int row = m0 + wm + mf * 16 + h * 8 + erow;
                    atomicAdd(&yleaf[(size_t)mat * BATCH + row], part[mf][h]);
                }
        }
    }
}

// ---------------------------------------------------------------------------
// Combine
// ---------------------------------------------------------------------------
__global__ __launch_bounds__(256) void combine_kernel(
    const float* __restrict__ pR, const float* __restrict__ yl,
    const float* __restrict__ b2, float* __restrict__ out)
{
    const int b = blockIdx.x * 256 + threadIdx.x;
    float p[N_INNER];
#pragma unroll
    for (int i = 0; i < N_INNER; i++) p[i] = pR[(size_t)i * BATCH + b];

    float prob[N_LEAF];
    prob[0] = 1.f;
#pragma unroll
    for (int lev = 0; lev < 5; lev++) {
        const int cnt = 1 << lev;
        const int off = cnt - 1;
#pragma unroll
        for (int i = N_LEAF - 1; i >= 0; i--) {
            if (i < cnt) {
                float pr   = p[off + i];
                float base = prob[i];
                prob[2 * i]     = base * (1.f - pr);
                prob[2 * i + 1] = base * pr;
            }
        }
    }
    float acc = 0.f;
#pragma unroll
    for (int l = 0; l < N_LEAF; l++)
        acc = fmaf(prob[l], yl[(size_t)l * BATCH + b] + b2[l], acc);
    out[b] = acc;
}

// ---------------------------------------------------------------------------
extern "C" void kernel_launch(void* const* d_in, const int* in_sizes, int n_in,
                              void* d_out, int out_size)
{
    const float* x       = (const float*)d_in[0];
    const float* enc_W   = (const float*)d_in[1];
    const float* enc_b   = (const float*)d_in[2];
    const float* in_W1   = (const float*)d_in[3];
    const float* in_b1   = (const float*)d_in[4];
    const float* in_Ww   = (const float*)d_in[5];
    const float* in_bw   = (const float*)d_in[6];
    const float* in_Wb   = (const float*)d_in[7];
    const float* in_bb   = (const float*)d_in[8];
    const float* in_Wbt  = (const float*)d_in[9];
    const float* in_bbt  = (const float*)d_in[10];
    const float* lf_W1   = (const float*)d_in[11];
    const float* lf_b1   = (const float*)d_in[12];
    const float* lf_W2   = (const float*)d_in[13];
    const float* lf_b2   = (const float*)d_in[14];
    float* out = (float*)d_out;

    float *pR, *yl;
    __half *xh, *xl, *e0h, *e0l, *e1h, *e1l, *wte;
    __half *ef, *lwh, *w1h, *wwh;
    cudaGetSymbolAddress((void**)&pR,  g_pR);
    cudaGetSymbolAddress((void**)&yl,  g_yleaf);
    cudaGetSymbolAddress((void**)&xh,  g_xh);
    cudaGetSymbolAddress((void**)&xl,  g_xl);
    cudaGetSymbolAddress((void**)&e0h, g_e0h);
    cudaGetSymbolAddress((void**)&e0l, g_e0l);
    cudaGetSymbolAddress((void**)&e1h, g_e1h);
    cudaGetSymbolAddress((void**)&e1l, g_e1l);
    cudaGetSymbolAddress((void**)&wte, g_wte);
    cudaGetSymbolAddress((void**)&ef,  g_ef);
    cudaGetSymbolAddress((void**)&lwh, g_lwh);
    cudaGetSymbolAddress((void**)&w1h, g_w1h);
    cudaGetSymbolAddress((void**)&wwh, g_wwh);

    cudaFuncSetAttribute(enc_kernel<0>, cudaFuncAttributeMaxDynamicSharedMemorySize, ENC_SMEM);
    cudaFuncSetAttribute(enc_kernel<1>, cudaFuncAttributeMaxDynamicSharedMemorySize, ENC_SMEM);
    cudaFuncSetAttribute(tail_kernel,   cudaFuncAttributeMaxDynamicSharedMemorySize, TAIL_SMEM);

    // 1) all prep in one launch
    prep_all_kernel<<<PR_WTL, 256>>>(x, xh, xl, in_W1, w1h,
                                     in_Ww, wwh, yl,
                                     enc_W, wte, lf_W1, lwh);

    // 2-5) encoder (fp16 act-hi/lo x weight-single, 2 MMA/k-step, occ 3)
    enc_kernel<0><<<dim3(128, 2), 256, ENC_SMEM>>>(xh, xl, wte,
        enc_b, e0h, e0l, nullptr);
    enc_kernel<0><<<dim3(128, 2), 256, ENC_SMEM>>>(e0h, e0l, wte + 65536,
        enc_b + 256, e1h, e1l, nullptr);
    enc_kernel<0><<<dim3(128, 2), 256, ENC_SMEM>>>(e1h, e1l, wte + 2 * 65536,
        enc_b + 512, e0h, e0l, nullptr);
    enc_kernel<1><<<dim3(128, 2), 256, ENC_SMEM>>>(e0h, e0l, wte + 3 * 65536,
        enc_b + 768, nullptr, nullptr, ef);

    // 6) merged inner + leaf (fp16 single x single)
    tail_kernel<<<dim3(63, 128), 256, TAIL_SMEM>>>(
        ef,
        w1h, wwh, x, in_b1, in_bw, in_Wb, in_bb, in_Wbt, in_bbt, pR,
        lwh, lf_b1, lf_W2, yl);

    // 7) combine
    combine_kernel<<<BATCH / 256, 256>>>(pR, yl, lf_b2, out);
}